// round 1
// baseline (speedup 1.0000x reference)
#include <cuda_runtime.h>

#define BB 8
#define SS 1024
#define DD 512
#define HH 8
#define DH 64
#define L2P 2047   // 2*S - 1
#define SCALE 0.125f  // 1/sqrt(Dh)

// ------------------ scratch (static device globals; no allocation) ------------------
__device__ float g_q[BB*SS*DD];              // [B,S,H,Dh]
__device__ float g_k[BB*SS*DD];
__device__ float g_v[BB*SS*DD];
__device__ float g_p[BB*L2P*DD];             // [B,2S-1,H,Dh]
__device__ float g_score[(size_t)BB*HH*SS*SS]; // [B,H,S,S] -> attn in place
__device__ float g_ctx[BB*SS*DD];            // [B,S,H,Dh] = [B,S,D]

// ------------------ generic tiled GEMM: C[M,N] = A[M,K] @ W[K,N] ------------------
// BM=BN=64, BK=16, 256 threads, 4x4 per thread. N,K multiples of 64/16; M guarded.
__global__ __launch_bounds__(256) void gemm64(const float* __restrict__ A,
                                              const float* __restrict__ W,
                                              float* __restrict__ C,
                                              int M, int N, int K) {
    __shared__ float As[16][64];   // As[k][m]
    __shared__ float Bs[16][64];   // Bs[k][n]
    int tid = threadIdx.x;
    int tx = tid & 15, ty = tid >> 4;
    int row0 = blockIdx.y * 64, col0 = blockIdx.x * 64;
    float acc[4][4] = {};

    for (int k0 = 0; k0 < K; k0 += 16) {
        int kk = tid & 15;
        int r0 = tid >> 4;
        #pragma unroll
        for (int pass = 0; pass < 4; pass++) {
            int r = r0 + pass * 16;
            int grow = row0 + r;
            As[kk][r] = (grow < M) ? A[(size_t)grow * K + k0 + kk] : 0.0f;
        }
        int nn = tid & 63;
        int kr0 = tid >> 6;
        #pragma unroll
        for (int pass = 0; pass < 4; pass++) {
            int kr = kr0 + pass * 4;
            Bs[kr][nn] = W[(size_t)(k0 + kr) * N + col0 + nn];
        }
        __syncthreads();
        #pragma unroll
        for (int kk2 = 0; kk2 < 16; kk2++) {
            float a[4], b[4];
            #pragma unroll
            for (int ii = 0; ii < 4; ii++) a[ii] = As[kk2][ty * 4 + ii];
            #pragma unroll
            for (int jj = 0; jj < 4; jj++) b[jj] = Bs[kk2][tx * 4 + jj];
            #pragma unroll
            for (int ii = 0; ii < 4; ii++)
                #pragma unroll
                for (int jj = 0; jj < 4; jj++)
                    acc[ii][jj] += a[ii] * b[jj];
        }
        __syncthreads();
    }
    #pragma unroll
    for (int ii = 0; ii < 4; ii++) {
        int grow = row0 + ty * 4 + ii;
        if (grow < M) {
            #pragma unroll
            for (int jj = 0; jj < 4; jj++)
                C[(size_t)grow * N + col0 + tx * 4 + jj] = acc[ii][jj];
        }
    }
}

// ------------------ fused content+pos score ------------------
// score[b,h,i,j] = ( (q_i+u)·k_j + (q_i+v)·p_{(S-1)+j-i} ) * SCALE
// grid: (S/64 j-tiles, S/64 i-tiles, B*H); 256 threads; 64x64 output tile.
__global__ __launch_bounds__(256) void score_kernel(const float* __restrict__ ub,
                                                    const float* __restrict__ vb) {
    int bh = blockIdx.z;
    int b = bh >> 3, h = bh & 7;
    int i0 = blockIdx.y * 64, j0 = blockIdx.x * 64;
    int pbase = 960 + j0 - i0;   // prow = pbase + t, t = (jj-ii)+63 in [0,126]

    __shared__ float QU[16][64];
    __shared__ float QV[16][64];
    __shared__ float KS[16][64];
    __shared__ float PS[16][128];

    int tid = threadIdx.x;
    int tx = tid & 15, ty = tid >> 4;
    float accC[4][4] = {}, accP[4][4] = {};

    for (int d0 = 0; d0 < DH; d0 += 16) {
        int dd = tid & 15;
        int r0 = tid >> 4;
        #pragma unroll
        for (int pass = 0; pass < 4; pass++) {
            int r = r0 + pass * 16;
            float qval = g_q[((size_t)(b * SS + i0 + r) * HH + h) * DH + d0 + dd];
            QU[dd][r] = qval + ub[h * DH + d0 + dd];
            QV[dd][r] = qval + vb[h * DH + d0 + dd];
            KS[dd][r] = g_k[((size_t)(b * SS + j0 + r) * HH + h) * DH + d0 + dd];
        }
        #pragma unroll
        for (int pass = 0; pass < 8; pass++) {
            int t = r0 + pass * 16;
            if (t < 127)
                PS[dd][t] = g_p[((size_t)(b * L2P + pbase + t) * HH + h) * DH + d0 + dd];
        }
        __syncthreads();

        int pcol0 = (tx - ty) * 4 + 63;  // base gather col for this thread's tile
        #pragma unroll
        for (int kk = 0; kk < 16; kk++) {
            float qu[4], qv[4], kv[4], ps[7];
            #pragma unroll
            for (int ii = 0; ii < 4; ii++) qu[ii] = QU[kk][ty * 4 + ii];
            #pragma unroll
            for (int ii = 0; ii < 4; ii++) qv[ii] = QV[kk][ty * 4 + ii];
            #pragma unroll
            for (int jj = 0; jj < 4; jj++) kv[jj] = KS[kk][tx * 4 + jj];
            #pragma unroll
            for (int d = 0; d < 7; d++) ps[d] = PS[kk][pcol0 + d - 3];
            #pragma unroll
            for (int ii = 0; ii < 4; ii++)
                #pragma unroll
                for (int jj = 0; jj < 4; jj++) {
                    accC[ii][jj] += qu[ii] * kv[jj];
                    accP[ii][jj] += qv[ii] * ps[jj - ii + 3];
                }
        }
        __syncthreads();
    }

    #pragma unroll
    for (int ii = 0; ii < 4; ii++) {
        int i = i0 + ty * 4 + ii;
        #pragma unroll
        for (int jj = 0; jj < 4; jj++) {
            int j = j0 + tx * 4 + jj;
            g_score[((size_t)bh * SS + i) * SS + j] = (accC[ii][jj] + accP[ii][jj]) * SCALE;
        }
    }
}

// ------------------ row softmax in place ------------------
__global__ __launch_bounds__(256) void softmax_kernel() {
    __shared__ float redm[8];
    __shared__ float reds[8];
    size_t row = blockIdx.x;
    float* r = g_score + row * SS;
    int tid = threadIdx.x;
    float v[4];
    float m = -1e30f;
    #pragma unroll
    for (int t = 0; t < 4; t++) { v[t] = r[tid + t * 256]; m = fmaxf(m, v[t]); }
    #pragma unroll
    for (int o = 16; o > 0; o >>= 1) m = fmaxf(m, __shfl_xor_sync(0xffffffffu, m, o));
    if ((tid & 31) == 0) redm[tid >> 5] = m;
    __syncthreads();
    m = redm[0];
    #pragma unroll
    for (int w = 1; w < 8; w++) m = fmaxf(m, redm[w]);

    float s = 0.0f;
    #pragma unroll
    for (int t = 0; t < 4; t++) { v[t] = __expf(v[t] - m); s += v[t]; }
    #pragma unroll
    for (int o = 16; o > 0; o >>= 1) s += __shfl_xor_sync(0xffffffffu, s, o);
    if ((tid & 31) == 0) reds[tid >> 5] = s;
    __syncthreads();
    s = reds[0];
    #pragma unroll
    for (int w = 1; w < 8; w++) s += reds[w];
    float inv = 1.0f / s;
    #pragma unroll
    for (int t = 0; t < 4; t++) r[tid + t * 256] = v[t] * inv;
}

// ------------------ context: ctx[b,i,h,:] = attn[b,h,i,:] @ v[b,:,h,:] ------------------
// grid: (S/64 i-tiles, B*H); 256 threads; output tile 64 i x 64 n (n = full Dh).
__global__ __launch_bounds__(256) void ctx_kernel() {
    int bh = blockIdx.y;
    int b = bh >> 3, h = bh & 7;
    int i0 = blockIdx.x * 64;
    const float* A = g_score + (size_t)bh * SS * SS;

    __shared__ float As[16][64];   // As[j][i]
    __shared__ float Bs[16][64];   // Bs[j][n]
    int tid = threadIdx.x;
    int tx = tid & 15, ty = tid >> 4;
    float acc[4][4] = {};

    for (int jc = 0; jc < SS; jc += 16) {
        int dd = tid & 15;
        int r0 = tid >> 4;
        #pragma unroll
        for (int pass = 0; pass < 4; pass++) {
            int r = r0 + pass * 16;
            As[dd][r] = A[(size_t)(i0 + r) * SS + jc + dd];
        }
        int nn = tid & 63;
        int jr0 = tid >> 6;
        #pragma unroll
        for (int pass = 0; pass < 4; pass++) {
            int jr = jr0 + pass * 4;
            Bs[jr][nn] = g_v[((size_t)(b * SS + jc + jr) * HH + h) * DH + nn];
        }
        __syncthreads();
        #pragma unroll
        for (int kk = 0; kk < 16; kk++) {
            float a[4], bv[4];
            #pragma unroll
            for (int ii = 0; ii < 4; ii++) a[ii] = As[kk][ty * 4 + ii];
            #pragma unroll
            for (int jj = 0; jj < 4; jj++) bv[jj] = Bs[kk][tx * 4 + jj];
            #pragma unroll
            for (int ii = 0; ii < 4; ii++)
                #pragma unroll
                for (int jj = 0; jj < 4; jj++)
                    acc[ii][jj] += a[ii] * bv[jj];
        }
        __syncthreads();
    }
    #pragma unroll
    for (int ii = 0; ii < 4; ii++) {
        int i = i0 + ty * 4 + ii;
        #pragma unroll
        for (int jj = 0; jj < 4; jj++)
            g_ctx[((size_t)(b * SS + i) * HH + h) * DH + tx * 4 + jj] = acc[ii][jj];
    }
}

// ------------------ launch ------------------
extern "C" void kernel_launch(void* const* d_in, const int* in_sizes, int n_in,
                              void* d_out, int out_size) {
    const float* query = (const float*)d_in[0];
    const float* key   = (const float*)d_in[1];
    const float* value = (const float*)d_in[2];
    const float* pos   = (const float*)d_in[3];
    const float* Wq    = (const float*)d_in[4];
    const float* Wk    = (const float*)d_in[5];
    const float* Wv    = (const float*)d_in[6];
    const float* Wp    = (const float*)d_in[7];
    const float* ub    = (const float*)d_in[8];
    const float* vb    = (const float*)d_in[9];
    const float* Wo    = (const float*)d_in[10];
    float* out = (float*)d_out;

    float *pq, *pk, *pv, *pp, *pctx;
    cudaGetSymbolAddress((void**)&pq,  g_q);
    cudaGetSymbolAddress((void**)&pk,  g_k);
    cudaGetSymbolAddress((void**)&pv,  g_v);
    cudaGetSymbolAddress((void**)&pp,  g_p);
    cudaGetSymbolAddress((void**)&pctx, g_ctx);

    dim3 blk(256);

    // projections
    gemm64<<<dim3(DD/64, (BB*SS)/64), blk>>>(query, Wq, pq, BB*SS, DD, DD);
    gemm64<<<dim3(DD/64, (BB*SS)/64), blk>>>(key,   Wk, pk, BB*SS, DD, DD);
    gemm64<<<dim3(DD/64, (BB*SS)/64), blk>>>(value, Wv, pv, BB*SS, DD, DD);
    gemm64<<<dim3(DD/64, (BB*L2P + 63)/64), blk>>>(pos, Wp, pp, BB*L2P, DD, DD);

    // fused content + gathered positional score
    score_kernel<<<dim3(SS/64, SS/64, BB*HH), blk>>>(ub, vb);

    // softmax rows
    softmax_kernel<<<dim3(BB*HH*SS), blk>>>();

    // attn @ v
    ctx_kernel<<<dim3(SS/64, BB*HH), blk>>>();

    // output projection
    gemm64<<<dim3(DD/64, (BB*SS)/64), blk>>>(pctx, Wo, out, BB*SS, DD, DD);
}

// round 2
// speedup vs baseline: 1.5894x; 1.5894x over previous
#include <cuda_runtime.h>

#define BB 8
#define SS 1024
#define DD 512
#define HH 8
#define DH 64
#define L2P 2047   // 2*S - 1
#define SCALE 0.125f  // 1/sqrt(Dh)

// ------------------ scratch (static device globals; no allocation) ------------------
__device__ float g_q[BB*SS*DD];              // [B,S,H,Dh]
__device__ float g_k[BB*SS*DD];
__device__ float g_v[BB*SS*DD];
__device__ float g_p[BB*L2P*DD];             // [B,2S-1,H,Dh]
__device__ float g_score[(size_t)BB*HH*SS*SS]; // [B,H,S,S] -> attn in place
__device__ float g_ctx[BB*SS*DD];            // [B,S,H,Dh] = [B,S,D]

// ------------------ GEMM: C[M,N] = A[M,K] @ W[K,N]; 128x128x8 tile, 8x8/thread ------
__global__ __launch_bounds__(256) void gemm128(const float* __restrict__ A,
                                               const float* __restrict__ W,
                                               float* __restrict__ C,
                                               int M, int N, int K) {
    __shared__ float As[8][128];
    __shared__ float Bs[8][128];
    int tid = threadIdx.x;
    int tx = tid & 15, ty = tid >> 4;
    int row0 = blockIdx.y * 128, col0 = blockIdx.x * 128;

    int ar = tid >> 1;          // 0..127
    int ac = (tid & 1) * 4;     // 0 or 4
    int br = tid >> 5;          // 0..7
    int bc = (tid & 31) * 4;    // 0..124

    float acc[8][8] = {};

    for (int k0 = 0; k0 < K; k0 += 8) {
        float4 av = make_float4(0.f, 0.f, 0.f, 0.f);
        if (row0 + ar < M)
            av = *(const float4*)&A[(size_t)(row0 + ar) * K + k0 + ac];
        As[ac + 0][ar] = av.x; As[ac + 1][ar] = av.y;
        As[ac + 2][ar] = av.z; As[ac + 3][ar] = av.w;
        *(float4*)&Bs[br][bc] = *(const float4*)&W[(size_t)(k0 + br) * N + col0 + bc];
        __syncthreads();

        #pragma unroll
        for (int k = 0; k < 8; k++) {
            float a[8], b[8];
            *(float4*)(a)     = *(float4*)&As[k][ty * 4];
            *(float4*)(a + 4) = *(float4*)&As[k][64 + ty * 4];
            *(float4*)(b)     = *(float4*)&Bs[k][tx * 4];
            *(float4*)(b + 4) = *(float4*)&Bs[k][64 + tx * 4];
            #pragma unroll
            for (int ii = 0; ii < 8; ii++)
                #pragma unroll
                for (int jj = 0; jj < 8; jj++)
                    acc[ii][jj] += a[ii] * b[jj];
        }
        __syncthreads();
    }

    #pragma unroll
    for (int ii = 0; ii < 8; ii++) {
        int r = (ii < 4) ? (ty * 4 + ii) : (64 + ty * 4 + ii - 4);
        int grow = row0 + r;
        if (grow < M) {
            *(float4*)&C[(size_t)grow * N + col0 + tx * 4]      = *(float4*)&acc[ii][0];
            *(float4*)&C[(size_t)grow * N + col0 + 64 + tx * 4] = *(float4*)&acc[ii][4];
        }
    }
}

// ------------------ fused content+pos score ------------------
// score[b,h,i,j] = ( (q_i+u)·k_j + (q_i+v)·p_{(S-1)+j-i} ) * SCALE
// tile: 128 i x 64 j, BK=8, 256 threads (16x16), 8x4 per thread (dual acc).
__global__ __launch_bounds__(256) void score_kernel(const float* __restrict__ ub,
                                                    const float* __restrict__ vb) {
    int bh = blockIdx.z;
    int b = bh >> 3, h = bh & 7;
    int i0 = blockIdx.y * 128, j0 = blockIdx.x * 64;
    int pbase = 896 + j0 - i0;  // prow = pbase + t, t = (c - r) + 127 in [0,190]

    __shared__ float QU[8][128];
    __shared__ float QV[8][128];
    __shared__ float KS[8][64];
    __shared__ float PS[8][192];

    int tid = threadIdx.x;
    int tx = tid & 15, ty = tid >> 4;
    float accC[8][4] = {}, accP[8][4] = {};

    int lr   = tid >> 1;        // 0..127
    int dseg = (tid & 1) * 4;   // 0 or 4

    for (int d0 = 0; d0 < DH; d0 += 8) {
        // Q tile + biases
        {
            float4 qv4 = *(const float4*)&g_q[((size_t)(b * SS + i0 + lr) * HH + h) * DH + d0 + dseg];
            float4 ubv = *(const float4*)&ub[h * DH + d0 + dseg];
            float4 vbv = *(const float4*)&vb[h * DH + d0 + dseg];
            QU[dseg + 0][lr] = qv4.x + ubv.x; QU[dseg + 1][lr] = qv4.y + ubv.y;
            QU[dseg + 2][lr] = qv4.z + ubv.z; QU[dseg + 3][lr] = qv4.w + ubv.w;
            QV[dseg + 0][lr] = qv4.x + vbv.x; QV[dseg + 1][lr] = qv4.y + vbv.y;
            QV[dseg + 2][lr] = qv4.z + vbv.z; QV[dseg + 3][lr] = qv4.w + vbv.w;
        }
        // K tile (first 128 threads)
        if (tid < 128) {
            int r2 = tid >> 1;
            float4 kv4 = *(const float4*)&g_k[((size_t)(b * SS + j0 + r2) * HH + h) * DH + d0 + dseg];
            KS[dseg + 0][r2] = kv4.x; KS[dseg + 1][r2] = kv4.y;
            KS[dseg + 2][r2] = kv4.z; KS[dseg + 3][r2] = kv4.w;
        }
        // P window: 191 rows x 8 dims
        #pragma unroll
        for (int pass = 0; pass < 2; pass++) {
            int slot = pass * 256 + tid;
            int tt = slot >> 1;
            int ds = (slot & 1) * 4;
            if (tt < 191) {
                float4 pv4 = *(const float4*)&g_p[((size_t)(b * L2P + pbase + tt) * HH + h) * DH + d0 + ds];
                PS[ds + 0][tt] = pv4.x; PS[ds + 1][tt] = pv4.y;
                PS[ds + 2][tt] = pv4.z; PS[ds + 3][tt] = pv4.w;
            }
        }
        __syncthreads();

        int t0 = (tx - ty) * 4 + 127;
        #pragma unroll
        for (int k = 0; k < 8; k++) {
            float qu[8], qv[8], kv[4], ps0[7], ps1[7];
            *(float4*)(qu)     = *(float4*)&QU[k][ty * 4];
            *(float4*)(qu + 4) = *(float4*)&QU[k][64 + ty * 4];
            *(float4*)(qv)     = *(float4*)&QV[k][ty * 4];
            *(float4*)(qv + 4) = *(float4*)&QV[k][64 + ty * 4];
            *(float4*)(kv)     = *(float4*)&KS[k][tx * 4];
            #pragma unroll
            for (int d = 0; d < 7; d++) {
                ps0[d] = PS[k][t0 - 3 + d];
                ps1[d] = PS[k][t0 - 67 + d];
            }
            #pragma unroll
            for (int ii = 0; ii < 4; ii++)
                #pragma unroll
                for (int jj = 0; jj < 4; jj++) {
                    accC[ii][jj]     += qu[ii]     * kv[jj];
                    accC[ii + 4][jj] += qu[ii + 4] * kv[jj];
                    accP[ii][jj]     += qv[ii]     * ps0[jj - ii + 3];
                    accP[ii + 4][jj] += qv[ii + 4] * ps1[jj - ii + 3];
                }
        }
        __syncthreads();
    }

    #pragma unroll
    for (int ii = 0; ii < 8; ii++) {
        int r = (ii < 4) ? (ty * 4 + ii) : (64 + ty * 4 + ii - 4);
        int i = i0 + r;
        float4 o;
        o.x = (accC[ii][0] + accP[ii][0]) * SCALE;
        o.y = (accC[ii][1] + accP[ii][1]) * SCALE;
        o.z = (accC[ii][2] + accP[ii][2]) * SCALE;
        o.w = (accC[ii][3] + accP[ii][3]) * SCALE;
        *(float4*)&g_score[((size_t)bh * SS + i) * SS + j0 + tx * 4] = o;
    }
}

// ------------------ row softmax in place (float4) ------------------
__global__ __launch_bounds__(256) void softmax_kernel() {
    __shared__ float redm[8];
    __shared__ float reds[8];
    size_t row = blockIdx.x;
    float4* r = (float4*)(g_score + row * SS);
    int tid = threadIdx.x;
    float4 v = r[tid];
    float m = fmaxf(fmaxf(v.x, v.y), fmaxf(v.z, v.w));
    #pragma unroll
    for (int o = 16; o > 0; o >>= 1) m = fmaxf(m, __shfl_xor_sync(0xffffffffu, m, o));
    if ((tid & 31) == 0) redm[tid >> 5] = m;
    __syncthreads();
    m = redm[0];
    #pragma unroll
    for (int w = 1; w < 8; w++) m = fmaxf(m, redm[w]);

    v.x = __expf(v.x - m); v.y = __expf(v.y - m);
    v.z = __expf(v.z - m); v.w = __expf(v.w - m);
    float s = v.x + v.y + v.z + v.w;
    #pragma unroll
    for (int o = 16; o > 0; o >>= 1) s += __shfl_xor_sync(0xffffffffu, s, o);
    if ((tid & 31) == 0) reds[tid >> 5] = s;
    __syncthreads();
    s = reds[0];
    #pragma unroll
    for (int w = 1; w < 8; w++) s += reds[w];
    float inv = 1.0f / s;
    v.x *= inv; v.y *= inv; v.z *= inv; v.w *= inv;
    r[tid] = v;
}

// ------------------ context: ctx[b,i,h,:] = attn[b,h,i,:] @ v[b,:,h,:] ------------------
// tile: 128 i x 64 n (full Dh), BK=16, 256 threads, 8x4 per thread.
__global__ __launch_bounds__(256) void ctx_kernel() {
    int bh = blockIdx.y;
    int b = bh >> 3, h = bh & 7;
    int i0 = blockIdx.x * 128;
    const float* A = g_score + (size_t)bh * SS * SS;

    __shared__ float As[16][128];
    __shared__ float Vs[16][64];
    int tid = threadIdx.x;
    int tx = tid & 15, ty = tid >> 4;
    float acc[8][4] = {};

    int ar = tid >> 1;
    int ac = (tid & 1) * 4;
    int vr = tid >> 4;          // 0..15
    int vc = (tid & 15) * 4;    // 0..60

    for (int jc = 0; jc < SS; jc += 16) {
        {
            const float* Arow = A + (size_t)(i0 + ar) * SS + jc;
            float4 a0 = *(const float4*)&Arow[ac];
            float4 a1 = *(const float4*)&Arow[8 + ac];
            As[ac + 0][ar] = a0.x; As[ac + 1][ar] = a0.y;
            As[ac + 2][ar] = a0.z; As[ac + 3][ar] = a0.w;
            As[8 + ac + 0][ar] = a1.x; As[8 + ac + 1][ar] = a1.y;
            As[8 + ac + 2][ar] = a1.z; As[8 + ac + 3][ar] = a1.w;
        }
        *(float4*)&Vs[vr][vc] =
            *(const float4*)&g_v[((size_t)(b * SS + jc + vr) * HH + h) * DH + vc];
        __syncthreads();

        #pragma unroll
        for (int k = 0; k < 16; k++) {
            float a[8], bv[4];
            *(float4*)(a)     = *(float4*)&As[k][ty * 4];
            *(float4*)(a + 4) = *(float4*)&As[k][64 + ty * 4];
            *(float4*)(bv)    = *(float4*)&Vs[k][tx * 4];
            #pragma unroll
            for (int ii = 0; ii < 8; ii++)
                #pragma unroll
                for (int jj = 0; jj < 4; jj++)
                    acc[ii][jj] += a[ii] * bv[jj];
        }
        __syncthreads();
    }

    #pragma unroll
    for (int ii = 0; ii < 8; ii++) {
        int r = (ii < 4) ? (ty * 4 + ii) : (64 + ty * 4 + ii - 4);
        int i = i0 + r;
        *(float4*)&g_ctx[((size_t)(b * SS + i) * HH + h) * DH + tx * 4] = *(float4*)&acc[ii][0];
    }
}

// ------------------ launch ------------------
extern "C" void kernel_launch(void* const* d_in, const int* in_sizes, int n_in,
                              void* d_out, int out_size) {
    const float* query = (const float*)d_in[0];
    const float* key   = (const float*)d_in[1];
    const float* value = (const float*)d_in[2];
    const float* pos   = (const float*)d_in[3];
    const float* Wq    = (const float*)d_in[4];
    const float* Wk    = (const float*)d_in[5];
    const float* Wv    = (const float*)d_in[6];
    const float* Wp    = (const float*)d_in[7];
    const float* ub    = (const float*)d_in[8];
    const float* vb    = (const float*)d_in[9];
    const float* Wo    = (const float*)d_in[10];
    float* out = (float*)d_out;

    float *pq, *pk, *pv, *pp, *pctx;
    cudaGetSymbolAddress((void**)&pq,  g_q);
    cudaGetSymbolAddress((void**)&pk,  g_k);
    cudaGetSymbolAddress((void**)&pv,  g_v);
    cudaGetSymbolAddress((void**)&pp,  g_p);
    cudaGetSymbolAddress((void**)&pctx, g_ctx);

    dim3 blk(256);

    // projections
    gemm128<<<dim3(DD/128, (BB*SS)/128), blk>>>(query, Wq, pq, BB*SS, DD, DD);
    gemm128<<<dim3(DD/128, (BB*SS)/128), blk>>>(key,   Wk, pk, BB*SS, DD, DD);
    gemm128<<<dim3(DD/128, (BB*SS)/128), blk>>>(value, Wv, pv, BB*SS, DD, DD);
    gemm128<<<dim3(DD/128, (BB*L2P + 127)/128), blk>>>(pos, Wp, pp, BB*L2P, DD, DD);

    // fused content + gathered positional score
    score_kernel<<<dim3(SS/64, SS/128, BB*HH), blk>>>(ub, vb);

    // softmax rows
    softmax_kernel<<<dim3(BB*HH*SS), blk>>>();

    // attn @ v
    ctx_kernel<<<dim3(SS/128, BB*HH), blk>>>();

    // output projection
    gemm128<<<dim3(DD/128, (BB*SS)/128), blk>>>(pctx, Wo, out, BB*SS, DD, DD);
}

// round 3
// speedup vs baseline: 1.6765x; 1.0548x over previous
#include <cuda_runtime.h>
#include <cuda_bf16.h>
#include <cstdint>

#define BB 8
#define SS 1024
#define DD 512
#define HH 8
#define DH 64
#define L2P 2047
#define SCALE 0.125f

// ---------------- scratch ----------------
__device__ uint32_t g_qhi[BB*SS*256], g_qlo[BB*SS*256];   // bf16 pairs packed along d
__device__ uint32_t g_khi[BB*SS*256], g_klo[BB*SS*256];
__device__ uint32_t g_vhi[BB*SS*256], g_vlo[BB*SS*256];
__device__ uint32_t g_phi[BB*L2P*256], g_plo[BB*L2P*256];
__device__ float g_score[(size_t)BB*HH*SS*SS];
__device__ float g_ctx[BB*SS*DD];

// ---------------- helpers ----------------
__device__ __forceinline__ void split_pair(float x0, float x1, uint32_t& h, uint32_t& l) {
    __nv_bfloat162 hh = __floats2bfloat162_rn(x0, x1);
    float r0 = x0 - __bfloat162float(hh.x);
    float r1 = x1 - __bfloat162float(hh.y);
    __nv_bfloat162 ll = __floats2bfloat162_rn(r0, r1);
    h = *reinterpret_cast<uint32_t*>(&hh);
    l = *reinterpret_cast<uint32_t*>(&ll);
}
__device__ __forceinline__ float2 unsplit(uint32_t h, uint32_t l) {
    __nv_bfloat162 hh = *reinterpret_cast<__nv_bfloat162*>(&h);
    __nv_bfloat162 ll = *reinterpret_cast<__nv_bfloat162*>(&l);
    return make_float2(__bfloat162float(hh.x) + __bfloat162float(ll.x),
                       __bfloat162float(hh.y) + __bfloat162float(ll.y));
}
__device__ __forceinline__ void mma16816(float d[4], const uint32_t a[4], const uint32_t b[2]) {
    asm volatile(
        "mma.sync.aligned.m16n8k16.row.col.f32.bf16.bf16.f32 "
        "{%0,%1,%2,%3}, {%4,%5,%6,%7}, {%8,%9}, {%0,%1,%2,%3};\n"
        : "+f"(d[0]), "+f"(d[1]), "+f"(d[2]), "+f"(d[3])
        : "r"(a[0]), "r"(a[1]), "r"(a[2]), "r"(a[3]), "r"(b[0]), "r"(b[1]));
}
__device__ __forceinline__ void ldA4(uint32_t a[4], const uint32_t* S, int stride,
                                     int m0, int kq0, int g, int t) {
    const uint32_t* p = S + (m0 + g) * stride + kq0 + t;
    a[0] = p[0]; a[2] = p[4];
    const uint32_t* p2 = p + 8 * stride;
    a[1] = p2[0]; a[3] = p2[4];
}
__device__ __forceinline__ void ldB2(uint32_t b[2], const uint32_t* S, int stride,
                                     int n0, int kq0, int g, int t) {
    const uint32_t* p = S + (n0 + g) * stride + kq0 + t;
    b[0] = p[0]; b[1] = p[4];
}

// ---------------- GEMM: C[M,N] = A[M,K] @ W[K,N] ----------------
// CTA 128x128, BK=32 (kq 16, stride 20), 8 warps (4x2), warp 32x64.
#define GSTR 20
template<bool SPLIT_OUT>
__global__ __launch_bounds__(256) void gemm_tc(const float* __restrict__ A,
                                               const float* __restrict__ W,
                                               float* __restrict__ Cf,
                                               uint32_t* __restrict__ Chi,
                                               uint32_t* __restrict__ Clo,
                                               int M, int N, int K) {
    __shared__ uint32_t sAh[128*GSTR], sAl[128*GSTR], sBh[128*GSTR], sBl[128*GSTR];
    int tid = threadIdx.x;
    int lane = tid & 31, wi = tid >> 5;
    int g = lane >> 2, t4 = lane & 3;
    int row0 = blockIdx.y * 128, col0 = blockIdx.x * 128;
    int wm = (wi & 3) * 32, wn = (wi >> 2) * 64;

    float acc[2][8][4];
    #pragma unroll
    for (int a = 0; a < 2; a++)
        #pragma unroll
        for (int b = 0; b < 8; b++)
            #pragma unroll
            for (int c = 0; c < 4; c++) acc[a][b][c] = 0.f;

    int arow = tid >> 1, ahalf = tid & 1;
    int bnc = tid & 31, bkp = tid >> 5;

    for (int k0 = 0; k0 < K; k0 += 32) {
        { // A fill
            float v[16];
            if (row0 + arow < M) {
                const float* src = A + (size_t)(row0 + arow) * K + k0 + ahalf * 16;
                #pragma unroll
                for (int q = 0; q < 4; q++) *(float4*)&v[q*4] = *(const float4*)&src[q*4];
            } else {
                #pragma unroll
                for (int q = 0; q < 16; q++) v[q] = 0.f;
            }
            #pragma unroll
            for (int q = 0; q < 8; q++) {
                uint32_t h, l;
                split_pair(v[2*q], v[2*q+1], h, l);
                sAh[arow * GSTR + ahalf * 8 + q] = h;
                sAl[arow * GSTR + ahalf * 8 + q] = l;
            }
        }
        #pragma unroll
        for (int pp = 0; pp < 2; pp++) { // B fill transposed
            int kq = bkp + pp * 8;
            int k = k0 + kq * 2;
            float4 r0 = *(const float4*)&W[(size_t)k * N + col0 + bnc * 4];
            float4 r1 = *(const float4*)&W[(size_t)(k + 1) * N + col0 + bnc * 4];
            float p0[4] = {r0.x, r0.y, r0.z, r0.w};
            float p1[4] = {r1.x, r1.y, r1.z, r1.w};
            #pragma unroll
            for (int e = 0; e < 4; e++) {
                uint32_t h, l;
                split_pair(p0[e], p1[e], h, l);
                sBh[(bnc * 4 + e) * GSTR + kq] = h;
                sBl[(bnc * 4 + e) * GSTR + kq] = l;
            }
        }
        __syncthreads();
        #pragma unroll
        for (int kq0 = 0; kq0 < 16; kq0 += 8) {
            uint32_t ah[2][4], al[2][4];
            #pragma unroll
            for (int mi = 0; mi < 2; mi++) {
                ldA4(ah[mi], sAh, GSTR, wm + 16 * mi, kq0, g, t4);
                ldA4(al[mi], sAl, GSTR, wm + 16 * mi, kq0, g, t4);
            }
            #pragma unroll
            for (int nf = 0; nf < 8; nf++) {
                uint32_t bh_[2], bl_[2];
                ldB2(bh_, sBh, GSTR, wn + 8 * nf, kq0, g, t4);
                ldB2(bl_, sBl, GSTR, wn + 8 * nf, kq0, g, t4);
                #pragma unroll
                for (int mi = 0; mi < 2; mi++) {
                    mma16816(acc[mi][nf], ah[mi], bh_);
                    mma16816(acc[mi][nf], ah[mi], bl_);
                    mma16816(acc[mi][nf], al[mi], bh_);
                }
            }
        }
        __syncthreads();
    }
    #pragma unroll
    for (int mi = 0; mi < 2; mi++)
        #pragma unroll
        for (int nf = 0; nf < 8; nf++) {
            int r = row0 + wm + 16 * mi + g;
            int c = col0 + wn + 8 * nf + 2 * t4;
            if (SPLIT_OUT) {
                if (r < M) {
                    uint32_t h, l;
                    split_pair(acc[mi][nf][0], acc[mi][nf][1], h, l);
                    Chi[(size_t)r * (N >> 1) + (c >> 1)] = h;
                    Clo[(size_t)r * (N >> 1) + (c >> 1)] = l;
                }
                if (r + 8 < M) {
                    uint32_t h, l;
                    split_pair(acc[mi][nf][2], acc[mi][nf][3], h, l);
                    Chi[(size_t)(r + 8) * (N >> 1) + (c >> 1)] = h;
                    Clo[(size_t)(r + 8) * (N >> 1) + (c >> 1)] = l;
                }
            } else {
                if (r < M)
                    *(float2*)&Cf[(size_t)r * N + c] = make_float2(acc[mi][nf][0], acc[mi][nf][1]);
                if (r + 8 < M)
                    *(float2*)&Cf[(size_t)(r + 8) * N + c] = make_float2(acc[mi][nf][2], acc[mi][nf][3]);
            }
        }
}

// ---------------- score kernel ----------------
// CTA: 128 i x 64 j; R = (q+v) @ P^T over 192-window; content = (q+u) @ k^T.
// smem tiles (d-chunk 32, kq 16, stride 20) then Rs[128][192] fp32 (union).
__global__ __launch_bounds__(256) void score_tc(const float* __restrict__ ub,
                                                const float* __restrict__ vb) {
    extern __shared__ uint32_t sm[];
    uint32_t *QUh = sm,        *QUl = sm + 2560;
    uint32_t *QVh = sm + 5120, *QVl = sm + 7680;
    uint32_t *Kh  = sm + 10240,*Kl  = sm + 11520;
    uint32_t *Ph  = sm + 12800,*Pl  = sm + 16640;
    float* Rs = (float*)sm;

    int tid = threadIdx.x;
    int lane = tid & 31, wi = tid >> 5;
    int g = lane >> 2, t4 = lane & 3;
    int bh = blockIdx.z, b = bh >> 3, h = bh & 7;
    int i0 = blockIdx.y * 128, j0 = blockIdx.x * 64;
    int pbase = 896 + j0 - i0;
    int wm = (wi & 3) * 32, wn = wi >> 2;

    float accR[2][12][4], accC[2][4][4];
    #pragma unroll
    for (int a = 0; a < 2; a++) {
        #pragma unroll
        for (int c = 0; c < 12; c++)
            #pragma unroll
            for (int e = 0; e < 4; e++) accR[a][c][e] = 0.f;
        #pragma unroll
        for (int c = 0; c < 4; c++)
            #pragma unroll
            for (int e = 0; e < 4; e++) accC[a][c][e] = 0.f;
    }

    int frow = tid >> 1, fhalf = tid & 1;

    for (int dc = 0; dc < 2; dc++) {
        { // QU/QV fill with bias add + resplit
            size_t base = ((size_t)(b * SS + i0 + frow) * HH + h) * 32 + dc * 16 + fhalf * 8;
            uint4 h0 = *(const uint4*)&g_qhi[base];
            uint4 h1 = *(const uint4*)&g_qhi[base + 4];
            uint4 l0 = *(const uint4*)&g_qlo[base];
            uint4 l1 = *(const uint4*)&g_qlo[base + 4];
            uint32_t hs[8] = {h0.x, h0.y, h0.z, h0.w, h1.x, h1.y, h1.z, h1.w};
            uint32_t ls[8] = {l0.x, l0.y, l0.z, l0.w, l1.x, l1.y, l1.z, l1.w};
            #pragma unroll
            for (int q = 0; q < 8; q++) {
                float2 f = unsplit(hs[q], ls[q]);
                int d = dc * 32 + (fhalf * 8 + q) * 2;
                float u0 = ub[h * DH + d], u1 = ub[h * DH + d + 1];
                float v0 = vb[h * DH + d], v1 = vb[h * DH + d + 1];
                uint32_t hh, ll;
                split_pair(f.x + u0, f.y + u1, hh, ll);
                QUh[frow * 20 + fhalf * 8 + q] = hh;
                QUl[frow * 20 + fhalf * 8 + q] = ll;
                split_pair(f.x + v0, f.y + v1, hh, ll);
                QVh[frow * 20 + fhalf * 8 + q] = hh;
                QVl[frow * 20 + fhalf * 8 + q] = ll;
            }
        }
        if (tid < 128) { // K fill (direct copy of packed bf16)
            size_t base = ((size_t)(b * SS + j0 + frow) * HH + h) * 32 + dc * 16 + fhalf * 8;
            *(uint4*)&Kh[frow * 20 + fhalf * 8]     = *(const uint4*)&g_khi[base];
            *(uint4*)&Kh[frow * 20 + fhalf * 8 + 4] = *(const uint4*)&g_khi[base + 4];
            *(uint4*)&Kl[frow * 20 + fhalf * 8]     = *(const uint4*)&g_klo[base];
            *(uint4*)&Kl[frow * 20 + fhalf * 8 + 4] = *(const uint4*)&g_klo[base + 4];
        }
        #pragma unroll
        for (int pass = 0; pass < 2; pass++) { // P window fill
            int idx = pass * 256 + tid;
            int tr = idx >> 1, th = idx & 1;
            if (tr < 191) {
                size_t base = ((size_t)(b * L2P + pbase + tr) * HH + h) * 32 + dc * 16 + th * 8;
                *(uint4*)&Ph[tr * 20 + th * 8]     = *(const uint4*)&g_phi[base];
                *(uint4*)&Ph[tr * 20 + th * 8 + 4] = *(const uint4*)&g_phi[base + 4];
                *(uint4*)&Pl[tr * 20 + th * 8]     = *(const uint4*)&g_plo[base];
                *(uint4*)&Pl[tr * 20 + th * 8 + 4] = *(const uint4*)&g_plo[base + 4];
            } else if (tr < 192) {
                uint4 z = make_uint4(0, 0, 0, 0);
                *(uint4*)&Ph[tr * 20 + th * 8]     = z;
                *(uint4*)&Ph[tr * 20 + th * 8 + 4] = z;
                *(uint4*)&Pl[tr * 20 + th * 8]     = z;
                *(uint4*)&Pl[tr * 20 + th * 8 + 4] = z;
            }
        }
        __syncthreads();

        #pragma unroll
        for (int kq0 = 0; kq0 < 16; kq0 += 8) {
            uint32_t uh[2][4], ul[2][4], vh[2][4], vl[2][4];
            #pragma unroll
            for (int mi = 0; mi < 2; mi++) {
                ldA4(uh[mi], QUh, 20, wm + 16 * mi, kq0, g, t4);
                ldA4(ul[mi], QUl, 20, wm + 16 * mi, kq0, g, t4);
                ldA4(vh[mi], QVh, 20, wm + 16 * mi, kq0, g, t4);
                ldA4(vl[mi], QVl, 20, wm + 16 * mi, kq0, g, t4);
            }
            #pragma unroll
            for (int nf = 0; nf < 4; nf++) {
                uint32_t bh_[2], bl_[2];
                ldB2(bh_, Kh, 20, wn * 32 + 8 * nf, kq0, g, t4);
                ldB2(bl_, Kl, 20, wn * 32 + 8 * nf, kq0, g, t4);
                #pragma unroll
                for (int mi = 0; mi < 2; mi++) {
                    mma16816(accC[mi][nf], uh[mi], bh_);
                    mma16816(accC[mi][nf], uh[mi], bl_);
                    mma16816(accC[mi][nf], ul[mi], bh_);
                }
            }
            #pragma unroll
            for (int nf = 0; nf < 12; nf++) {
                uint32_t bh_[2], bl_[2];
                ldB2(bh_, Ph, 20, wn * 96 + 8 * nf, kq0, g, t4);
                ldB2(bl_, Pl, 20, wn * 96 + 8 * nf, kq0, g, t4);
                #pragma unroll
                for (int mi = 0; mi < 2; mi++) {
                    mma16816(accR[mi][nf], vh[mi], bh_);
                    mma16816(accR[mi][nf], vh[mi], bl_);
                    mma16816(accR[mi][nf], vl[mi], bh_);
                }
            }
        }
        __syncthreads();
    }

    // dump R to smem (tiles dead)
    #pragma unroll
    for (int mi = 0; mi < 2; mi++)
        #pragma unroll
        for (int nf = 0; nf < 12; nf++) {
            int il = wm + 16 * mi;
            int tc = wn * 96 + 8 * nf + 2 * t4;
            Rs[(il + g) * 192 + tc]         = accR[mi][nf][0];
            Rs[(il + g) * 192 + tc + 1]     = accR[mi][nf][1];
            Rs[(il + g + 8) * 192 + tc]     = accR[mi][nf][2];
            Rs[(il + g + 8) * 192 + tc + 1] = accR[mi][nf][3];
        }
    __syncthreads();

    // gather + combine + store
    #pragma unroll
    for (int mi = 0; mi < 2; mi++)
        #pragma unroll
        for (int nf = 0; nf < 4; nf++) {
            int il = wm + 16 * mi + g;
            int jl = wn * 32 + 8 * nf + 2 * t4;
            float p00 = Rs[il * 192 + (jl - il + 127)];
            float p01 = Rs[il * 192 + (jl + 1 - il + 127)];
            int il2 = il + 8;
            float p10 = Rs[il2 * 192 + (jl - il2 + 127)];
            float p11 = Rs[il2 * 192 + (jl + 1 - il2 + 127)];
            size_t o0 = ((size_t)bh * SS + i0 + il) * SS + j0 + jl;
            size_t o1 = ((size_t)bh * SS + i0 + il2) * SS + j0 + jl;
            *(float2*)&g_score[o0] = make_float2((accC[mi][nf][0] + p00) * SCALE,
                                                 (accC[mi][nf][1] + p01) * SCALE);
            *(float2*)&g_score[o1] = make_float2((accC[mi][nf][2] + p10) * SCALE,
                                                 (accC[mi][nf][3] + p11) * SCALE);
        }
}

// ---------------- row softmax ----------------
__global__ __launch_bounds__(256) void softmax_kernel() {
    __shared__ float redm[8];
    __shared__ float reds[8];
    size_t row = blockIdx.x;
    float4* r = (float4*)(g_score + row * SS);
    int tid = threadIdx.x;
    float4 v = r[tid];
    float m = fmaxf(fmaxf(v.x, v.y), fmaxf(v.z, v.w));
    #pragma unroll
    for (int o = 16; o > 0; o >>= 1) m = fmaxf(m, __shfl_xor_sync(0xffffffffu, m, o));
    if ((tid & 31) == 0) redm[tid >> 5] = m;
    __syncthreads();
    m = redm[0];
    #pragma unroll
    for (int w = 1; w < 8; w++) m = fmaxf(m, redm[w]);
    v.x = __expf(v.x - m); v.y = __expf(v.y - m);
    v.z = __expf(v.z - m); v.w = __expf(v.w - m);
    float s = v.x + v.y + v.z + v.w;
    #pragma unroll
    for (int o = 16; o > 0; o >>= 1) s += __shfl_xor_sync(0xffffffffu, s, o);
    if ((tid & 31) == 0) reds[tid >> 5] = s;
    __syncthreads();
    s = reds[0];
    #pragma unroll
    for (int w = 1; w < 8; w++) s += reds[w];
    float inv = 1.0f / s;
    v.x *= inv; v.y *= inv; v.z *= inv; v.w *= inv;
    r[tid] = v;
}

// ---------------- ctx: attn @ v ----------------
// CTA 128 i x 64 d, k=j streamed BK=64 (kq 32, stride 36), warps 4x2 (32m x 32n).
#define CSTR 36
__global__ __launch_bounds__(256) void ctx_tc() {
    extern __shared__ uint32_t sm[];
    uint32_t *Ah = sm, *Al = sm + 4608, *Vh = sm + 9216, *Vl = sm + 11520;

    int tid = threadIdx.x;
    int lane = tid & 31, wi = tid >> 5;
    int g = lane >> 2, t4 = lane & 3;
    int bh = blockIdx.y, b = bh >> 3, h = bh & 7;
    int i0 = blockIdx.x * 128;
    int wm = (wi & 3) * 32, wn = (wi >> 2) * 32;

    float acc[2][4][4];
    #pragma unroll
    for (int a = 0; a < 2; a++)
        #pragma unroll
        for (int c = 0; c < 4; c++)
            #pragma unroll
            for (int e = 0; e < 4; e++) acc[a][c][e] = 0.f;

    int frow = tid >> 1, fhalf = tid & 1;
    int vd = tid >> 2, vjq0 = (tid & 3) * 8;

    for (int jc = 0; jc < SS; jc += 64) {
        { // attn fill + split
            const float* src = g_score + ((size_t)bh * SS + i0 + frow) * SS + jc + fhalf * 32;
            float v[32];
            #pragma unroll
            for (int q = 0; q < 8; q++) *(float4*)&v[q*4] = *(const float4*)&src[q*4];
            #pragma unroll
            for (int q = 0; q < 16; q++) {
                uint32_t hh, ll;
                split_pair(v[2*q], v[2*q+1], hh, ll);
                Ah[frow * CSTR + fhalf * 16 + q] = hh;
                Al[frow * CSTR + fhalf * 16 + q] = ll;
            }
        }
        { // V fill transposed: Vs[d][j/2]
            const uint32_t* vhp = g_vhi;
            const uint32_t* vlp = g_vlo;
            #pragma unroll
            for (int q = 0; q < 8; q++) {
                int jq = vjq0 + q;
                int j = jc + 2 * jq;
                size_t w0i = (size_t)(b * SS + j) * 256 + ((h * DH + vd) >> 1);
                size_t w1i = (size_t)(b * SS + j + 1) * 256 + ((h * DH + vd) >> 1);
                uint32_t h0 = vhp[w0i], h1 = vhp[w1i];
                uint32_t l0 = vlp[w0i], l1 = vlp[w1i];
                int sh = (vd & 1) * 16;
                Vh[vd * CSTR + jq] = ((h0 >> sh) & 0xffffu) | (((h1 >> sh) & 0xffffu) << 16);
                Vl[vd * CSTR + jq] = ((l0 >> sh) & 0xffffu) | (((l1 >> sh) & 0xffffu) << 16);
            }
        }
        __syncthreads();
        #pragma unroll
        for (int kq0 = 0; kq0 < 32; kq0 += 8) {
            uint32_t ah[2][4], al[2][4];
            #pragma unroll
            for (int mi = 0; mi < 2; mi++) {
                ldA4(ah[mi], Ah, CSTR, wm + 16 * mi, kq0, g, t4);
                ldA4(al[mi], Al, CSTR, wm + 16 * mi, kq0, g, t4);
            }
            #pragma unroll
            for (int nf = 0; nf < 4; nf++) {
                uint32_t bh_[2], bl_[2];
                ldB2(bh_, Vh, CSTR, wn + 8 * nf, kq0, g, t4);
                ldB2(bl_, Vl, CSTR, wn + 8 * nf, kq0, g, t4);
                #pragma unroll
                for (int mi = 0; mi < 2; mi++) {
                    mma16816(acc[mi][nf], ah[mi], bh_);
                    mma16816(acc[mi][nf], ah[mi], bl_);
                    mma16816(acc[mi][nf], al[mi], bh_);
                }
            }
        }
        __syncthreads();
    }
    #pragma unroll
    for (int mi = 0; mi < 2; mi++)
        #pragma unroll
        for (int nf = 0; nf < 4; nf++) {
            int i = i0 + wm + 16 * mi + g;
            int d = wn + 8 * nf + 2 * t4;
            *(float2*)&g_ctx[((size_t)(b * SS + i) * HH + h) * DH + d] =
                make_float2(acc[mi][nf][0], acc[mi][nf][1]);
            *(float2*)&g_ctx[((size_t)(b * SS + i + 8) * HH + h) * DH + d] =
                make_float2(acc[mi][nf][2], acc[mi][nf][3]);
        }
}

// ---------------- launch ----------------
extern "C" void kernel_launch(void* const* d_in, const int* in_sizes, int n_in,
                              void* d_out, int out_size) {
    const float* query = (const float*)d_in[0];
    const float* key   = (const float*)d_in[1];
    const float* value = (const float*)d_in[2];
    const float* pos   = (const float*)d_in[3];
    const float* Wq    = (const float*)d_in[4];
    const float* Wk    = (const float*)d_in[5];
    const float* Wv    = (const float*)d_in[6];
    const float* Wp    = (const float*)d_in[7];
    const float* ub    = (const float*)d_in[8];
    const float* vb    = (const float*)d_in[9];
    const float* Wo    = (const float*)d_in[10];
    float* out = (float*)d_out;

    uint32_t *qh, *ql, *kh, *kl, *vh, *vl, *ph, *pl;
    float *pctx;
    cudaGetSymbolAddress((void**)&qh, g_qhi); cudaGetSymbolAddress((void**)&ql, g_qlo);
    cudaGetSymbolAddress((void**)&kh, g_khi); cudaGetSymbolAddress((void**)&kl, g_klo);
    cudaGetSymbolAddress((void**)&vh, g_vhi); cudaGetSymbolAddress((void**)&vl, g_vlo);
    cudaGetSymbolAddress((void**)&ph, g_phi); cudaGetSymbolAddress((void**)&pl, g_plo);
    cudaGetSymbolAddress((void**)&pctx, g_ctx);

    cudaFuncSetAttribute(score_tc, cudaFuncAttributeMaxDynamicSharedMemorySize, 98304);
    cudaFuncSetAttribute(ctx_tc, cudaFuncAttributeMaxDynamicSharedMemorySize, 55296);

    dim3 blk(256);

    // projections -> split bf16 outputs
    gemm_tc<true><<<dim3(4, 64), blk>>>(query, Wq, nullptr, qh, ql, BB*SS, DD, DD);
    gemm_tc<true><<<dim3(4, 64), blk>>>(key,   Wk, nullptr, kh, kl, BB*SS, DD, DD);
    gemm_tc<true><<<dim3(4, 64), blk>>>(value, Wv, nullptr, vh, vl, BB*SS, DD, DD);
    gemm_tc<true><<<dim3(4, 128), blk>>>(pos,  Wp, nullptr, ph, pl, BB*L2P, DD, DD);

    // fused content + positional score (tensor cores)
    score_tc<<<dim3(SS/64, SS/128, BB*HH), blk, 98304>>>(ub, vb);

    // softmax
    softmax_kernel<<<dim3(BB*HH*SS), blk>>>();

    // attn @ v
    ctx_tc<<<dim3(SS/128, BB*HH), blk, 55296>>>();

    // output projection (fp32 out)
    gemm_tc<false><<<dim3(4, 64), blk>>>(pctx, Wo, out, nullptr, nullptr, BB*SS, DD, DD);
}

// round 4
// speedup vs baseline: 2.6242x; 1.5653x over previous
#include <cuda_runtime.h>
#include <cuda_bf16.h>
#include <cstdint>

#define BB 8
#define SS 1024
#define DD 512
#define HH 8
#define DH 64
#define L2P 2047
#define SCALE 0.125f
#define MROWS (BB*SS)      // 8192
#define PROWS (BB*L2P)     // 16376

// ---------------- scratch ----------------
// pre-split inputs (A operands)
__device__ __nv_bfloat16 g_xqh[MROWS*DD], g_xql[MROWS*DD];
__device__ __nv_bfloat16 g_xkh[MROWS*DD], g_xkl[MROWS*DD];
__device__ __nv_bfloat16 g_xvh[MROWS*DD], g_xvl[MROWS*DD];
__device__ __nv_bfloat16 g_xph[PROWS*DD], g_xpl[PROWS*DD];
// pre-split weights [K][N]
__device__ __nv_bfloat16 g_wh[5*DD*DD], g_wl[5*DD*DD];
// projection outputs (split bf16), layout [b,s,h*64+dh]
__device__ __nv_bfloat16 g_quh[MROWS*DD], g_qul[MROWS*DD];
__device__ __nv_bfloat16 g_qvh[MROWS*DD], g_qvl[MROWS*DD];
__device__ __nv_bfloat16 g_kh[MROWS*DD],  g_kl[MROWS*DD];
__device__ __nv_bfloat16 g_vh[MROWS*DD],  g_vl[MROWS*DD];
__device__ __nv_bfloat16 g_ph[(PROWS+8)*DD], g_pl[(PROWS+8)*DD];
// score fp32, attn split, ctx split
__device__ float g_score[(size_t)BB*HH*SS*SS];
__device__ __nv_bfloat16 g_ah[(size_t)BB*HH*SS*SS], g_al[(size_t)BB*HH*SS*SS];
__device__ __nv_bfloat16 g_ch[MROWS*DD], g_cl[MROWS*DD];

// ---------------- helpers ----------------
__device__ __forceinline__ void split_pair(float x0, float x1, uint32_t& h, uint32_t& l) {
    __nv_bfloat162 hh = __floats2bfloat162_rn(x0, x1);
    float r0 = x0 - __bfloat162float(hh.x);
    float r1 = x1 - __bfloat162float(hh.y);
    __nv_bfloat162 ll = __floats2bfloat162_rn(r0, r1);
    h = *reinterpret_cast<uint32_t*>(&hh);
    l = *reinterpret_cast<uint32_t*>(&ll);
}
__device__ __forceinline__ void mma16816(float d[4], const uint32_t a[4], const uint32_t b[2]) {
    asm volatile(
        "mma.sync.aligned.m16n8k16.row.col.f32.bf16.bf16.f32 "
        "{%0,%1,%2,%3}, {%4,%5,%6,%7}, {%8,%9}, {%0,%1,%2,%3};\n"
        : "+f"(d[0]), "+f"(d[1]), "+f"(d[2]), "+f"(d[3])
        : "r"(a[0]), "r"(a[1]), "r"(a[2]), "r"(a[3]), "r"(b[0]), "r"(b[1]));
}
__device__ __forceinline__ void ldsm4(uint32_t r[4], uint32_t addr) {
    asm volatile("ldmatrix.sync.aligned.m8n8.x4.shared.b16 {%0,%1,%2,%3},[%4];"
        : "=r"(r[0]), "=r"(r[1]), "=r"(r[2]), "=r"(r[3]) : "r"(addr));
}
__device__ __forceinline__ void ldsm4t(uint32_t r[4], uint32_t addr) {
    asm volatile("ldmatrix.sync.aligned.m8n8.x4.trans.shared.b16 {%0,%1,%2,%3},[%4];"
        : "=r"(r[0]), "=r"(r[1]), "=r"(r[2]), "=r"(r[3]) : "r"(addr));
}
__device__ __forceinline__ void cp16(uint32_t dst, const void* src, bool pred) {
    int sz = pred ? 16 : 0;
    asm volatile("cp.async.cg.shared.global [%0],[%1],16,%2;\n"
        :: "r"(dst), "l"(src), "r"(sz));
}
__device__ __forceinline__ void cpcommit() { asm volatile("cp.async.commit_group;\n"); }
template<int N> __device__ __forceinline__ void cpwait() {
    asm volatile("cp.async.wait_group %0;\n" :: "n"(N));
}

// ---------------- split prepass ----------------
__global__ __launch_bounds__(256) void split_k(const float4* __restrict__ src,
                                               uint32_t* __restrict__ hi,
                                               uint32_t* __restrict__ lo, int n4) {
    int i = blockIdx.x * 256 + threadIdx.x;
    if (i < n4) {
        float4 v = src[i];
        uint32_t h0, l0, h1, l1;
        split_pair(v.x, v.y, h0, l0);
        split_pair(v.z, v.w, h1, l1);
        hi[2*i] = h0; hi[2*i+1] = h1;
        lo[2*i] = l0; lo[2*i+1] = l1;
    }
}

// ---------------- GEMM v2: C[M,N] = A[M,K] @ W[K,N], bf16-split operands -------------
// CTA 128x128, BK=32, 2-stage cp.async, ldmatrix. 8 warps 4x2, warp 32x64.
// EPI: 0 = fp32 out; 1 = split out (C1); 2 = dual-bias split out (C1 = acc+bias1, C2 = acc+bias2)
#define G_AL  10240
#define G_BH  20480
#define G_BL  29184
#define G_STG 37888
template<int EPI>
__global__ __launch_bounds__(256, 2) void gemm_v2(
    const __nv_bfloat16* __restrict__ Ah, const __nv_bfloat16* __restrict__ Al,
    const __nv_bfloat16* __restrict__ Bh, const __nv_bfloat16* __restrict__ Bl,
    float* __restrict__ Cf,
    __nv_bfloat16* __restrict__ C1h, __nv_bfloat16* __restrict__ C1l,
    __nv_bfloat16* __restrict__ C2h, __nv_bfloat16* __restrict__ C2l,
    const float* __restrict__ bias1, const float* __restrict__ bias2,
    int M, int N, int K) {
    extern __shared__ char smem[];
    uint32_t sb = (uint32_t)__cvta_generic_to_shared(smem);
    int tid = threadIdx.x, lane = tid & 31, wi = tid >> 5;
    int g = lane >> 2, t4 = lane & 3;
    int row0 = blockIdx.y * 128, col0 = blockIdx.x * 128;
    int wm = (wi & 3) * 32, wn = (wi >> 2) * 64;

    float acc[2][8][4];
    #pragma unroll
    for (int a = 0; a < 2; a++)
        #pragma unroll
        for (int b = 0; b < 8; b++)
            #pragma unroll
            for (int c = 0; c < 4; c++) acc[a][b][c] = 0.f;

    const int NIT = K >> 5;
    auto issue = [&](int it) {
        int k0 = it * 32;
        uint32_t st = sb + (it & 1) * G_STG;
        #pragma unroll
        for (int q = 0; q < 2; q++) {
            int c = q * 256 + tid;
            int m = c >> 2, seg = c & 3;
            bool ok = (row0 + m) < M;
            int mr = ok ? (row0 + m) : 0;
            const __nv_bfloat16* s = Ah + (size_t)mr * K + k0 + seg * 8;
            cp16(st + m * 80 + seg * 16, s, ok);
            const __nv_bfloat16* s2 = Al + (size_t)mr * K + k0 + seg * 8;
            cp16(st + G_AL + m * 80 + seg * 16, s2, ok);
        }
        #pragma unroll
        for (int q = 0; q < 2; q++) {
            int c = q * 256 + tid;
            int k = c >> 4, seg = c & 15;
            const __nv_bfloat16* s = Bh + (size_t)(k0 + k) * N + col0 + seg * 8;
            cp16(st + G_BH + k * 272 + seg * 16, s, true);
            const __nv_bfloat16* s2 = Bl + (size_t)(k0 + k) * N + col0 + seg * 8;
            cp16(st + G_BL + k * 272 + seg * 16, s2, true);
        }
        cpcommit();
    };

    issue(0);
    for (int it = 0; it < NIT; it++) {
        if (it + 1 < NIT) { issue(it + 1); cpwait<1>(); }
        else cpwait<0>();
        __syncthreads();
        uint32_t st = sb + (it & 1) * G_STG;
        #pragma unroll
        for (int kk = 0; kk < 32; kk += 16) {
            uint32_t ah[2][4], al[2][4];
            #pragma unroll
            for (int mi = 0; mi < 2; mi++) {
                uint32_t ad = st + (wm + 16 * mi + (lane & 15)) * 80 + (kk + ((lane >> 4) << 3)) * 2;
                ldsm4(ah[mi], ad);
                ldsm4(al[mi], ad + G_AL);
            }
            #pragma unroll
            for (int nh = 0; nh < 4; nh++) {
                int n0 = wn + 16 * nh;
                uint32_t bd = st + G_BH + (kk + (lane & 7) + (lane & 8)) * 272
                              + (n0 + ((lane & 16) >> 1)) * 2;
                uint32_t bh4[4], bl4[4];
                ldsm4t(bh4, bd);
                ldsm4t(bl4, bd + (G_BL - G_BH));
                #pragma unroll
                for (int half = 0; half < 2; half++) {
                    int nf = 2 * nh + half;
                    uint32_t bhh[2] = {bh4[2*half], bh4[2*half+1]};
                    uint32_t bll[2] = {bl4[2*half], bl4[2*half+1]};
                    #pragma unroll
                    for (int mi = 0; mi < 2; mi++) {
                        mma16816(acc[mi][nf], ah[mi], bhh);
                        mma16816(acc[mi][nf], ah[mi], bll);
                        mma16816(acc[mi][nf], al[mi], bhh);
                    }
                }
            }
        }
        __syncthreads();
    }

    #pragma unroll
    for (int mi = 0; mi < 2; mi++)
        #pragma unroll
        for (int nf = 0; nf < 8; nf++) {
            #pragma unroll
            for (int half = 0; half < 2; half++) {
                int r = row0 + wm + 16 * mi + g + 8 * half;
                int c = col0 + wn + 8 * nf + 2 * t4;
                float v0 = acc[mi][nf][2*half], v1 = acc[mi][nf][2*half+1];
                if (r < M) {
                    if (EPI == 0) {
                        *(float2*)&Cf[(size_t)r * N + c] = make_float2(v0, v1);
                    } else if (EPI == 1) {
                        uint32_t h, l;
                        split_pair(v0, v1, h, l);
                        *(uint32_t*)&C1h[(size_t)r * N + c] = h;
                        *(uint32_t*)&C1l[(size_t)r * N + c] = l;
                    } else {
                        uint32_t h, l;
                        split_pair(v0 + bias1[c], v1 + bias1[c+1], h, l);
                        *(uint32_t*)&C1h[(size_t)r * N + c] = h;
                        *(uint32_t*)&C1l[(size_t)r * N + c] = l;
                        split_pair(v0 + bias2[c], v1 + bias2[c+1], h, l);
                        *(uint32_t*)&C2h[(size_t)r * N + c] = h;
                        *(uint32_t*)&C2l[(size_t)r * N + c] = l;
                    }
                }
            }
        }
}

// ---------------- score v2 ----------------
// CTA 128 i x 64 j; content = QU @ K^T, R = QV @ P^T (192-window), gather+combine.
// 2-stage over d-chunks of 32. 8 warps: wm=(wi&3)*32, wn=wi>>2.
#define S_QUH 0
#define S_QUL 10240
#define S_QVH 20480
#define S_QVL 30720
#define S_KH  40960
#define S_KL  46080
#define S_PH  51200
#define S_PL  66560
#define S_STG 81920
__global__ __launch_bounds__(256) void score_v2() {
    extern __shared__ char smem[];
    uint32_t sb = (uint32_t)__cvta_generic_to_shared(smem);
    float* Rs = (float*)smem;

    int tid = threadIdx.x, lane = tid & 31, wi = tid >> 5;
    int g = lane >> 2, t4 = lane & 3;
    int bh = blockIdx.z, b = bh >> 3, h = bh & 7;
    int i0 = blockIdx.y * 128, j0 = blockIdx.x * 64;
    int pbase = 896 + j0 - i0;
    int wm = (wi & 3) * 32, wn = wi >> 2;

    float accR[2][12][4], accC[2][4][4];
    #pragma unroll
    for (int a = 0; a < 2; a++) {
        #pragma unroll
        for (int c = 0; c < 12; c++)
            #pragma unroll
            for (int e = 0; e < 4; e++) accR[a][c][e] = 0.f;
        #pragma unroll
        for (int c = 0; c < 4; c++)
            #pragma unroll
            for (int e = 0; e < 4; e++) accC[a][c][e] = 0.f;
    }

    auto issue = [&](int it) {
        int dc = h * DH + it * 32;
        uint32_t st = sb + (it & 1) * S_STG;
        #pragma unroll
        for (int q = 0; q < 2; q++) {
            int c = q * 256 + tid;
            int m = c >> 2, seg = c & 3;
            size_t src = (size_t)(b * SS + i0 + m) * DD + dc + seg * 8;
            uint32_t d = st + m * 80 + seg * 16;
            cp16(d + S_QUH, g_quh + src, true);
            cp16(d + S_QUL, g_qul + src, true);
            cp16(d + S_QVH, g_qvh + src, true);
            cp16(d + S_QVL, g_qvl + src, true);
        }
        {
            int m = tid >> 2, seg = tid & 3;
            size_t src = (size_t)(b * SS + j0 + m) * DD + dc + seg * 8;
            uint32_t d = st + m * 80 + seg * 16;
            cp16(d + S_KH, g_kh + src, true);
            cp16(d + S_KL, g_kl + src, true);
        }
        #pragma unroll
        for (int q = 0; q < 3; q++) {
            int c = q * 256 + tid;
            int tr = c >> 2, seg = c & 3;
            bool ok = tr < 191;
            int trc = ok ? tr : 0;
            size_t src = (size_t)(b * L2P + pbase + trc) * DD + dc + seg * 8;
            uint32_t d = st + tr * 80 + seg * 16;
            cp16(d + S_PH, g_ph + src, ok);
            cp16(d + S_PL, g_pl + src, ok);
        }
        cpcommit();
    };

    issue(0);
    for (int it = 0; it < 2; it++) {
        if (it == 0) { issue(1); cpwait<1>(); }
        else cpwait<0>();
        __syncthreads();
        uint32_t st = sb + (it & 1) * S_STG;
        #pragma unroll
        for (int kk = 0; kk < 32; kk += 16) {
            uint32_t uh[2][4], ul[2][4], vh[2][4], vl[2][4];
            #pragma unroll
            for (int mi = 0; mi < 2; mi++) {
                uint32_t ad = st + (wm + 16 * mi + (lane & 15)) * 80 + (kk + ((lane >> 4) << 3)) * 2;
                ldsm4(uh[mi], ad + S_QUH);
                ldsm4(ul[mi], ad + S_QUL);
                ldsm4(vh[mi], ad + S_QVH);
                ldsm4(vl[mi], ad + S_QVL);
            }
            // content: K frags, non-trans (rows = n)
            #pragma unroll
            for (int nh = 0; nh < 2; nh++) {
                int n0 = wn * 32 + 16 * nh;
                uint32_t bd = st + (n0 + (lane & 15)) * 80 + (kk + ((lane >> 4) << 3)) * 2;
                uint32_t bh4[4], bl4[4];
                ldsm4(bh4, bd + S_KH);
                ldsm4(bl4, bd + S_KL);
                #pragma unroll
                for (int half = 0; half < 2; half++) {
                    int nf = 2 * nh + half;
                    uint32_t bhh[2] = {bh4[half], bh4[half+2]};
                    uint32_t bll[2] = {bl4[half], bl4[half+2]};
                    #pragma unroll
                    for (int mi = 0; mi < 2; mi++) {
                        mma16816(accC[mi][nf], uh[mi], bhh);
                        mma16816(accC[mi][nf], uh[mi], bll);
                        mma16816(accC[mi][nf], ul[mi], bhh);
                    }
                }
            }
            // pos: P frags
            #pragma unroll
            for (int nh = 0; nh < 6; nh++) {
                int n0 = wn * 96 + 16 * nh;
                uint32_t bd = st + (n0 + (lane & 15)) * 80 + (kk + ((lane >> 4) << 3)) * 2;
                uint32_t bh4[4], bl4[4];
                ldsm4(bh4, bd + S_PH);
                ldsm4(bl4, bd + S_PL);
                #pragma unroll
                for (int half = 0; half < 2; half++) {
                    int nf = 2 * nh + half;
                    uint32_t bhh[2] = {bh4[half], bh4[half+2]};
                    uint32_t bll[2] = {bl4[half], bl4[half+2]};
                    #pragma unroll
                    for (int mi = 0; mi < 2; mi++) {
                        mma16816(accR[mi][nf], vh[mi], bhh);
                        mma16816(accR[mi][nf], vh[mi], bll);
                        mma16816(accR[mi][nf], vl[mi], bhh);
                    }
                }
            }
        }
        __syncthreads();
    }

    // dump R to smem
    #pragma unroll
    for (int mi = 0; mi < 2; mi++)
        #pragma unroll
        for (int nf = 0; nf < 12; nf++) {
            int il = wm + 16 * mi;
            int tc = wn * 96 + 8 * nf + 2 * t4;
            Rs[(il + g) * 192 + tc]         = accR[mi][nf][0];
            Rs[(il + g) * 192 + tc + 1]     = accR[mi][nf][1];
            Rs[(il + g + 8) * 192 + tc]     = accR[mi][nf][2];
            Rs[(il + g + 8) * 192 + tc + 1] = accR[mi][nf][3];
        }
    __syncthreads();

    // gather + combine + store
    #pragma unroll
    for (int mi = 0; mi < 2; mi++)
        #pragma unroll
        for (int nf = 0; nf < 4; nf++) {
            int il = wm + 16 * mi + g;
            int jl = wn * 32 + 8 * nf + 2 * t4;
            float p00 = Rs[il * 192 + (jl - il + 127)];
            float p01 = Rs[il * 192 + (jl + 1 - il + 127)];
            int il2 = il + 8;
            float p10 = Rs[il2 * 192 + (jl - il2 + 127)];
            float p11 = Rs[il2 * 192 + (jl + 1 - il2 + 127)];
            size_t o0 = ((size_t)bh * SS + i0 + il) * SS + j0 + jl;
            size_t o1 = ((size_t)bh * SS + i0 + il2) * SS + j0 + jl;
            *(float2*)&g_score[o0] = make_float2((accC[mi][nf][0] + p00) * SCALE,
                                                 (accC[mi][nf][1] + p01) * SCALE);
            *(float2*)&g_score[o1] = make_float2((accC[mi][nf][2] + p10) * SCALE,
                                                 (accC[mi][nf][3] + p11) * SCALE);
        }
}

// ---------------- softmax -> split bf16 attn ----------------
__global__ __launch_bounds__(256) void softmax_split() {
    __shared__ float redm[8];
    __shared__ float reds[8];
    size_t row = blockIdx.x;
    const float4* r = (const float4*)(g_score + row * SS);
    int tid = threadIdx.x;
    float4 v = r[tid];
    float m = fmaxf(fmaxf(v.x, v.y), fmaxf(v.z, v.w));
    #pragma unroll
    for (int o = 16; o > 0; o >>= 1) m = fmaxf(m, __shfl_xor_sync(0xffffffffu, m, o));
    if ((tid & 31) == 0) redm[tid >> 5] = m;
    __syncthreads();
    m = redm[0];
    #pragma unroll
    for (int w = 1; w < 8; w++) m = fmaxf(m, redm[w]);
    v.x = __expf(v.x - m); v.y = __expf(v.y - m);
    v.z = __expf(v.z - m); v.w = __expf(v.w - m);
    float s = v.x + v.y + v.z + v.w;
    #pragma unroll
    for (int o = 16; o > 0; o >>= 1) s += __shfl_xor_sync(0xffffffffu, s, o);
    if ((tid & 31) == 0) reds[tid >> 5] = s;
    __syncthreads();
    s = reds[0];
    #pragma unroll
    for (int w = 1; w < 8; w++) s += reds[w];
    float inv = 1.0f / s;
    v.x *= inv; v.y *= inv; v.z *= inv; v.w *= inv;
    uint32_t h0, l0, h1, l1;
    split_pair(v.x, v.y, h0, l0);
    split_pair(v.z, v.w, h1, l1);
    uint32_t* ph = (uint32_t*)g_ah + row * 512 + tid * 2;
    uint32_t* pl = (uint32_t*)g_al + row * 512 + tid * 2;
    ph[0] = h0; ph[1] = h1;
    pl[0] = l0; pl[1] = l1;
}

// ---------------- ctx v2: ctx = attn @ v ----------------
// CTA 128 i x 64 d, BK=64 over j, 2-stage cp.async, ldmatrix. warps 4x2, warp 32x32.
#define C_AL  18432
#define C_BH  36864
#define C_BL  46080
#define C_STG 55296
__global__ __launch_bounds__(256, 2) void ctx_v2() {
    extern __shared__ char smem[];
    uint32_t sb = (uint32_t)__cvta_generic_to_shared(smem);
    int tid = threadIdx.x, lane = tid & 31, wi = tid >> 5;
    int g = lane >> 2, t4 = lane & 3;
    int bh = blockIdx.y, b = bh >> 3, h = bh & 7;
    int i0 = blockIdx.x * 128;
    int wm = (wi & 3) * 32, wn = (wi >> 2) * 32;
    const __nv_bfloat16* Abh = g_ah + (size_t)bh * SS * SS;
    const __nv_bfloat16* Abl = g_al + (size_t)bh * SS * SS;

    float acc[2][4][4];
    #pragma unroll
    for (int a = 0; a < 2; a++)
        #pragma unroll
        for (int c = 0; c < 4; c++)
            #pragma unroll
            for (int e = 0; e < 4; e++) acc[a][c][e] = 0.f;

    auto issue = [&](int it) {
        int jc = it * 64;
        uint32_t st = sb + (it & 1) * C_STG;
        #pragma unroll
        for (int q = 0; q < 4; q++) {
            int c = q * 256 + tid;
            int m = c >> 3, seg = c & 7;
            size_t src = (size_t)(i0 + m) * SS + jc + seg * 8;
            uint32_t d = st + m * 144 + seg * 16;
            cp16(d, Abh + src, true);
            cp16(d + C_AL, Abl + src, true);
        }
        #pragma unroll
        for (int q = 0; q < 2; q++) {
            int c = q * 256 + tid;
            int k = c >> 3, seg = c & 7;
            size_t src = (size_t)(b * SS + jc + k) * DD + h * DH + seg * 8;
            uint32_t d = st + k * 144 + seg * 16;
            cp16(d + C_BH, g_vh + src, true);
            cp16(d + C_BL, g_vl + src, true);
        }
        cpcommit();
    };

    issue(0);
    for (int it = 0; it < 16; it++) {
        if (it + 1 < 16) { issue(it + 1); cpwait<1>(); }
        else cpwait<0>();
        __syncthreads();
        uint32_t st = sb + (it & 1) * C_STG;
        #pragma unroll
        for (int kk = 0; kk < 64; kk += 16) {
            uint32_t ah[2][4], al[2][4];
            #pragma unroll
            for (int mi = 0; mi < 2; mi++) {
                uint32_t ad = st + (wm + 16 * mi + (lane & 15)) * 144 + (kk + ((lane >> 4) << 3)) * 2;
                ldsm4(ah[mi], ad);
                ldsm4(al[mi], ad + C_AL);
            }
            #pragma unroll
            for (int nh = 0; nh < 2; nh++) {
                int n0 = wn + 16 * nh;
                uint32_t bd = st + C_BH + (kk + (lane & 7) + (lane & 8)) * 144
                              + (n0 + ((lane & 16) >> 1)) * 2;
                uint32_t bh4[4], bl4[4];
                ldsm4t(bh4, bd);
                ldsm4t(bl4, bd + (C_BL - C_BH));
                #pragma unroll
                for (int half = 0; half < 2; half++) {
                    int nf = 2 * nh + half;
                    uint32_t bhh[2] = {bh4[2*half], bh4[2*half+1]};
                    uint32_t bll[2] = {bl4[2*half], bl4[2*half+1]};
                    #pragma unroll
                    for (int mi = 0; mi < 2; mi++) {
                        mma16816(acc[mi][nf], ah[mi], bhh);
                        mma16816(acc[mi][nf], ah[mi], bll);
                        mma16816(acc[mi][nf], al[mi], bhh);
                    }
                }
            }
        }
        __syncthreads();
    }

    #pragma unroll
    for (int mi = 0; mi < 2; mi++)
        #pragma unroll
        for (int nf = 0; nf < 4; nf++)
            #pragma unroll
            for (int half = 0; half < 2; half++) {
                int i = i0 + wm + 16 * mi + g + 8 * half;
                int d = wn + 8 * nf + 2 * t4;
                uint32_t hh, ll;
                split_pair(acc[mi][nf][2*half], acc[mi][nf][2*half+1], hh, ll);
                size_t o = (size_t)(b * SS + i) * DD + h * DH + d;
                *(uint32_t*)&g_ch[o] = hh;
                *(uint32_t*)&g_cl[o] = ll;
            }
}

// ---------------- launch ----------------
extern "C" void kernel_launch(void* const* d_in, const int* in_sizes, int n_in,
                              void* d_out, int out_size) {
    const float* query = (const float*)d_in[0];
    const float* key   = (const float*)d_in[1];
    const float* value = (const float*)d_in[2];
    const float* pos   = (const float*)d_in[3];
    const float* Wq    = (const float*)d_in[4];
    const float* Wk    = (const float*)d_in[5];
    const float* Wv    = (const float*)d_in[6];
    const float* Wp    = (const float*)d_in[7];
    const float* ub    = (const float*)d_in[8];
    const float* vb    = (const float*)d_in[9];
    const float* Wo    = (const float*)d_in[10];
    float* out = (float*)d_out;

    __nv_bfloat16 *xqh,*xql,*xkh,*xkl,*xvh,*xvl,*xph,*xpl,*wh,*wl;
    __nv_bfloat16 *quh,*qul,*qvh,*qvl,*kh,*kl,*vh,*vl,*ph,*pl,*ch,*cl;
    cudaGetSymbolAddress((void**)&xqh, g_xqh); cudaGetSymbolAddress((void**)&xql, g_xql);
    cudaGetSymbolAddress((void**)&xkh, g_xkh); cudaGetSymbolAddress((void**)&xkl, g_xkl);
    cudaGetSymbolAddress((void**)&xvh, g_xvh); cudaGetSymbolAddress((void**)&xvl, g_xvl);
    cudaGetSymbolAddress((void**)&xph, g_xph); cudaGetSymbolAddress((void**)&xpl, g_xpl);
    cudaGetSymbolAddress((void**)&wh, g_wh);   cudaGetSymbolAddress((void**)&wl, g_wl);
    cudaGetSymbolAddress((void**)&quh, g_quh); cudaGetSymbolAddress((void**)&qul, g_qul);
    cudaGetSymbolAddress((void**)&qvh, g_qvh); cudaGetSymbolAddress((void**)&qvl, g_qvl);
    cudaGetSymbolAddress((void**)&kh, g_kh);   cudaGetSymbolAddress((void**)&kl, g_kl);
    cudaGetSymbolAddress((void**)&vh, g_vh);   cudaGetSymbolAddress((void**)&vl, g_vl);
    cudaGetSymbolAddress((void**)&ph, g_ph);   cudaGetSymbolAddress((void**)&pl, g_pl);
    cudaGetSymbolAddress((void**)&ch, g_ch);   cudaGetSymbolAddress((void**)&cl, g_cl);

    static bool attr_done = false;
    if (!attr_done) {
        cudaFuncSetAttribute(gemm_v2<0>, cudaFuncAttributeMaxDynamicSharedMemorySize, 2*G_STG);
        cudaFuncSetAttribute(gemm_v2<1>, cudaFuncAttributeMaxDynamicSharedMemorySize, 2*G_STG);
        cudaFuncSetAttribute(gemm_v2<2>, cudaFuncAttributeMaxDynamicSharedMemorySize, 2*G_STG);
        cudaFuncSetAttribute(score_v2,  cudaFuncAttributeMaxDynamicSharedMemorySize, 2*S_STG);
        cudaFuncSetAttribute(ctx_v2,    cudaFuncAttributeMaxDynamicSharedMemorySize, 2*C_STG);
        attr_done = true;
    }

    dim3 blk(256);

    // split prepass (inputs + weights)
    split_k<<<(MROWS*DD/4 + 255)/256, blk>>>((const float4*)query, (uint32_t*)xqh, (uint32_t*)xql, MROWS*DD/4);
    split_k<<<(MROWS*DD/4 + 255)/256, blk>>>((const float4*)key,   (uint32_t*)xkh, (uint32_t*)xkl, MROWS*DD/4);
    split_k<<<(MROWS*DD/4 + 255)/256, blk>>>((const float4*)value, (uint32_t*)xvh, (uint32_t*)xvl, MROWS*DD/4);
    split_k<<<(PROWS*DD/4 + 255)/256, blk>>>((const float4*)pos,   (uint32_t*)xph, (uint32_t*)xpl, PROWS*DD/4);
    split_k<<<(DD*DD/4 + 255)/256, blk>>>((const float4*)Wq, (uint32_t*)(wh + 0*DD*DD), (uint32_t*)(wl + 0*DD*DD), DD*DD/4);
    split_k<<<(DD*DD/4 + 255)/256, blk>>>((const float4*)Wk, (uint32_t*)(wh + 1*DD*DD), (uint32_t*)(wl + 1*DD*DD), DD*DD/4);
    split_k<<<(DD*DD/4 + 255)/256, blk>>>((const float4*)Wv, (uint32_t*)(wh + 2*DD*DD), (uint32_t*)(wl + 2*DD*DD), DD*DD/4);
    split_k<<<(DD*DD/4 + 255)/256, blk>>>((const float4*)Wp, (uint32_t*)(wh + 3*DD*DD), (uint32_t*)(wl + 3*DD*DD), DD*DD/4);
    split_k<<<(DD*DD/4 + 255)/256, blk>>>((const float4*)Wo, (uint32_t*)(wh + 4*DD*DD), (uint32_t*)(wl + 4*DD*DD), DD*DD/4);

    // projections
    gemm_v2<2><<<dim3(4, 64), blk, 2*G_STG>>>(xqh, xql, wh + 0*DD*DD, wl + 0*DD*DD,
        nullptr, quh, qul, qvh, qvl, ub, vb, MROWS, DD, DD);
    gemm_v2<1><<<dim3(4, 64), blk, 2*G_STG>>>(xkh, xkl, wh + 1*DD*DD, wl + 1*DD*DD,
        nullptr, kh, kl, nullptr, nullptr, nullptr, nullptr, MROWS, DD, DD);
    gemm_v2<1><<<dim3(4, 64), blk, 2*G_STG>>>(xvh, xvl, wh + 2*DD*DD, wl + 2*DD*DD,
        nullptr, vh, vl, nullptr, nullptr, nullptr, nullptr, MROWS, DD, DD);
    gemm_v2<1><<<dim3(4, 128), blk, 2*G_STG>>>(xph, xpl, wh + 3*DD*DD, wl + 3*DD*DD,
        nullptr, ph, pl, nullptr, nullptr, nullptr, nullptr, PROWS, DD, DD);

    // fused content + positional score
    score_v2<<<dim3(SS/64, SS/128, BB*HH), blk, 2*S_STG>>>();

    // softmax + split
    softmax_split<<<dim3(BB*HH*SS), blk>>>();

    // attn @ v
    ctx_v2<<<dim3(SS/128, BB*HH), blk, 2*C_STG>>>();

    // output projection
    gemm_v2<0><<<dim3(4, 64), blk, 2*G_STG>>>(ch, cl, wh + 4*DD*DD, wl + 4*DD*DD,
        out, nullptr, nullptr, nullptr, nullptr, nullptr, nullptr, MROWS, DD, DD);
}

// round 5
// speedup vs baseline: 3.1538x; 1.2018x over previous
#include <cuda_runtime.h>
#include <cuda_bf16.h>
#include <cstdint>

#define BB 8
#define SS 1024
#define DD 512
#define HH 8
#define DH 64
#define L2P 2047
#define SCALE 0.125f
#define MROWS (BB*SS)      // 8192
#define PROWS (BB*L2P)     // 16376

// ---------------- scratch ----------------
__device__ __nv_bfloat16 g_xqh[MROWS*DD], g_xql[MROWS*DD];
__device__ __nv_bfloat16 g_xkh[MROWS*DD], g_xkl[MROWS*DD];
__device__ __nv_bfloat16 g_xvh[MROWS*DD], g_xvl[MROWS*DD];
__device__ __nv_bfloat16 g_xph[PROWS*DD], g_xpl[PROWS*DD];
__device__ __nv_bfloat16 g_wh[5*DD*DD], g_wl[5*DD*DD];
__device__ __nv_bfloat16 g_quh[MROWS*DD], g_qul[MROWS*DD];
__device__ __nv_bfloat16 g_qvh[MROWS*DD], g_qvl[MROWS*DD];
__device__ __nv_bfloat16 g_kh[MROWS*DD],  g_kl[MROWS*DD];
__device__ __nv_bfloat16 g_vh[MROWS*DD],  g_vl[MROWS*DD];
__device__ __nv_bfloat16 g_ph[(PROWS+8)*DD], g_pl[(PROWS+8)*DD];
__device__ __nv_bfloat16 g_ch[MROWS*DD], g_cl[MROWS*DD];

// ---------------- helpers ----------------
__device__ __forceinline__ void split_pair(float x0, float x1, uint32_t& h, uint32_t& l) {
    __nv_bfloat162 hh = __floats2bfloat162_rn(x0, x1);
    float r0 = x0 - __bfloat162float(hh.x);
    float r1 = x1 - __bfloat162float(hh.y);
    __nv_bfloat162 ll = __floats2bfloat162_rn(r0, r1);
    h = *reinterpret_cast<uint32_t*>(&hh);
    l = *reinterpret_cast<uint32_t*>(&ll);
}
__device__ __forceinline__ void mma16816(float d[4], const uint32_t a[4], const uint32_t b[2]) {
    asm volatile(
        "mma.sync.aligned.m16n8k16.row.col.f32.bf16.bf16.f32 "
        "{%0,%1,%2,%3}, {%4,%5,%6,%7}, {%8,%9}, {%0,%1,%2,%3};\n"
        : "+f"(d[0]), "+f"(d[1]), "+f"(d[2]), "+f"(d[3])
        : "r"(a[0]), "r"(a[1]), "r"(a[2]), "r"(a[3]), "r"(b[0]), "r"(b[1]));
}
__device__ __forceinline__ void mma3(float d[4], const uint32_t ah[4], const uint32_t al[4],
                                     const uint32_t bh[2], const uint32_t bl[2]) {
    mma16816(d, ah, bh);
    mma16816(d, ah, bl);
    mma16816(d, al, bh);
}
__device__ __forceinline__ void ldsm4(uint32_t r[4], uint32_t addr) {
    asm volatile("ldmatrix.sync.aligned.m8n8.x4.shared.b16 {%0,%1,%2,%3},[%4];"
        : "=r"(r[0]), "=r"(r[1]), "=r"(r[2]), "=r"(r[3]) : "r"(addr));
}
__device__ __forceinline__ void ldsm4t(uint32_t r[4], uint32_t addr) {
    asm volatile("ldmatrix.sync.aligned.m8n8.x4.trans.shared.b16 {%0,%1,%2,%3},[%4];"
        : "=r"(r[0]), "=r"(r[1]), "=r"(r[2]), "=r"(r[3]) : "r"(addr));
}
__device__ __forceinline__ void cp16(uint32_t dst, const void* src, bool pred) {
    int sz = pred ? 16 : 0;
    asm volatile("cp.async.cg.shared.global [%0],[%1],16,%2;\n"
        :: "r"(dst), "l"(src), "r"(sz));
}
__device__ __forceinline__ void cpcommit() { asm volatile("cp.async.commit_group;\n"); }
template<int N> __device__ __forceinline__ void cpwait() {
    asm volatile("cp.async.wait_group %0;\n" :: "n"(N));
}

// ---------------- split prepass ----------------
__global__ __launch_bounds__(256) void split_k(const float4* __restrict__ src,
                                               uint32_t* __restrict__ hi,
                                               uint32_t* __restrict__ lo, int n4) {
    int i = blockIdx.x * 256 + threadIdx.x;
    if (i < n4) {
        float4 v = src[i];
        uint32_t h0, l0, h1, l1;
        split_pair(v.x, v.y, h0, l0);
        split_pair(v.z, v.w, h1, l1);
        hi[2*i] = h0; hi[2*i+1] = h1;
        lo[2*i] = l0; lo[2*i+1] = l1;
    }
}

// ---------------- GEMM (unchanged from R4) ----------------
#define G_AL  10240
#define G_BH  20480
#define G_BL  29184
#define G_STG 37888
template<int EPI>
__global__ __launch_bounds__(256, 2) void gemm_v2(
    const __nv_bfloat16* __restrict__ Ah, const __nv_bfloat16* __restrict__ Al,
    const __nv_bfloat16* __restrict__ Bh, const __nv_bfloat16* __restrict__ Bl,
    float* __restrict__ Cf,
    __nv_bfloat16* __restrict__ C1h, __nv_bfloat16* __restrict__ C1l,
    __nv_bfloat16* __restrict__ C2h, __nv_bfloat16* __restrict__ C2l,
    const float* __restrict__ bias1, const float* __restrict__ bias2,
    int M, int N, int K) {
    extern __shared__ char smem[];
    uint32_t sb = (uint32_t)__cvta_generic_to_shared(smem);
    int tid = threadIdx.x, lane = tid & 31, wi = tid >> 5;
    int g = lane >> 2, t4 = lane & 3;
    int row0 = blockIdx.y * 128, col0 = blockIdx.x * 128;
    int wm = (wi & 3) * 32, wn = (wi >> 2) * 64;

    float acc[2][8][4];
    #pragma unroll
    for (int a = 0; a < 2; a++)
        #pragma unroll
        for (int b = 0; b < 8; b++)
            #pragma unroll
            for (int c = 0; c < 4; c++) acc[a][b][c] = 0.f;

    const int NIT = K >> 5;
    auto issue = [&](int it) {
        int k0 = it * 32;
        uint32_t st = sb + (it & 1) * G_STG;
        #pragma unroll
        for (int q = 0; q < 2; q++) {
            int c = q * 256 + tid;
            int m = c >> 2, seg = c & 3;
            bool ok = (row0 + m) < M;
            int mr = ok ? (row0 + m) : 0;
            cp16(st + m * 80 + seg * 16, Ah + (size_t)mr * K + k0 + seg * 8, ok);
            cp16(st + G_AL + m * 80 + seg * 16, Al + (size_t)mr * K + k0 + seg * 8, ok);
        }
        #pragma unroll
        for (int q = 0; q < 2; q++) {
            int c = q * 256 + tid;
            int k = c >> 4, seg = c & 15;
            cp16(st + G_BH + k * 272 + seg * 16, Bh + (size_t)(k0 + k) * N + col0 + seg * 8, true);
            cp16(st + G_BL + k * 272 + seg * 16, Bl + (size_t)(k0 + k) * N + col0 + seg * 8, true);
        }
        cpcommit();
    };

    issue(0);
    for (int it = 0; it < NIT; it++) {
        if (it + 1 < NIT) { issue(it + 1); cpwait<1>(); }
        else cpwait<0>();
        __syncthreads();
        uint32_t st = sb + (it & 1) * G_STG;
        #pragma unroll
        for (int kk = 0; kk < 32; kk += 16) {
            uint32_t ah[2][4], al[2][4];
            #pragma unroll
            for (int mi = 0; mi < 2; mi++) {
                uint32_t ad = st + (wm + 16 * mi + (lane & 15)) * 80 + (kk + ((lane >> 4) << 3)) * 2;
                ldsm4(ah[mi], ad);
                ldsm4(al[mi], ad + G_AL);
            }
            #pragma unroll
            for (int nh = 0; nh < 4; nh++) {
                int n0 = wn + 16 * nh;
                uint32_t bd = st + G_BH + (kk + (lane & 7) + (lane & 8)) * 272
                              + (n0 + ((lane & 16) >> 1)) * 2;
                uint32_t bh4[4], bl4[4];
                ldsm4t(bh4, bd);
                ldsm4t(bl4, bd + (G_BL - G_BH));
                #pragma unroll
                for (int half = 0; half < 2; half++) {
                    int nf = 2 * nh + half;
                    uint32_t bhh[2] = {bh4[2*half], bh4[2*half+1]};
                    uint32_t bll[2] = {bl4[2*half], bl4[2*half+1]};
                    #pragma unroll
                    for (int mi = 0; mi < 2; mi++)
                        mma3(acc[mi][nf], ah[mi], al[mi], bhh, bll);
                }
            }
        }
        __syncthreads();
    }

    #pragma unroll
    for (int mi = 0; mi < 2; mi++)
        #pragma unroll
        for (int nf = 0; nf < 8; nf++)
            #pragma unroll
            for (int half = 0; half < 2; half++) {
                int r = row0 + wm + 16 * mi + g + 8 * half;
                int c = col0 + wn + 8 * nf + 2 * t4;
                float v0 = acc[mi][nf][2*half], v1 = acc[mi][nf][2*half+1];
                if (r < M) {
                    if (EPI == 0) {
                        *(float2*)&Cf[(size_t)r * N + c] = make_float2(v0, v1);
                    } else if (EPI == 1) {
                        uint32_t h, l;
                        split_pair(v0, v1, h, l);
                        *(uint32_t*)&C1h[(size_t)r * N + c] = h;
                        *(uint32_t*)&C1l[(size_t)r * N + c] = l;
                    } else {
                        uint32_t h, l;
                        split_pair(v0 + bias1[c], v1 + bias1[c+1], h, l);
                        *(uint32_t*)&C1h[(size_t)r * N + c] = h;
                        *(uint32_t*)&C1l[(size_t)r * N + c] = l;
                        split_pair(v0 + bias2[c], v1 + bias2[c+1], h, l);
                        *(uint32_t*)&C2h[(size_t)r * N + c] = h;
                        *(uint32_t*)&C2l[(size_t)r * N + c] = l;
                    }
                }
            }
}

// ---------------- fused flash attention (score + softmax + attn@V) ----------------
// CTA: 128 i-rows for one (b,h); streams 16 j-tiles of 64.
#define SQ_UH 0
#define SQ_UL 18432
#define SQ_VH 36864
#define SQ_VL 55296
#define SK_H  73728
#define SK_L  82944
#define SP_H  92160
#define SP_L  119808
#define SV_H  147456
#define SV_L  156672
#define SATT  165888
#define SATT_L (SATT + 18432)
#define SSTAT 202752
#define FL_SMEM 204288

__global__ __launch_bounds__(256, 1) void flash_v1() {
    extern __shared__ char smem[];
    uint32_t sb = (uint32_t)__cvta_generic_to_shared(smem);
    float* S32  = (float*)(smem + SATT);
    float* m_s  = (float*)(smem + SSTAT);
    float* l_s  = m_s + 128;
    float* al_s = m_s + 256;

    int tid = threadIdx.x, lane = tid & 31, wi = tid >> 5;
    int g = lane >> 2, t4 = lane & 3;
    int bh = blockIdx.y, b = bh >> 3, h = bh & 7;
    int i0 = blockIdx.x * 128;
    int wm = (wi & 3) * 32, wcol = wi >> 2;

    float accO[2][4][4];
    #pragma unroll
    for (int a = 0; a < 2; a++)
        #pragma unroll
        for (int c = 0; c < 4; c++)
            #pragma unroll
            for (int e = 0; e < 4; e++) accO[a][c][e] = 0.f;

    auto issue_kp = [&](int jt) {
        int j0 = jt * 64;
        #pragma unroll
        for (int q = 0; q < 2; q++) {
            int c = q * 256 + tid;
            int row = c >> 3, seg = c & 7;
            size_t src = (size_t)(b * SS + j0 + row) * DD + h * DH + seg * 8;
            uint32_t d = sb + row * 144 + seg * 16;
            cp16(d + SK_H, g_kh + src, true);
            cp16(d + SK_L, g_kl + src, true);
        }
        int pb = 896 + j0 - i0;
        #pragma unroll
        for (int q = 0; q < 6; q++) {
            int c = q * 256 + tid;
            int row = c >> 3, seg = c & 7;
            bool ok = row < 191;
            int rc = ok ? row : 0;
            size_t src = (size_t)(b * L2P + pb + rc) * DD + h * DH + seg * 8;
            uint32_t d = sb + row * 144 + seg * 16;
            cp16(d + SP_H, g_ph + src, ok);
            cp16(d + SP_L, g_pl + src, ok);
        }
        cpcommit();
    };
    auto issue_v = [&](int jt) {
        int j0 = jt * 64;
        #pragma unroll
        for (int q = 0; q < 2; q++) {
            int c = q * 256 + tid;
            int row = c >> 3, seg = c & 7;
            size_t src = (size_t)(b * SS + j0 + row) * DD + h * DH + seg * 8;
            uint32_t d = sb + row * 144 + seg * 16;
            cp16(d + SV_H, g_vh + src, true);
            cp16(d + SV_L, g_vl + src, true);
        }
        cpcommit();
    };

    // prologue: Q (all 4 arrays) + K0 + P0 as one group, then V0
    #pragma unroll
    for (int q = 0; q < 4; q++) {
        int c = q * 256 + tid;
        int row = c >> 3, seg = c & 7;
        size_t src = (size_t)(b * SS + i0 + row) * DD + h * DH + seg * 8;
        uint32_t d = sb + row * 144 + seg * 16;
        cp16(d + SQ_UH, g_quh + src, true);
        cp16(d + SQ_UL, g_qul + src, true);
        cp16(d + SQ_VH, g_qvh + src, true);
        cp16(d + SQ_VL, g_qvl + src, true);
    }
    issue_kp(0);
    issue_v(0);

    for (int jt = 0; jt < 16; jt++) {
        cpwait<1>();
        __syncthreads();

        // ---- phase 1: content = QU @ K^T ----
        float accC[2][4][4];
        #pragma unroll
        for (int a = 0; a < 2; a++)
            #pragma unroll
            for (int c = 0; c < 4; c++)
                #pragma unroll
                for (int e = 0; e < 4; e++) accC[a][c][e] = 0.f;
        #pragma unroll
        for (int kk = 0; kk < 64; kk += 16) {
            uint32_t uh[2][4], ul[2][4];
            #pragma unroll
            for (int mi = 0; mi < 2; mi++) {
                uint32_t ad = sb + SQ_UH + (wm + 16 * mi + (lane & 15)) * 144
                              + (kk + ((lane >> 4) << 3)) * 2;
                ldsm4(uh[mi], ad);
                ldsm4(ul[mi], ad + (SQ_UL - SQ_UH));
            }
            #pragma unroll
            for (int nh = 0; nh < 2; nh++) {
                int n0 = wcol * 32 + 16 * nh;
                uint32_t bd = sb + SK_H + (n0 + (lane & 15)) * 144
                              + (kk + ((lane >> 4) << 3)) * 2;
                uint32_t bh4[4], bl4[4];
                ldsm4(bh4, bd);
                ldsm4(bl4, bd + (SK_L - SK_H));
                #pragma unroll
                for (int half = 0; half < 2; half++) {
                    int nf = 2 * nh + half;
                    uint32_t bhh[2] = {bh4[half], bh4[half+2]};
                    uint32_t bll[2] = {bl4[half], bl4[half+2]};
                    #pragma unroll
                    for (int mi = 0; mi < 2; mi++)
                        mma3(accC[mi][nf], uh[mi], ul[mi], bhh, bll);
                }
            }
        }
        // dump content (scaled) — exclusive cells, no sync needed yet
        #pragma unroll
        for (int mi = 0; mi < 2; mi++)
            #pragma unroll
            for (int nf = 0; nf < 4; nf++)
                #pragma unroll
                for (int half = 0; half < 2; half++) {
                    int rl = wm + 16 * mi + g + 8 * half;
                    int jj = wcol * 32 + 8 * nf + 2 * t4;
                    S32[rl * 68 + jj]     = accC[mi][nf][2*half]   * SCALE;
                    S32[rl * 68 + jj + 1] = accC[mi][nf][2*half+1] * SCALE;
                }

        // ---- phase 2: pos = QV @ P^T (192-window) ----
        float accR[2][12][4];
        #pragma unroll
        for (int a = 0; a < 2; a++)
            #pragma unroll
            for (int c = 0; c < 12; c++)
                #pragma unroll
                for (int e = 0; e < 4; e++) accR[a][c][e] = 0.f;
        #pragma unroll
        for (int kk = 0; kk < 64; kk += 16) {
            uint32_t vh[2][4], vl[2][4];
            #pragma unroll
            for (int mi = 0; mi < 2; mi++) {
                uint32_t ad = sb + SQ_VH + (wm + 16 * mi + (lane & 15)) * 144
                              + (kk + ((lane >> 4) << 3)) * 2;
                ldsm4(vh[mi], ad);
                ldsm4(vl[mi], ad + (SQ_VL - SQ_VH));
            }
            #pragma unroll
            for (int nh = 0; nh < 6; nh++) {
                int n0 = wcol * 96 + 16 * nh;
                uint32_t bd = sb + SP_H + (n0 + (lane & 15)) * 144
                              + (kk + ((lane >> 4) << 3)) * 2;
                uint32_t bh4[4], bl4[4];
                ldsm4(bh4, bd);
                ldsm4(bl4, bd + (SP_L - SP_H));
                #pragma unroll
                for (int half = 0; half < 2; half++) {
                    int nf = 2 * nh + half;
                    uint32_t bhh[2] = {bh4[half], bh4[half+2]};
                    uint32_t bll[2] = {bl4[half], bl4[half+2]};
                    #pragma unroll
                    for (int mi = 0; mi < 2; mi++)
                        mma3(accR[mi][nf], vh[mi], vl[mi], bhh, bll);
                }
            }
        }
        __syncthreads();          // K,P consumed; content dumps visible
        issue_kp(jt < 15 ? jt + 1 : 15);

        // scatter pos: j = t + r - 127 (injective per row -> race-free RMW)
        #pragma unroll
        for (int mi = 0; mi < 2; mi++)
            #pragma unroll
            for (int nf = 0; nf < 12; nf++)
                #pragma unroll
                for (int half = 0; half < 2; half++) {
                    int rl = wm + 16 * mi + g + 8 * half;
                    int t = wcol * 96 + 8 * nf + 2 * t4;
                    int jl = t + rl - 127;
                    if (jl >= 0 && jl < 64)
                        S32[rl * 68 + jl] += accR[mi][nf][2*half] * SCALE;
                    int jl2 = jl + 1;
                    if (jl2 >= 0 && jl2 < 64)
                        S32[rl * 68 + jl2] += accR[mi][nf][2*half+1] * SCALE;
                }
        __syncthreads();

        // ---- online softmax (thread = half-row) ----
        int r = tid >> 1, hf = tid & 1;
        float p[32];
        {
            const float4* Sp = (const float4*)(S32 + r * 68 + hf * 32);
            float tm = -1e30f;
            #pragma unroll
            for (int q = 0; q < 8; q++) {
                float4 v = Sp[q];
                p[4*q] = v.x; p[4*q+1] = v.y; p[4*q+2] = v.z; p[4*q+3] = v.w;
                tm = fmaxf(tm, fmaxf(fmaxf(v.x, v.y), fmaxf(v.z, v.w)));
            }
            tm = fmaxf(tm, __shfl_xor_sync(0xffffffffu, tm, 1));
            float mo = jt ? m_s[r] : -1e30f;
            float lo = jt ? l_s[r] : 0.f;
            float mn = fmaxf(mo, tm);
            float alpha = __expf(mo - mn);
            float sum = 0.f;
            #pragma unroll
            for (int c = 0; c < 32; c++) { p[c] = __expf(p[c] - mn); sum += p[c]; }
            sum += __shfl_xor_sync(0xffffffffu, sum, 1);
            if (hf == 0) { m_s[r] = mn; l_s[r] = alpha * lo + sum; al_s[r] = alpha; }
        }
        __syncthreads();          // S32 reads done, stats visible

        // write probs (split bf16) into attn buffer (shares space with S32)
        {
            uint32_t* ahp = (uint32_t*)(smem + SATT)   + r * 36 + hf * 16;
            uint32_t* alp = (uint32_t*)(smem + SATT_L) + r * 36 + hf * 16;
            #pragma unroll
            for (int q = 0; q < 16; q++) {
                uint32_t hh, ll;
                split_pair(p[2*q], p[2*q+1], hh, ll);
                ahp[q] = hh; alp[q] = ll;
            }
        }
        cpwait<1>();              // V(jt) ready (KP(jt+1) may be in flight)
        __syncthreads();          // attn visible to all, V visible

        // rescale O by alpha, then accumulate P @ V
        #pragma unroll
        for (int mi = 0; mi < 2; mi++)
            #pragma unroll
            for (int half = 0; half < 2; half++) {
                int rl = wm + 16 * mi + g + 8 * half;
                float a = al_s[rl];
                #pragma unroll
                for (int nf = 0; nf < 4; nf++) {
                    accO[mi][nf][2*half]   *= a;
                    accO[mi][nf][2*half+1] *= a;
                }
            }
        #pragma unroll
        for (int kk = 0; kk < 64; kk += 16) {
            uint32_t ah[2][4], al[2][4];
            #pragma unroll
            for (int mi = 0; mi < 2; mi++) {
                uint32_t ad = sb + SATT + (wm + 16 * mi + (lane & 15)) * 144
                              + (kk + ((lane >> 4) << 3)) * 2;
                ldsm4(ah[mi], ad);
                ldsm4(al[mi], ad + (SATT_L - SATT));
            }
            #pragma unroll
            for (int nh = 0; nh < 2; nh++) {
                int n0 = wcol * 32 + 16 * nh;
                uint32_t bd = sb + SV_H + (kk + (lane & 7) + (lane & 8)) * 144
                              + (n0 + ((lane & 16) >> 1)) * 2;
                uint32_t bh4[4], bl4[4];
                ldsm4t(bh4, bd);
                ldsm4t(bl4, bd + (SV_L - SV_H));
                #pragma unroll
                for (int half = 0; half < 2; half++) {
                    int nf = 2 * nh + half;
                    uint32_t bhh[2] = {bh4[2*half], bh4[2*half+1]};
                    uint32_t bll[2] = {bl4[2*half], bl4[2*half+1]};
                    #pragma unroll
                    for (int mi = 0; mi < 2; mi++)
                        mma3(accO[mi][nf], ah[mi], al[mi], bhh, bll);
                }
            }
        }
        __syncthreads();          // attn + V consumed
        issue_v(jt < 15 ? jt + 1 : 15);
    }

    // epilogue: normalize by l, split, store context
    #pragma unroll
    for (int mi = 0; mi < 2; mi++)
        #pragma unroll
        for (int nf = 0; nf < 4; nf++)
            #pragma unroll
            for (int half = 0; half < 2; half++) {
                int rl = wm + 16 * mi + g + 8 * half;
                float inv = 1.f / l_s[rl];
                int dl = wcol * 32 + 8 * nf + 2 * t4;
                uint32_t hh, ll;
                split_pair(accO[mi][nf][2*half] * inv, accO[mi][nf][2*half+1] * inv, hh, ll);
                size_t o = (size_t)(b * SS + i0 + rl) * DD + h * DH + dl;
                *(uint32_t*)&g_ch[o] = hh;
                *(uint32_t*)&g_cl[o] = ll;
            }
}

// ---------------- launch ----------------
extern "C" void kernel_launch(void* const* d_in, const int* in_sizes, int n_in,
                              void* d_out, int out_size) {
    const float* query = (const float*)d_in[0];
    const float* key   = (const float*)d_in[1];
    const float* value = (const float*)d_in[2];
    const float* pos   = (const float*)d_in[3];
    const float* Wq    = (const float*)d_in[4];
    const float* Wk    = (const float*)d_in[5];
    const float* Wv    = (const float*)d_in[6];
    const float* Wp    = (const float*)d_in[7];
    const float* ub    = (const float*)d_in[8];
    const float* vb    = (const float*)d_in[9];
    const float* Wo    = (const float*)d_in[10];
    float* out = (float*)d_out;

    __nv_bfloat16 *xqh,*xql,*xkh,*xkl,*xvh,*xvl,*xph,*xpl,*wh,*wl;
    __nv_bfloat16 *quh,*qul,*qvh,*qvl,*kh,*kl,*vh,*vl,*ph,*pl,*ch,*cl;
    cudaGetSymbolAddress((void**)&xqh, g_xqh); cudaGetSymbolAddress((void**)&xql, g_xql);
    cudaGetSymbolAddress((void**)&xkh, g_xkh); cudaGetSymbolAddress((void**)&xkl, g_xkl);
    cudaGetSymbolAddress((void**)&xvh, g_xvh); cudaGetSymbolAddress((void**)&xvl, g_xvl);
    cudaGetSymbolAddress((void**)&xph, g_xph); cudaGetSymbolAddress((void**)&xpl, g_xpl);
    cudaGetSymbolAddress((void**)&wh, g_wh);   cudaGetSymbolAddress((void**)&wl, g_wl);
    cudaGetSymbolAddress((void**)&quh, g_quh); cudaGetSymbolAddress((void**)&qul, g_qul);
    cudaGetSymbolAddress((void**)&qvh, g_qvh); cudaGetSymbolAddress((void**)&qvl, g_qvl);
    cudaGetSymbolAddress((void**)&kh, g_kh);   cudaGetSymbolAddress((void**)&kl, g_kl);
    cudaGetSymbolAddress((void**)&vh, g_vh);   cudaGetSymbolAddress((void**)&vl, g_vl);
    cudaGetSymbolAddress((void**)&ph, g_ph);   cudaGetSymbolAddress((void**)&pl, g_pl);
    cudaGetSymbolAddress((void**)&ch, g_ch);   cudaGetSymbolAddress((void**)&cl, g_cl);

    static bool attr_done = false;
    if (!attr_done) {
        cudaFuncSetAttribute(gemm_v2<0>, cudaFuncAttributeMaxDynamicSharedMemorySize, 2*G_STG);
        cudaFuncSetAttribute(gemm_v2<1>, cudaFuncAttributeMaxDynamicSharedMemorySize, 2*G_STG);
        cudaFuncSetAttribute(gemm_v2<2>, cudaFuncAttributeMaxDynamicSharedMemorySize, 2*G_STG);
        cudaFuncSetAttribute(flash_v1,   cudaFuncAttributeMaxDynamicSharedMemorySize, FL_SMEM);
        attr_done = true;
    }

    dim3 blk(256);

    split_k<<<(MROWS*DD/4 + 255)/256, blk>>>((const float4*)query, (uint32_t*)xqh, (uint32_t*)xql, MROWS*DD/4);
    split_k<<<(MROWS*DD/4 + 255)/256, blk>>>((const float4*)key,   (uint32_t*)xkh, (uint32_t*)xkl, MROWS*DD/4);
    split_k<<<(MROWS*DD/4 + 255)/256, blk>>>((const float4*)value, (uint32_t*)xvh, (uint32_t*)xvl, MROWS*DD/4);
    split_k<<<(PROWS*DD/4 + 255)/256, blk>>>((const float4*)pos,   (uint32_t*)xph, (uint32_t*)xpl, PROWS*DD/4);
    split_k<<<(DD*DD/4 + 255)/256, blk>>>((const float4*)Wq, (uint32_t*)(wh + 0*DD*DD), (uint32_t*)(wl + 0*DD*DD), DD*DD/4);
    split_k<<<(DD*DD/4 + 255)/256, blk>>>((const float4*)Wk, (uint32_t*)(wh + 1*DD*DD), (uint32_t*)(wl + 1*DD*DD), DD*DD/4);
    split_k<<<(DD*DD/4 + 255)/256, blk>>>((const float4*)Wv, (uint32_t*)(wh + 2*DD*DD), (uint32_t*)(wl + 2*DD*DD), DD*DD/4);
    split_k<<<(DD*DD/4 + 255)/256, blk>>>((const float4*)Wp, (uint32_t*)(wh + 3*DD*DD), (uint32_t*)(wl + 3*DD*DD), DD*DD/4);
    split_k<<<(DD*DD/4 + 255)/256, blk>>>((const float4*)Wo, (uint32_t*)(wh + 4*DD*DD), (uint32_t*)(wl + 4*DD*DD), DD*DD/4);

    gemm_v2<2><<<dim3(4, 64), blk, 2*G_STG>>>(xqh, xql, wh + 0*DD*DD, wl + 0*DD*DD,
        nullptr, quh, qul, qvh, qvl, ub, vb, MROWS, DD, DD);
    gemm_v2<1><<<dim3(4, 64), blk, 2*G_STG>>>(xkh, xkl, wh + 1*DD*DD, wl + 1*DD*DD,
        nullptr, kh, kl, nullptr, nullptr, nullptr, nullptr, MROWS, DD, DD);
    gemm_v2<1><<<dim3(4, 64), blk, 2*G_STG>>>(xvh, xvl, wh + 2*DD*DD, wl + 2*DD*DD,
        nullptr, vh, vl, nullptr, nullptr, nullptr, nullptr, MROWS, DD, DD);
    gemm_v2<1><<<dim3(4, 128), blk, 2*G_STG>>>(xph, xpl, wh + 3*DD*DD, wl + 3*DD*DD,
        nullptr, ph, pl, nullptr, nullptr, nullptr, nullptr, PROWS, DD, DD);

    // fused score + softmax + attn@V
    flash_v1<<<dim3(SS/128, BB*HH), blk, FL_SMEM>>>();

    // output projection
    gemm_v2<0><<<dim3(4, 64), blk, 2*G_STG>>>(ch, cl, wh + 4*DD*DD, wl + 4*DD*DD,
        out, nullptr, nullptr, nullptr, nullptr, nullptr, nullptr, MROWS, DD, DD);
}

// round 7
// speedup vs baseline: 3.3448x; 1.0606x over previous
#include <cuda_runtime.h>
#include <cuda_bf16.h>
#include <cstdint>

#define BB 8
#define SS 1024
#define DD 512
#define HH 8
#define DH 64
#define L2P 2047
#define SCALE 0.125f
#define MROWS (BB*SS)      // 8192
#define PROWS (BB*L2P)     // 16376

// ---------------- scratch ----------------
__device__ __nv_bfloat16 g_xqh[MROWS*DD], g_xql[MROWS*DD];
__device__ __nv_bfloat16 g_xkh[MROWS*DD], g_xkl[MROWS*DD];
__device__ __nv_bfloat16 g_xvh[MROWS*DD], g_xvl[MROWS*DD];
__device__ __nv_bfloat16 g_xph[PROWS*DD], g_xpl[PROWS*DD];
__device__ __nv_bfloat16 g_wh[5*DD*DD], g_wl[5*DD*DD];
__device__ __nv_bfloat16 g_qh[MROWS*DD],  g_ql[MROWS*DD];
__device__ __nv_bfloat16 g_kh[MROWS*DD],  g_kl[MROWS*DD];
__device__ __nv_bfloat16 g_vh[MROWS*DD],  g_vl[MROWS*DD];
__device__ __nv_bfloat16 g_ph[(PROWS+8)*DD], g_pl[(PROWS+8)*DD];
__device__ __nv_bfloat16 g_ch[MROWS*DD], g_cl[MROWS*DD];
__device__ float g_uk[BB*HH*SS];            // u_h . k_{b,j}
__device__ float g_vp[BB*HH*L2P + 64];      // v_h . p_{b,t}

// ---------------- helpers ----------------
__device__ __forceinline__ void split_pair(float x0, float x1, uint32_t& h, uint32_t& l) {
    __nv_bfloat162 hh = __floats2bfloat162_rn(x0, x1);
    float r0 = x0 - __bfloat162float(hh.x);
    float r1 = x1 - __bfloat162float(hh.y);
    __nv_bfloat162 ll = __floats2bfloat162_rn(r0, r1);
    h = *reinterpret_cast<uint32_t*>(&hh);
    l = *reinterpret_cast<uint32_t*>(&ll);
}
__device__ __forceinline__ float2 unsplit(uint32_t h, uint32_t l) {
    __nv_bfloat162 hh = *reinterpret_cast<__nv_bfloat162*>(&h);
    __nv_bfloat162 ll = *reinterpret_cast<__nv_bfloat162*>(&l);
    return make_float2(__bfloat162float(hh.x) + __bfloat162float(ll.x),
                       __bfloat162float(hh.y) + __bfloat162float(ll.y));
}
__device__ __forceinline__ void mma16816(float d[4], const uint32_t a[4], const uint32_t b[2]) {
    asm volatile(
        "mma.sync.aligned.m16n8k16.row.col.f32.bf16.bf16.f32 "
        "{%0,%1,%2,%3}, {%4,%5,%6,%7}, {%8,%9}, {%0,%1,%2,%3};\n"
        : "+f"(d[0]), "+f"(d[1]), "+f"(d[2]), "+f"(d[3])
        : "r"(a[0]), "r"(a[1]), "r"(a[2]), "r"(a[3]), "r"(b[0]), "r"(b[1]));
}
__device__ __forceinline__ void mma3(float d[4], const uint32_t ah[4], const uint32_t al[4],
                                     const uint32_t bh[2], const uint32_t bl[2]) {
    mma16816(d, ah, bh);
    mma16816(d, ah, bl);
    mma16816(d, al, bh);
}
__device__ __forceinline__ void ldsm4(uint32_t r[4], uint32_t addr) {
    asm volatile("ldmatrix.sync.aligned.m8n8.x4.shared.b16 {%0,%1,%2,%3},[%4];"
        : "=r"(r[0]), "=r"(r[1]), "=r"(r[2]), "=r"(r[3]) : "r"(addr));
}
__device__ __forceinline__ void ldsm4t(uint32_t r[4], uint32_t addr) {
    asm volatile("ldmatrix.sync.aligned.m8n8.x4.trans.shared.b16 {%0,%1,%2,%3},[%4];"
        : "=r"(r[0]), "=r"(r[1]), "=r"(r[2]), "=r"(r[3]) : "r"(addr));
}
__device__ __forceinline__ void cp16(uint32_t dst, const void* src, bool pred) {
    int sz = pred ? 16 : 0;
    asm volatile("cp.async.cg.shared.global [%0],[%1],16,%2;\n"
        :: "r"(dst), "l"(src), "r"(sz));
}
// 4-byte variant: only 4-byte alignment required (used for the odd-stride vp vector)
__device__ __forceinline__ void cp4(uint32_t dst, const void* src) {
    asm volatile("cp.async.ca.shared.global [%0],[%1],4;\n" :: "r"(dst), "l"(src));
}
__device__ __forceinline__ void cpcommit() { asm volatile("cp.async.commit_group;\n"); }
template<int N> __device__ __forceinline__ void cpwait() {
    asm volatile("cp.async.wait_group %0;\n" :: "n"(N));
}

// ---------------- split prepass ----------------
__global__ __launch_bounds__(256) void split_k(const float4* __restrict__ src,
                                               uint32_t* __restrict__ hi,
                                               uint32_t* __restrict__ lo, int n4) {
    int i = blockIdx.x * 256 + threadIdx.x;
    if (i < n4) {
        float4 v = src[i];
        uint32_t h0, l0, h1, l1;
        split_pair(v.x, v.y, h0, l0);
        split_pair(v.z, v.w, h1, l1);
        hi[2*i] = h0; hi[2*i+1] = h1;
        lo[2*i] = l0; lo[2*i+1] = l1;
    }
}

// ---------------- bias GEMV: out[b,h,row] = bias_h . x_{b,row,h,:} ----------------
__global__ __launch_bounds__(256) void biasdot(const float* __restrict__ bias,
                                               const __nv_bfloat16* __restrict__ xh,
                                               const __nv_bfloat16* __restrict__ xl,
                                               float* __restrict__ outg, int ROWS) {
    int gw = blockIdx.x * 8 + (threadIdx.x >> 5);
    int lane = threadIdx.x & 31;
    int ngroups = (ROWS + 7) >> 3;
    int jg = gw % ngroups;
    int rem = gw / ngroups;
    int h = rem & 7, b = rem >> 3;
    if (b >= BB) return;
    int jsub = lane >> 2, dq = lane & 3;
    int j = jg * 8 + jsub;
    float acc = 0.f;
    if (j < ROWS) {
        size_t base = ((size_t)(b * ROWS + j)) * DD + h * DH + dq * 16;
        uint4 h0 = *(const uint4*)&xh[base];
        uint4 h1 = *(const uint4*)&xh[base + 8];
        uint4 l0 = *(const uint4*)&xl[base];
        uint4 l1 = *(const uint4*)&xl[base + 8];
        uint32_t hs[8] = {h0.x,h0.y,h0.z,h0.w,h1.x,h1.y,h1.z,h1.w};
        uint32_t ls[8] = {l0.x,l0.y,l0.z,l0.w,l1.x,l1.y,l1.z,l1.w};
        const float* u = bias + h * DH + dq * 16;
        #pragma unroll
        for (int e = 0; e < 8; e++) {
            float2 f = unsplit(hs[e], ls[e]);
            acc += f.x * u[2*e] + f.y * u[2*e+1];
        }
    }
    acc += __shfl_xor_sync(0xffffffffu, acc, 1);
    acc += __shfl_xor_sync(0xffffffffu, acc, 2);
    if (dq == 0 && j < ROWS)
        outg[((size_t)(b * HH + h)) * ROWS + j] = acc;
}

// ---------------- GEMM (as R5) ----------------
#define G_AL  10240
#define G_BH  20480
#define G_BL  29184
#define G_STG 37888
template<int EPI>
__global__ __launch_bounds__(256, 2) void gemm_v2(
    const __nv_bfloat16* __restrict__ Ah, const __nv_bfloat16* __restrict__ Al,
    const __nv_bfloat16* __restrict__ Bh, const __nv_bfloat16* __restrict__ Bl,
    float* __restrict__ Cf,
    __nv_bfloat16* __restrict__ C1h, __nv_bfloat16* __restrict__ C1l,
    int M, int N, int K) {
    extern __shared__ char smem[];
    uint32_t sb = (uint32_t)__cvta_generic_to_shared(smem);
    int tid = threadIdx.x, lane = tid & 31, wi = tid >> 5;
    int g = lane >> 2, t4 = lane & 3;
    int row0 = blockIdx.y * 128, col0 = blockIdx.x * 128;
    int wm = (wi & 3) * 32, wn = (wi >> 2) * 64;

    float acc[2][8][4];
    #pragma unroll
    for (int a = 0; a < 2; a++)
        #pragma unroll
        for (int b = 0; b < 8; b++)
            #pragma unroll
            for (int c = 0; c < 4; c++) acc[a][b][c] = 0.f;

    const int NIT = K >> 5;
    auto issue = [&](int it) {
        int k0 = it * 32;
        uint32_t st = sb + (it & 1) * G_STG;
        #pragma unroll
        for (int q = 0; q < 2; q++) {
            int c = q * 256 + tid;
            int m = c >> 2, seg = c & 3;
            bool ok = (row0 + m) < M;
            int mr = ok ? (row0 + m) : 0;
            cp16(st + m * 80 + seg * 16, Ah + (size_t)mr * K + k0 + seg * 8, ok);
            cp16(st + G_AL + m * 80 + seg * 16, Al + (size_t)mr * K + k0 + seg * 8, ok);
        }
        #pragma unroll
        for (int q = 0; q < 2; q++) {
            int c = q * 256 + tid;
            int k = c >> 4, seg = c & 15;
            cp16(st + G_BH + k * 272 + seg * 16, Bh + (size_t)(k0 + k) * N + col0 + seg * 8, true);
            cp16(st + G_BL + k * 272 + seg * 16, Bl + (size_t)(k0 + k) * N + col0 + seg * 8, true);
        }
        cpcommit();
    };

    issue(0);
    for (int it = 0; it < NIT; it++) {
        if (it + 1 < NIT) { issue(it + 1); cpwait<1>(); }
        else cpwait<0>();
        __syncthreads();
        uint32_t st = sb + (it & 1) * G_STG;
        #pragma unroll
        for (int kk = 0; kk < 32; kk += 16) {
            uint32_t ah[2][4], al[2][4];
            #pragma unroll
            for (int mi = 0; mi < 2; mi++) {
                uint32_t ad = st + (wm + 16 * mi + (lane & 15)) * 80 + (kk + ((lane >> 4) << 3)) * 2;
                ldsm4(ah[mi], ad);
                ldsm4(al[mi], ad + G_AL);
            }
            #pragma unroll
            for (int nh = 0; nh < 4; nh++) {
                int n0 = wn + 16 * nh;
                uint32_t bd = st + G_BH + (kk + (lane & 7) + (lane & 8)) * 272
                              + (n0 + ((lane & 16) >> 1)) * 2;
                uint32_t bh4[4], bl4[4];
                ldsm4t(bh4, bd);
                ldsm4t(bl4, bd + (G_BL - G_BH));
                #pragma unroll
                for (int half = 0; half < 2; half++) {
                    int nf = 2 * nh + half;
                    uint32_t bhh[2] = {bh4[2*half], bh4[2*half+1]};
                    uint32_t bll[2] = {bl4[2*half], bl4[2*half+1]};
                    #pragma unroll
                    for (int mi = 0; mi < 2; mi++)
                        mma3(acc[mi][nf], ah[mi], al[mi], bhh, bll);
                }
            }
        }
        __syncthreads();
    }

    #pragma unroll
    for (int mi = 0; mi < 2; mi++)
        #pragma unroll
        for (int nf = 0; nf < 8; nf++)
            #pragma unroll
            for (int half = 0; half < 2; half++) {
                int r = row0 + wm + 16 * mi + g + 8 * half;
                int c = col0 + wn + 8 * nf + 2 * t4;
                float v0 = acc[mi][nf][2*half], v1 = acc[mi][nf][2*half+1];
                if (r < M) {
                    if (EPI == 0) {
                        *(float2*)&Cf[(size_t)r * N + c] = make_float2(v0, v1);
                    } else {
                        uint32_t h, l;
                        split_pair(v0, v1, h, l);
                        *(uint32_t*)&C1h[(size_t)r * N + c] = h;
                        *(uint32_t*)&C1l[(size_t)r * N + c] = l;
                    }
                }
            }
}

// ---------------- fused flash attention v2 ----------------
// CTA: 64 i-rows for one (b,h); streams 8 j-tiles of 128. P-window 191 (pad 192).
#define SQ_H  0
#define SQ_L  9216
#define SK_H  18432
#define SK_L  36864
#define SP_H  55296
#define SP_L  82944
#define SV_H  110592
#define SV_L  129024
#define SATT  147456
#define SATT_L (SATT + 17408)
#define SSTAT (SATT + 34816)
#define UKOFF (SSTAT + 768)
#define VPOFF (UKOFF + 1024)
#define FL_SMEM (VPOFF + 1536)

__global__ __launch_bounds__(256, 1) void flash_v2() {
    extern __shared__ char smem[];
    uint32_t sb = (uint32_t)__cvta_generic_to_shared(smem);
    float* S32  = (float*)(smem + SATT);
    float* m_s  = (float*)(smem + SSTAT);
    float* l_s  = m_s + 64;
    float* al_s = m_s + 128;
    float* uk_s = (float*)(smem + UKOFF);
    float* vp_s = (float*)(smem + VPOFF);

    int tid = threadIdx.x, lane = tid & 31, wi = tid >> 5;
    int g = lane >> 2, t4 = lane & 3;
    int bh = blockIdx.y, b = bh >> 3, h = bh & 7;
    int i0 = blockIdx.x * 64;
    int wm = (wi & 3) * 16, wcol = wi >> 2;

    float accO[4][4];
    #pragma unroll
    for (int c = 0; c < 4; c++)
        #pragma unroll
        for (int e = 0; e < 4; e++) accO[c][e] = 0.f;

    auto issue_kp = [&](int jt) {
        int j0 = jt * 128;
        int pbase = 960 + j0 - i0;
        #pragma unroll
        for (int q = 0; q < 4; q++) {
            int c = q * 256 + tid;
            int row = c >> 3, seg = c & 7;
            size_t src = (size_t)(b * SS + j0 + row) * DD + h * DH + seg * 8;
            uint32_t d = sb + row * 144 + seg * 16;
            cp16(d + SK_H, g_kh + src, true);
            cp16(d + SK_L, g_kl + src, true);
        }
        #pragma unroll
        for (int q = 0; q < 6; q++) {
            int c = q * 256 + tid;
            int row = c >> 3, seg = c & 7;
            bool ok = row < 191;
            int rc = ok ? row : 0;
            size_t src = (size_t)(b * L2P + pbase + rc) * DD + h * DH + seg * 8;
            uint32_t d = sb + row * 144 + seg * 16;
            cp16(d + SP_H, g_ph + src, ok);
            cp16(d + SP_L, g_pl + src, ok);
        }
        if (tid < 32)
            cp16(sb + UKOFF + (jt & 1) * 512 + tid * 16,
                 g_uk + ((size_t)(b * HH + h)) * SS + j0 + tid * 4, true);
        // vp has odd stride (L2P=2047) -> only 4B-aligned; use 4-byte cp.async
        if (tid < 192)
            cp4(sb + VPOFF + (jt & 1) * 768 + tid * 4,
                g_vp + ((size_t)(b * HH + h)) * L2P + pbase + tid);
        cpcommit();
    };
    auto issue_v = [&](int jt) {
        int j0 = jt * 128;
        #pragma unroll
        for (int q = 0; q < 4; q++) {
            int c = q * 256 + tid;
            int row = c >> 3, seg = c & 7;
            size_t src = (size_t)(b * SS + j0 + row) * DD + h * DH + seg * 8;
            uint32_t d = sb + row * 144 + seg * 16;
            cp16(d + SV_H, g_vh + src, true);
            cp16(d + SV_L, g_vl + src, true);
        }
        cpcommit();
    };

    // prologue: Q + KP(0) [group], V(0) [group]
    #pragma unroll
    for (int q = 0; q < 2; q++) {
        int c = q * 256 + tid;
        int row = c >> 3, seg = c & 7;
        size_t src = (size_t)(b * SS + i0 + row) * DD + h * DH + seg * 8;
        uint32_t d = sb + row * 144 + seg * 16;
        cp16(d + SQ_H, g_qh + src, true);
        cp16(d + SQ_L, g_ql + src, true);
    }
    issue_kp(0);
    issue_v(0);

    for (int jt = 0; jt < 8; jt++) {
        cpwait<1>();
        __syncthreads();
        int ub2 = (jt & 1) * 128;
        int vb2 = (jt & 1) * 192;

        // ---- content = Q @ K^T  (64 x 128) ----
        float accC[8][4];
        #pragma unroll
        for (int c = 0; c < 8; c++)
            #pragma unroll
            for (int e = 0; e < 4; e++) accC[c][e] = 0.f;
        #pragma unroll
        for (int kk = 0; kk < 64; kk += 16) {
            uint32_t ah[4], al[4];
            uint32_t ad = sb + SQ_H + (wm + (lane & 15)) * 144 + (kk + ((lane >> 4) << 3)) * 2;
            ldsm4(ah, ad);
            ldsm4(al, ad + (SQ_L - SQ_H));
            #pragma unroll
            for (int nh = 0; nh < 4; nh++) {
                int n0 = wcol * 64 + 16 * nh;
                uint32_t bd = sb + SK_H + (n0 + (lane & 15)) * 144 + (kk + ((lane >> 4) << 3)) * 2;
                uint32_t bh4[4], bl4[4];
                ldsm4(bh4, bd);
                ldsm4(bl4, bd + (SK_L - SK_H));
                #pragma unroll
                for (int half = 0; half < 2; half++) {
                    int nf = 2 * nh + half;
                    uint32_t bhh[2] = {bh4[half], bh4[half+2]};
                    uint32_t bll[2] = {bl4[half], bl4[half+2]};
                    mma3(accC[nf], ah, al, bhh, bll);
                }
            }
        }
        // dump content + uk (exclusive cells)
        #pragma unroll
        for (int nf = 0; nf < 8; nf++) {
            int jj = wcol * 64 + 8 * nf + 2 * t4;
            int rl = wm + g;
            S32[rl * 132 + jj]     = (accC[nf][0] + uk_s[ub2 + jj])     * SCALE;
            S32[rl * 132 + jj + 1] = (accC[nf][1] + uk_s[ub2 + jj + 1]) * SCALE;
            S32[(rl + 8) * 132 + jj]     = (accC[nf][2] + uk_s[ub2 + jj])     * SCALE;
            S32[(rl + 8) * 132 + jj + 1] = (accC[nf][3] + uk_s[ub2 + jj + 1]) * SCALE;
        }

        // ---- pos = Q @ P^T  (64 x 192 window) ----
        float accR[12][4];
        #pragma unroll
        for (int c = 0; c < 12; c++)
            #pragma unroll
            for (int e = 0; e < 4; e++) accR[c][e] = 0.f;
        #pragma unroll
        for (int kk = 0; kk < 64; kk += 16) {
            uint32_t ah[4], al[4];
            uint32_t ad = sb + SQ_H + (wm + (lane & 15)) * 144 + (kk + ((lane >> 4) << 3)) * 2;
            ldsm4(ah, ad);
            ldsm4(al, ad + (SQ_L - SQ_H));
            #pragma unroll
            for (int nh = 0; nh < 6; nh++) {
                int n0 = wcol * 96 + 16 * nh;
                uint32_t bd = sb + SP_H + (n0 + (lane & 15)) * 144 + (kk + ((lane >> 4) << 3)) * 2;
                uint32_t bh4[4], bl4[4];
                ldsm4(bh4, bd);
                ldsm4(bl4, bd + (SP_L - SP_H));
                #pragma unroll
                for (int half = 0; half < 2; half++) {
                    int nf = 2 * nh + half;
                    uint32_t bhh[2] = {bh4[half], bh4[half+2]};
                    uint32_t bll[2] = {bl4[half], bl4[half+2]};
                    mma3(accR[nf], ah, al, bhh, bll);
                }
            }
        }
        __syncthreads();          // K,P consumed; content dumps visible
        if (jt < 7) issue_kp(jt + 1); else cpcommit();

        // scatter pos: jl = t + rl - 63 (injective per row)
        #pragma unroll
        for (int nf = 0; nf < 12; nf++) {
            int t = wcol * 96 + 8 * nf + 2 * t4;
            #pragma unroll
            for (int half = 0; half < 2; half++) {
                int rl = wm + g + 8 * half;
                int jl = t + rl - 63;
                if (jl >= 0 && jl < 128)
                    S32[rl * 132 + jl] += (accR[nf][2*half] + vp_s[vb2 + t]) * SCALE;
                int jl2 = jl + 1;
                if (jl2 >= 0 && jl2 < 128)
                    S32[rl * 132 + jl2] += (accR[nf][2*half+1] + vp_s[vb2 + t + 1]) * SCALE;
            }
        }
        __syncthreads();

        // ---- online softmax (4 threads per row) ----
        int r = tid >> 2, q4 = tid & 3;
        float p[32];
        {
            const float4* Sp = (const float4*)(S32 + r * 132 + q4 * 32);
            float tm = -1e30f;
            #pragma unroll
            for (int q = 0; q < 8; q++) {
                float4 v = Sp[q];
                p[4*q] = v.x; p[4*q+1] = v.y; p[4*q+2] = v.z; p[4*q+3] = v.w;
                tm = fmaxf(tm, fmaxf(fmaxf(v.x, v.y), fmaxf(v.z, v.w)));
            }
            tm = fmaxf(tm, __shfl_xor_sync(0xffffffffu, tm, 1));
            tm = fmaxf(tm, __shfl_xor_sync(0xffffffffu, tm, 2));
            float mo = jt ? m_s[r] : -1e30f;
            float lo = jt ? l_s[r] : 0.f;
            float mn = fmaxf(mo, tm);
            float alpha = __expf(mo - mn);
            float sum = 0.f;
            #pragma unroll
            for (int c = 0; c < 32; c++) { p[c] = __expf(p[c] - mn); sum += p[c]; }
            sum += __shfl_xor_sync(0xffffffffu, sum, 1);
            sum += __shfl_xor_sync(0xffffffffu, sum, 2);
            if (q4 == 0) { m_s[r] = mn; l_s[r] = alpha * lo + sum; al_s[r] = alpha; }
        }
        __syncthreads();          // S32 reads done; stats visible

        // write probs (split bf16) into attn buffer (aliases S32)
        {
            uint32_t* ahp = (uint32_t*)(smem + SATT)   + r * 68 + q4 * 16;
            uint32_t* alp = (uint32_t*)(smem + SATT_L) + r * 68 + q4 * 16;
            #pragma unroll
            for (int q = 0; q < 16; q++) {
                uint32_t hh, ll;
                split_pair(p[2*q], p[2*q+1], hh, ll);
                ahp[q] = hh; alp[q] = ll;
            }
        }
        cpwait<1>();              // V(jt) ready
        __syncthreads();

        // rescale O, then accumulate P @ V (k = 128)
        {
            float a1 = al_s[wm + g];
            float a2 = al_s[wm + g + 8];
            #pragma unroll
            for (int nf = 0; nf < 4; nf++) {
                accO[nf][0] *= a1; accO[nf][1] *= a1;
                accO[nf][2] *= a2; accO[nf][3] *= a2;
            }
        }
        #pragma unroll
        for (int kk = 0; kk < 128; kk += 16) {
            uint32_t ah[4], al[4];
            uint32_t ad = sb + SATT + (wm + (lane & 15)) * 272 + (kk + ((lane >> 4) << 3)) * 2;
            ldsm4(ah, ad);
            ldsm4(al, ad + (SATT_L - SATT));
            #pragma unroll
            for (int nh = 0; nh < 2; nh++) {
                int n0 = wcol * 32 + 16 * nh;
                uint32_t bd = sb + SV_H + (kk + (lane & 7) + (lane & 8)) * 144
                              + (n0 + ((lane & 16) >> 1)) * 2;
                uint32_t bh4[4], bl4[4];
                ldsm4t(bh4, bd);
                ldsm4t(bl4, bd + (SV_L - SV_H));
                #pragma unroll
                for (int half = 0; half < 2; half++) {
                    int nf = 2 * nh + half;
                    uint32_t bhh[2] = {bh4[2*half], bh4[2*half+1]};
                    uint32_t bll[2] = {bl4[2*half], bl4[2*half+1]};
                    mma3(accO[nf], ah, al, bhh, bll);
                }
            }
        }
        __syncthreads();          // attn + V consumed
        if (jt < 7) issue_v(jt + 1); else cpcommit();
    }

    // epilogue: normalize, split, store context
    #pragma unroll
    for (int nf = 0; nf < 4; nf++)
        #pragma unroll
        for (int half = 0; half < 2; half++) {
            int rl = wm + g + 8 * half;
            float inv = 1.f / l_s[rl];
            int dl = wcol * 32 + 8 * nf + 2 * t4;
            uint32_t hh, ll;
            split_pair(accO[nf][2*half] * inv, accO[nf][2*half+1] * inv, hh, ll);
            size_t o = (size_t)(b * SS + i0 + rl) * DD + h * DH + dl;
            *(uint32_t*)&g_ch[o] = hh;
            *(uint32_t*)&g_cl[o] = ll;
        }
}

// ---------------- launch ----------------
extern "C" void kernel_launch(void* const* d_in, const int* in_sizes, int n_in,
                              void* d_out, int out_size) {
    const float* query = (const float*)d_in[0];
    const float* key   = (const float*)d_in[1];
    const float* value = (const float*)d_in[2];
    const float* pos   = (const float*)d_in[3];
    const float* Wq    = (const float*)d_in[4];
    const float* Wk    = (const float*)d_in[5];
    const float* Wv    = (const float*)d_in[6];
    const float* Wp    = (const float*)d_in[7];
    const float* ub    = (const float*)d_in[8];
    const float* vb    = (const float*)d_in[9];
    const float* Wo    = (const float*)d_in[10];
    float* out = (float*)d_out;

    __nv_bfloat16 *xqh,*xql,*xkh,*xkl,*xvh,*xvl,*xph,*xpl,*wh,*wl;
    __nv_bfloat16 *qh,*ql,*kh,*kl,*vh,*vl,*ph,*pl,*ch,*cl;
    float *ukp, *vpp;
    cudaGetSymbolAddress((void**)&xqh, g_xqh); cudaGetSymbolAddress((void**)&xql, g_xql);
    cudaGetSymbolAddress((void**)&xkh, g_xkh); cudaGetSymbolAddress((void**)&xkl, g_xkl);
    cudaGetSymbolAddress((void**)&xvh, g_xvh); cudaGetSymbolAddress((void**)&xvl, g_xvl);
    cudaGetSymbolAddress((void**)&xph, g_xph); cudaGetSymbolAddress((void**)&xpl, g_xpl);
    cudaGetSymbolAddress((void**)&wh, g_wh);   cudaGetSymbolAddress((void**)&wl, g_wl);
    cudaGetSymbolAddress((void**)&qh, g_qh);   cudaGetSymbolAddress((void**)&ql, g_ql);
    cudaGetSymbolAddress((void**)&kh, g_kh);   cudaGetSymbolAddress((void**)&kl, g_kl);
    cudaGetSymbolAddress((void**)&vh, g_vh);   cudaGetSymbolAddress((void**)&vl, g_vl);
    cudaGetSymbolAddress((void**)&ph, g_ph);   cudaGetSymbolAddress((void**)&pl, g_pl);
    cudaGetSymbolAddress((void**)&ch, g_ch);   cudaGetSymbolAddress((void**)&cl, g_cl);
    cudaGetSymbolAddress((void**)&ukp, g_uk);  cudaGetSymbolAddress((void**)&vpp, g_vp);

    static bool attr_done = false;
    if (!attr_done) {
        cudaFuncSetAttribute(gemm_v2<0>, cudaFuncAttributeMaxDynamicSharedMemorySize, 2*G_STG);
        cudaFuncSetAttribute(gemm_v2<1>, cudaFuncAttributeMaxDynamicSharedMemorySize, 2*G_STG);
        cudaFuncSetAttribute(flash_v2,   cudaFuncAttributeMaxDynamicSharedMemorySize, FL_SMEM);
        attr_done = true;
    }

    dim3 blk(256);

    split_k<<<(MROWS*DD/4 + 255)/256, blk>>>((const float4*)query, (uint32_t*)xqh, (uint32_t*)xql, MROWS*DD/4);
    split_k<<<(MROWS*DD/4 + 255)/256, blk>>>((const float4*)key,   (uint32_t*)xkh, (uint32_t*)xkl, MROWS*DD/4);
    split_k<<<(MROWS*DD/4 + 255)/256, blk>>>((const float4*)value, (uint32_t*)xvh, (uint32_t*)xvl, MROWS*DD/4);
    split_k<<<(PROWS*DD/4 + 255)/256, blk>>>((const float4*)pos,   (uint32_t*)xph, (uint32_t*)xpl, PROWS*DD/4);
    split_k<<<(DD*DD/4 + 255)/256, blk>>>((const float4*)Wq, (uint32_t*)(wh + 0*DD*DD), (uint32_t*)(wl + 0*DD*DD), DD*DD/4);
    split_k<<<(DD*DD/4 + 255)/256, blk>>>((const float4*)Wk, (uint32_t*)(wh + 1*DD*DD), (uint32_t*)(wl + 1*DD*DD), DD*DD/4);
    split_k<<<(DD*DD/4 + 255)/256, blk>>>((const float4*)Wv, (uint32_t*)(wh + 2*DD*DD), (uint32_t*)(wl + 2*DD*DD), DD*DD/4);
    split_k<<<(DD*DD/4 + 255)/256, blk>>>((const float4*)Wp, (uint32_t*)(wh + 3*DD*DD), (uint32_t*)(wl + 3*DD*DD), DD*DD/4);
    split_k<<<(DD*DD/4 + 255)/256, blk>>>((const float4*)Wo, (uint32_t*)(wh + 4*DD*DD), (uint32_t*)(wl + 4*DD*DD), DD*DD/4);

    // projections (q is plain now; biases handled via rank-1 terms)
    gemm_v2<1><<<dim3(4, 64), blk, 2*G_STG>>>(xqh, xql, wh + 0*DD*DD, wl + 0*DD*DD,
        nullptr, qh, ql, MROWS, DD, DD);
    gemm_v2<1><<<dim3(4, 64), blk, 2*G_STG>>>(xkh, xkl, wh + 1*DD*DD, wl + 1*DD*DD,
        nullptr, kh, kl, MROWS, DD, DD);
    gemm_v2<1><<<dim3(4, 64), blk, 2*G_STG>>>(xvh, xvl, wh + 2*DD*DD, wl + 2*DD*DD,
        nullptr, vh, vl, MROWS, DD, DD);
    gemm_v2<1><<<dim3(4, 128), blk, 2*G_STG>>>(xph, xpl, wh + 3*DD*DD, wl + 3*DD*DD,
        nullptr, ph, pl, PROWS, DD, DD);

    // rank-1 bias terms: uk[b,h,j] = u_h.k ; vp[b,h,t] = v_h.p
    biasdot<<<dim3(8*8*(SS/8)/8), blk>>>(ub, kh, kl, ukp, SS);
    biasdot<<<dim3((8*8*((L2P+7)/8) + 7)/8), blk>>>(vb, ph, pl, vpp, L2P);

    // fused score + softmax + attn@V
    flash_v2<<<dim3(SS/64, BB*HH), blk, FL_SMEM>>>();

    // output projection
    gemm_v2<0><<<dim3(4, 64), blk, 2*G_STG>>>(ch, cl, wh + 4*DD*DD, wl + 4*DD*DD,
        out, nullptr, nullptr, MROWS, DD, DD);
}

// round 9
// speedup vs baseline: 3.5848x; 1.0717x over previous
#include <cuda_runtime.h>
#include <cuda_bf16.h>
#include <cstdint>

#define BB 8
#define SS 1024
#define DD 512
#define HH 8
#define DH 64
#define L2P 2047
#define SCALE 0.125f
#define MROWS (BB*SS)      // 8192
#define PROWS (BB*L2P)     // 16376

// ---------------- scratch ----------------
__device__ __nv_bfloat16 g_xqh[MROWS*DD], g_xql[MROWS*DD];
__device__ __nv_bfloat16 g_xkh[MROWS*DD], g_xkl[MROWS*DD];
__device__ __nv_bfloat16 g_xvh[MROWS*DD], g_xvl[MROWS*DD];
__device__ __nv_bfloat16 g_xph[PROWS*DD], g_xpl[PROWS*DD];
__device__ __nv_bfloat16 g_wh[5*DD*DD], g_wl[5*DD*DD];   // W [K,N] split
__device__ __nv_bfloat16 g_qh[MROWS*DD],  g_ql[MROWS*DD];
__device__ __nv_bfloat16 g_kh[MROWS*DD],  g_kl[MROWS*DD];
__device__ __nv_bfloat16 g_vh[MROWS*DD],  g_vl[MROWS*DD];
__device__ __nv_bfloat16 g_ph[(PROWS+8)*DD], g_pl[(PROWS+8)*DD];
__device__ __nv_bfloat16 g_ch[MROWS*DD], g_cl[MROWS*DD];
__device__ float g_uk[BB*HH*SS];
__device__ float g_vp[BB*HH*L2P + 64];

// ---------------- helpers ----------------
__device__ __forceinline__ void split_pair(float x0, float x1, uint32_t& h, uint32_t& l) {
    __nv_bfloat162 hh = __floats2bfloat162_rn(x0, x1);
    float r0 = x0 - __bfloat162float(hh.x);
    float r1 = x1 - __bfloat162float(hh.y);
    __nv_bfloat162 ll = __floats2bfloat162_rn(r0, r1);
    h = *reinterpret_cast<uint32_t*>(&hh);
    l = *reinterpret_cast<uint32_t*>(&ll);
}
__device__ __forceinline__ float2 unsplit(uint32_t h, uint32_t l) {
    __nv_bfloat162 hh = *reinterpret_cast<__nv_bfloat162*>(&h);
    __nv_bfloat162 ll = *reinterpret_cast<__nv_bfloat162*>(&l);
    return make_float2(__bfloat162float(hh.x) + __bfloat162float(ll.x),
                       __bfloat162float(hh.y) + __bfloat162float(ll.y));
}
__device__ __forceinline__ void mma16816(float d[4], const uint32_t a[4], const uint32_t b[2]) {
    asm volatile(
        "mma.sync.aligned.m16n8k16.row.col.f32.bf16.bf16.f32 "
        "{%0,%1,%2,%3}, {%4,%5,%6,%7}, {%8,%9}, {%0,%1,%2,%3};\n"
        : "+f"(d[0]), "+f"(d[1]), "+f"(d[2]), "+f"(d[3])
        : "r"(a[0]), "r"(a[1]), "r"(a[2]), "r"(a[3]), "r"(b[0]), "r"(b[1]));
}
__device__ __forceinline__ void mma3(float d[4], const uint32_t ah[4], const uint32_t al[4],
                                     const uint32_t bh[2], const uint32_t bl[2]) {
    mma16816(d, ah, bh);
    mma16816(d, ah, bl);
    mma16816(d, al, bh);
}
__device__ __forceinline__ void ldsm4(uint32_t r[4], uint32_t addr) {
    asm volatile("ldmatrix.sync.aligned.m8n8.x4.shared.b16 {%0,%1,%2,%3},[%4];"
        : "=r"(r[0]), "=r"(r[1]), "=r"(r[2]), "=r"(r[3]) : "r"(addr));
}
__device__ __forceinline__ void ldsm4t(uint32_t r[4], uint32_t addr) {
    asm volatile("ldmatrix.sync.aligned.m8n8.x4.trans.shared.b16 {%0,%1,%2,%3},[%4];"
        : "=r"(r[0]), "=r"(r[1]), "=r"(r[2]), "=r"(r[3]) : "r"(addr));
}
__device__ __forceinline__ void cp16(uint32_t dst, const void* src, bool pred) {
    int sz = pred ? 16 : 0;
    asm volatile("cp.async.cg.shared.global [%0],[%1],16,%2;\n"
        :: "r"(dst), "l"(src), "r"(sz));
}
__device__ __forceinline__ void cp4(uint32_t dst, const void* src) {
    asm volatile("cp.async.ca.shared.global [%0],[%1],4;\n" :: "r"(dst), "l"(src));
}
__device__ __forceinline__ void cpcommit() { asm volatile("cp.async.commit_group;\n"); }
template<int N> __device__ __forceinline__ void cpwait() {
    asm volatile("cp.async.wait_group %0;\n" :: "n"(N));
}

// ---------------- merged input split prepass (q,k,v,pos in one launch) ----------------
#define C_Q  (MROWS*DD/4)            // 1048576
#define C_K  (2*C_Q)
#define C_V  (3*C_Q)
#define C_P  (C_V + PROWS*DD/4)      // + 2096128
__global__ __launch_bounds__(256) void split_in_all(const float4* __restrict__ q,
                                                    const float4* __restrict__ k,
                                                    const float4* __restrict__ v,
                                                    const float4* __restrict__ p) {
    long i = (long)blockIdx.x * 256 + threadIdx.x;
    const float4* src; uint32_t *hi, *lo; long off;
    if (i < C_Q)      { src = q; hi = (uint32_t*)g_xqh; lo = (uint32_t*)g_xql; off = i; }
    else if (i < C_K) { src = k; hi = (uint32_t*)g_xkh; lo = (uint32_t*)g_xkl; off = i - C_Q; }
    else if (i < C_V) { src = v; hi = (uint32_t*)g_xvh; lo = (uint32_t*)g_xvl; off = i - C_K; }
    else if (i < C_P) { src = p; hi = (uint32_t*)g_xph; lo = (uint32_t*)g_xpl; off = i - C_V; }
    else return;
    float4 val = src[off];
    uint32_t h0, l0, h1, l1;
    split_pair(val.x, val.y, h0, l0);
    split_pair(val.z, val.w, h1, l1);
    hi[2*off] = h0; hi[2*off+1] = h1;
    lo[2*off] = l0; lo[2*off+1] = l1;
}

// ---------------- merged weight split (5 weights, z-indexed) ----------------
__global__ __launch_bounds__(256) void split_w_all(const float4* __restrict__ W0,
                                                   const float4* __restrict__ W1,
                                                   const float4* __restrict__ W2,
                                                   const float4* __restrict__ W3,
                                                   const float4* __restrict__ W4) {
    int z = blockIdx.z;
    const float4* src = (z == 0) ? W0 : (z == 1) ? W1 : (z == 2) ? W2 : (z == 3) ? W3 : W4;
    uint32_t* hi = (uint32_t*)g_wh + (size_t)z * (DD*DD/2);
    uint32_t* lo = (uint32_t*)g_wl + (size_t)z * (DD*DD/2);
    int i = blockIdx.x * 256 + threadIdx.x;
    float4 v = src[i];
    uint32_t h0, l0, h1, l1;
    split_pair(v.x, v.y, h0, l0);
    split_pair(v.z, v.w, h1, l1);
    hi[2*i] = h0; hi[2*i+1] = h1;
    lo[2*i] = l0; lo[2*i+1] = l1;
}

// ---------------- bias GEMV ----------------
__global__ __launch_bounds__(256) void biasdot(const float* __restrict__ bias,
                                               const __nv_bfloat16* __restrict__ xh,
                                               const __nv_bfloat16* __restrict__ xl,
                                               float* __restrict__ outg, int ROWS) {
    int gw = blockIdx.x * 8 + (threadIdx.x >> 5);
    int lane = threadIdx.x & 31;
    int ngroups = (ROWS + 7) >> 3;
    int jg = gw % ngroups;
    int rem = gw / ngroups;
    int h = rem & 7, b = rem >> 3;
    if (b >= BB) return;
    int jsub = lane >> 2, dq = lane & 3;
    int j = jg * 8 + jsub;
    float acc = 0.f;
    if (j < ROWS) {
        size_t base = ((size_t)(b * ROWS + j)) * DD + h * DH + dq * 16;
        uint4 h0 = *(const uint4*)&xh[base];
        uint4 h1 = *(const uint4*)&xh[base + 8];
        uint4 l0 = *(const uint4*)&xl[base];
        uint4 l1 = *(const uint4*)&xl[base + 8];
        uint32_t hs[8] = {h0.x,h0.y,h0.z,h0.w,h1.x,h1.y,h1.z,h1.w};
        uint32_t ls[8] = {l0.x,l0.y,l0.z,l0.w,l1.x,l1.y,l1.z,l1.w};
        const float* u = bias + h * DH + dq * 16;
        #pragma unroll
        for (int e = 0; e < 8; e++) {
            float2 f = unsplit(hs[e], ls[e]);
            acc += f.x * u[2*e] + f.y * u[2*e+1];
        }
    }
    acc += __shfl_xor_sync(0xffffffffu, acc, 1);
    acc += __shfl_xor_sync(0xffffffffu, acc, 2);
    if (dq == 0 && j < ROWS)
        outg[((size_t)(b * HH + h)) * ROWS + j] = acc;
}

// ---------------- GEMM core (macro-shared body) ----------------
#define G_AL  10240
#define G_BH  20480
#define G_BL  29184
#define G_STG 37888

// Merged projection GEMM: all 4 projections in one grid (4 x 320).
__global__ __launch_bounds__(256, 2) void gemm_proj_all() {
    extern __shared__ char smem[];
    uint32_t sb = (uint32_t)__cvta_generic_to_shared(smem);
    int tid = threadIdx.x, lane = tid & 31, wi = tid >> 5;
    int g = lane >> 2, t4 = lane & 3;
    int y = blockIdx.y;
    const __nv_bfloat16 *Ah, *Al, *Bh, *Bl;
    __nv_bfloat16 *Ch, *Cl;
    int M, row0;
    if (y < 192) {
        int sel = y >> 6;
        row0 = (y & 63) * 128; M = MROWS;
        if (sel == 0)      { Ah = g_xqh; Al = g_xql; Ch = g_qh; Cl = g_ql; }
        else if (sel == 1) { Ah = g_xkh; Al = g_xkl; Ch = g_kh; Cl = g_kl; }
        else               { Ah = g_xvh; Al = g_xvl; Ch = g_vh; Cl = g_vl; }
        Bh = g_wh + (size_t)sel * DD * DD;
        Bl = g_wl + (size_t)sel * DD * DD;
    } else {
        row0 = (y - 192) * 128; M = PROWS;
        Ah = g_xph; Al = g_xpl; Ch = g_ph; Cl = g_pl;
        Bh = g_wh + (size_t)3 * DD * DD;
        Bl = g_wl + (size_t)3 * DD * DD;
    }
    int col0 = blockIdx.x * 128;
    int wm = (wi & 3) * 32, wn = (wi >> 2) * 64;

    float acc[2][8][4];
    #pragma unroll
    for (int a = 0; a < 2; a++)
        #pragma unroll
        for (int b = 0; b < 8; b++)
            #pragma unroll
            for (int c = 0; c < 4; c++) acc[a][b][c] = 0.f;

    auto issue = [&](int it) {
        int k0 = it * 32;
        uint32_t st = sb + (it & 1) * G_STG;
        #pragma unroll
        for (int q = 0; q < 2; q++) {
            int c = q * 256 + tid;
            int m = c >> 2, seg = c & 3;
            bool ok = (row0 + m) < M;
            int mr = ok ? (row0 + m) : 0;
            cp16(st + m * 80 + seg * 16, Ah + (size_t)mr * DD + k0 + seg * 8, ok);
            cp16(st + G_AL + m * 80 + seg * 16, Al + (size_t)mr * DD + k0 + seg * 8, ok);
        }
        #pragma unroll
        for (int q = 0; q < 2; q++) {
            int c = q * 256 + tid;
            int k = c >> 4, seg = c & 15;
            cp16(st + G_BH + k * 272 + seg * 16, Bh + (size_t)(k0 + k) * DD + col0 + seg * 8, true);
            cp16(st + G_BL + k * 272 + seg * 16, Bl + (size_t)(k0 + k) * DD + col0 + seg * 8, true);
        }
        cpcommit();
    };

    issue(0);
    for (int it = 0; it < 16; it++) {
        if (it + 1 < 16) { issue(it + 1); cpwait<1>(); }
        else cpwait<0>();
        __syncthreads();
        uint32_t st = sb + (it & 1) * G_STG;
        #pragma unroll
        for (int kk = 0; kk < 32; kk += 16) {
            uint32_t ah[2][4], al[2][4];
            #pragma unroll
            for (int mi = 0; mi < 2; mi++) {
                uint32_t ad = st + (wm + 16 * mi + (lane & 15)) * 80 + (kk + ((lane >> 4) << 3)) * 2;
                ldsm4(ah[mi], ad);
                ldsm4(al[mi], ad + G_AL);
            }
            #pragma unroll
            for (int nh = 0; nh < 4; nh++) {
                int n0 = wn + 16 * nh;
                uint32_t bd = st + G_BH + (kk + (lane & 7) + (lane & 8)) * 272
                              + (n0 + ((lane & 16) >> 1)) * 2;
                uint32_t bh4[4], bl4[4];
                ldsm4t(bh4, bd);
                ldsm4t(bl4, bd + (G_BL - G_BH));
                #pragma unroll
                for (int half = 0; half < 2; half++) {
                    int nf = 2 * nh + half;
                    uint32_t bhh[2] = {bh4[2*half], bh4[2*half+1]};
                    uint32_t bll[2] = {bl4[2*half], bl4[2*half+1]};
                    #pragma unroll
                    for (int mi = 0; mi < 2; mi++)
                        mma3(acc[mi][nf], ah[mi], al[mi], bhh, bll);
                }
            }
        }
        __syncthreads();
    }

    #pragma unroll
    for (int mi = 0; mi < 2; mi++)
        #pragma unroll
        for (int nf = 0; nf < 8; nf++)
            #pragma unroll
            for (int half = 0; half < 2; half++) {
                int r = row0 + wm + 16 * mi + g + 8 * half;
                int c = col0 + wn + 8 * nf + 2 * t4;
                if (r < M) {
                    uint32_t h, l;
                    split_pair(acc[mi][nf][2*half], acc[mi][nf][2*half+1], h, l);
                    *(uint32_t*)&Ch[(size_t)r * DD + c] = h;
                    *(uint32_t*)&Cl[(size_t)r * DD + c] = l;
                }
            }
}

// Output projection GEMM (fp32 out)
__global__ __launch_bounds__(256, 2) void gemm_out(float* __restrict__ Cf) {
    extern __shared__ char smem[];
    uint32_t sb = (uint32_t)__cvta_generic_to_shared(smem);
    int tid = threadIdx.x, lane = tid & 31, wi = tid >> 5;
    int g = lane >> 2, t4 = lane & 3;
    int row0 = blockIdx.y * 128, col0 = blockIdx.x * 128;
    int wm = (wi & 3) * 32, wn = (wi >> 2) * 64;
    const __nv_bfloat16* Ah = g_ch;
    const __nv_bfloat16* Al = g_cl;
    const __nv_bfloat16* Bh = g_wh + (size_t)4 * DD * DD;
    const __nv_bfloat16* Bl = g_wl + (size_t)4 * DD * DD;

    float acc[2][8][4];
    #pragma unroll
    for (int a = 0; a < 2; a++)
        #pragma unroll
        for (int b = 0; b < 8; b++)
            #pragma unroll
            for (int c = 0; c < 4; c++) acc[a][b][c] = 0.f;

    auto issue = [&](int it) {
        int k0 = it * 32;
        uint32_t st = sb + (it & 1) * G_STG;
        #pragma unroll
        for (int q = 0; q < 2; q++) {
            int c = q * 256 + tid;
            int m = c >> 2, seg = c & 3;
            cp16(st + m * 80 + seg * 16, Ah + (size_t)(row0 + m) * DD + k0 + seg * 8, true);
            cp16(st + G_AL + m * 80 + seg * 16, Al + (size_t)(row0 + m) * DD + k0 + seg * 8, true);
        }
        #pragma unroll
        for (int q = 0; q < 2; q++) {
            int c = q * 256 + tid;
            int k = c >> 4, seg = c & 15;
            cp16(st + G_BH + k * 272 + seg * 16, Bh + (size_t)(k0 + k) * DD + col0 + seg * 8, true);
            cp16(st + G_BL + k * 272 + seg * 16, Bl + (size_t)(k0 + k) * DD + col0 + seg * 8, true);
        }
        cpcommit();
    };

    issue(0);
    for (int it = 0; it < 16; it++) {
        if (it + 1 < 16) { issue(it + 1); cpwait<1>(); }
        else cpwait<0>();
        __syncthreads();
        uint32_t st = sb + (it & 1) * G_STG;
        #pragma unroll
        for (int kk = 0; kk < 32; kk += 16) {
            uint32_t ah[2][4], al[2][4];
            #pragma unroll
            for (int mi = 0; mi < 2; mi++) {
                uint32_t ad = st + (wm + 16 * mi + (lane & 15)) * 80 + (kk + ((lane >> 4) << 3)) * 2;
                ldsm4(ah[mi], ad);
                ldsm4(al[mi], ad + G_AL);
            }
            #pragma unroll
            for (int nh = 0; nh < 4; nh++) {
                int n0 = wn + 16 * nh;
                uint32_t bd = st + G_BH + (kk + (lane & 7) + (lane & 8)) * 272
                              + (n0 + ((lane & 16) >> 1)) * 2;
                uint32_t bh4[4], bl4[4];
                ldsm4t(bh4, bd);
                ldsm4t(bl4, bd + (G_BL - G_BH));
                #pragma unroll
                for (int half = 0; half < 2; half++) {
                    int nf = 2 * nh + half;
                    uint32_t bhh[2] = {bh4[2*half], bh4[2*half+1]};
                    uint32_t bll[2] = {bl4[2*half], bl4[2*half+1]};
                    #pragma unroll
                    for (int mi = 0; mi < 2; mi++)
                        mma3(acc[mi][nf], ah[mi], al[mi], bhh, bll);
                }
            }
        }
        __syncthreads();
    }

    #pragma unroll
    for (int mi = 0; mi < 2; mi++)
        #pragma unroll
        for (int nf = 0; nf < 8; nf++)
            #pragma unroll
            for (int half = 0; half < 2; half++) {
                int r = row0 + wm + 16 * mi + g + 8 * half;
                int c = col0 + wn + 8 * nf + 2 * t4;
                *(float2*)&Cf[(size_t)r * DD + c] =
                    make_float2(acc[mi][nf][2*half], acc[mi][nf][2*half+1]);
            }
}

// ---------------- fused flash attention v3 (merged content+pos MMA loop) ----------------
#define SQ_H  0
#define SQ_L  9216
#define SK_H  18432
#define SK_L  36864
#define SP_H  55296
#define SP_L  82944
#define SV_H  110592
#define SV_L  129024
#define SATT  147456
#define SATT_L (SATT + 17408)
#define SSTAT (SATT + 34816)
#define UKOFF (SSTAT + 768)
#define VPOFF (UKOFF + 1024)
#define FL_SMEM (VPOFF + 1536)

__global__ __launch_bounds__(256, 1) void flash_v3() {
    extern __shared__ char smem[];
    uint32_t sb = (uint32_t)__cvta_generic_to_shared(smem);
    float* S32  = (float*)(smem + SATT);
    float* m_s  = (float*)(smem + SSTAT);
    float* l_s  = m_s + 64;
    float* al_s = m_s + 128;
    float* uk_s = (float*)(smem + UKOFF);
    float* vp_s = (float*)(smem + VPOFF);

    int tid = threadIdx.x, lane = tid & 31, wi = tid >> 5;
    int g = lane >> 2, t4 = lane & 3;
    int bh = blockIdx.y, b = bh >> 3, h = bh & 7;
    int i0 = blockIdx.x * 64;
    int wm = (wi & 3) * 16, wcol = wi >> 2;

    float accO[4][4];
    #pragma unroll
    for (int c = 0; c < 4; c++)
        #pragma unroll
        for (int e = 0; e < 4; e++) accO[c][e] = 0.f;

    auto issue_kp = [&](int jt) {
        int j0 = jt * 128;
        int pbase = 960 + j0 - i0;
        #pragma unroll
        for (int q = 0; q < 4; q++) {
            int c = q * 256 + tid;
            int row = c >> 3, seg = c & 7;
            size_t src = (size_t)(b * SS + j0 + row) * DD + h * DH + seg * 8;
            uint32_t d = sb + row * 144 + seg * 16;
            cp16(d + SK_H, g_kh + src, true);
            cp16(d + SK_L, g_kl + src, true);
        }
        #pragma unroll
        for (int q = 0; q < 6; q++) {
            int c = q * 256 + tid;
            int row = c >> 3, seg = c & 7;
            bool ok = row < 191;
            int rc = ok ? row : 0;
            size_t src = (size_t)(b * L2P + pbase + rc) * DD + h * DH + seg * 8;
            uint32_t d = sb + row * 144 + seg * 16;
            cp16(d + SP_H, g_ph + src, ok);
            cp16(d + SP_L, g_pl + src, ok);
        }
        if (tid < 32)
            cp16(sb + UKOFF + (jt & 1) * 512 + tid * 16,
                 g_uk + ((size_t)(b * HH + h)) * SS + j0 + tid * 4, true);
        if (tid < 192)
            cp4(sb + VPOFF + (jt & 1) * 768 + tid * 4,
                g_vp + ((size_t)(b * HH + h)) * L2P + pbase + tid);
        cpcommit();
    };
    auto issue_v = [&](int jt) {
        int j0 = jt * 128;
        #pragma unroll
        for (int q = 0; q < 4; q++) {
            int c = q * 256 + tid;
            int row = c >> 3, seg = c & 7;
            size_t src = (size_t)(b * SS + j0 + row) * DD + h * DH + seg * 8;
            uint32_t d = sb + row * 144 + seg * 16;
            cp16(d + SV_H, g_vh + src, true);
            cp16(d + SV_L, g_vl + src, true);
        }
        cpcommit();
    };

    #pragma unroll
    for (int q = 0; q < 2; q++) {
        int c = q * 256 + tid;
        int row = c >> 3, seg = c & 7;
        size_t src = (size_t)(b * SS + i0 + row) * DD + h * DH + seg * 8;
        uint32_t d = sb + row * 144 + seg * 16;
        cp16(d + SQ_H, g_qh + src, true);
        cp16(d + SQ_L, g_ql + src, true);
    }
    issue_kp(0);
    issue_v(0);

    for (int jt = 0; jt < 8; jt++) {
        cpwait<1>();
        __syncthreads();
        int ub2 = (jt & 1) * 128;
        int vb2 = (jt & 1) * 192;

        // ---- merged content (QK^T) + pos (QP^T) over the same Q fragments ----
        float accC[8][4];
        float accR[12][4];
        #pragma unroll
        for (int c = 0; c < 8; c++)
            #pragma unroll
            for (int e = 0; e < 4; e++) accC[c][e] = 0.f;
        #pragma unroll
        for (int c = 0; c < 12; c++)
            #pragma unroll
            for (int e = 0; e < 4; e++) accR[c][e] = 0.f;

        #pragma unroll
        for (int kk = 0; kk < 64; kk += 16) {
            uint32_t ah[4], al[4];
            uint32_t ad = sb + SQ_H + (wm + (lane & 15)) * 144 + (kk + ((lane >> 4) << 3)) * 2;
            ldsm4(ah, ad);
            ldsm4(al, ad + (SQ_L - SQ_H));
            #pragma unroll
            for (int nh = 0; nh < 4; nh++) {
                int n0 = wcol * 64 + 16 * nh;
                uint32_t bd = sb + SK_H + (n0 + (lane & 15)) * 144 + (kk + ((lane >> 4) << 3)) * 2;
                uint32_t bh4[4], bl4[4];
                ldsm4(bh4, bd);
                ldsm4(bl4, bd + (SK_L - SK_H));
                #pragma unroll
                for (int half = 0; half < 2; half++) {
                    int nf = 2 * nh + half;
                    uint32_t bhh[2] = {bh4[half], bh4[half+2]};
                    uint32_t bll[2] = {bl4[half], bl4[half+2]};
                    mma3(accC[nf], ah, al, bhh, bll);
                }
            }
            #pragma unroll
            for (int nh = 0; nh < 6; nh++) {
                int n0 = wcol * 96 + 16 * nh;
                uint32_t bd = sb + SP_H + (n0 + (lane & 15)) * 144 + (kk + ((lane >> 4) << 3)) * 2;
                uint32_t bh4[4], bl4[4];
                ldsm4(bh4, bd);
                ldsm4(bl4, bd + (SP_L - SP_H));
                #pragma unroll
                for (int half = 0; half < 2; half++) {
                    int nf = 2 * nh + half;
                    uint32_t bhh[2] = {bh4[half], bh4[half+2]};
                    uint32_t bll[2] = {bl4[half], bl4[half+2]};
                    mma3(accR[nf], ah, al, bhh, bll);
                }
            }
        }
        // dump content + uk (exclusive cells, no sync needed)
        #pragma unroll
        for (int nf = 0; nf < 8; nf++) {
            int jj = wcol * 64 + 8 * nf + 2 * t4;
            int rl = wm + g;
            S32[rl * 132 + jj]     = (accC[nf][0] + uk_s[ub2 + jj])     * SCALE;
            S32[rl * 132 + jj + 1] = (accC[nf][1] + uk_s[ub2 + jj + 1]) * SCALE;
            S32[(rl + 8) * 132 + jj]     = (accC[nf][2] + uk_s[ub2 + jj])     * SCALE;
            S32[(rl + 8) * 132 + jj + 1] = (accC[nf][3] + uk_s[ub2 + jj + 1]) * SCALE;
        }
        __syncthreads();          // K,P consumed; content dumps visible
        if (jt < 7) issue_kp(jt + 1); else cpcommit();

        // scatter pos: jl = t + rl - 63 (injective per row)
        #pragma unroll
        for (int nf = 0; nf < 12; nf++) {
            int t = wcol * 96 + 8 * nf + 2 * t4;
            #pragma unroll
            for (int half = 0; half < 2; half++) {
                int rl = wm + g + 8 * half;
                int jl = t + rl - 63;
                if (jl >= 0 && jl < 128)
                    S32[rl * 132 + jl] += (accR[nf][2*half] + vp_s[vb2 + t]) * SCALE;
                int jl2 = jl + 1;
                if (jl2 >= 0 && jl2 < 128)
                    S32[rl * 132 + jl2] += (accR[nf][2*half+1] + vp_s[vb2 + t + 1]) * SCALE;
            }
        }
        __syncthreads();

        // ---- online softmax (4 threads per row) ----
        int r = tid >> 2, q4 = tid & 3;
        float p[32];
        {
            const float4* Sp = (const float4*)(S32 + r * 132 + q4 * 32);
            float tm = -1e30f;
            #pragma unroll
            for (int q = 0; q < 8; q++) {
                float4 v = Sp[q];
                p[4*q] = v.x; p[4*q+1] = v.y; p[4*q+2] = v.z; p[4*q+3] = v.w;
                tm = fmaxf(tm, fmaxf(fmaxf(v.x, v.y), fmaxf(v.z, v.w)));
            }
            tm = fmaxf(tm, __shfl_xor_sync(0xffffffffu, tm, 1));
            tm = fmaxf(tm, __shfl_xor_sync(0xffffffffu, tm, 2));
            float mo = jt ? m_s[r] : -1e30f;
            float lo = jt ? l_s[r] : 0.f;
            float mn = fmaxf(mo, tm);
            float alpha = __expf(mo - mn);
            float sum = 0.f;
            #pragma unroll
            for (int c = 0; c < 32; c++) { p[c] = __expf(p[c] - mn); sum += p[c]; }
            sum += __shfl_xor_sync(0xffffffffu, sum, 1);
            sum += __shfl_xor_sync(0xffffffffu, sum, 2);
            if (q4 == 0) { m_s[r] = mn; l_s[r] = alpha * lo + sum; al_s[r] = alpha; }
        }
        __syncthreads();

        // write probs (split bf16) into attn buffer (aliases S32)
        {
            uint32_t* ahp = (uint32_t*)(smem + SATT)   + r * 68 + q4 * 16;
            uint32_t* alp = (uint32_t*)(smem + SATT_L) + r * 68 + q4 * 16;
            #pragma unroll
            for (int q = 0; q < 16; q++) {
                uint32_t hh, ll;
                split_pair(p[2*q], p[2*q+1], hh, ll);
                ahp[q] = hh; alp[q] = ll;
            }
        }
        cpwait<1>();              // V(jt) ready
        __syncthreads();

        // rescale O, then accumulate P @ V (k = 128)
        {
            float a1 = al_s[wm + g];
            float a2 = al_s[wm + g + 8];
            #pragma unroll
            for (int nf = 0; nf < 4; nf++) {
                accO[nf][0] *= a1; accO[nf][1] *= a1;
                accO[nf][2] *= a2; accO[nf][3] *= a2;
            }
        }
        #pragma unroll
        for (int kk = 0; kk < 128; kk += 16) {
            uint32_t ah[4], al[4];
            uint32_t ad = sb + SATT + (wm + (lane & 15)) * 272 + (kk + ((lane >> 4) << 3)) * 2;
            ldsm4(ah, ad);
            ldsm4(al, ad + (SATT_L - SATT));
            #pragma unroll
            for (int nh = 0; nh < 2; nh++) {
                int n0 = wcol * 32 + 16 * nh;
                uint32_t bd = sb + SV_H + (kk + (lane & 7) + (lane & 8)) * 144
                              + (n0 + ((lane & 16) >> 1)) * 2;
                uint32_t bh4[4], bl4[4];
                ldsm4t(bh4, bd);
                ldsm4t(bl4, bd + (SV_L - SV_H));
                #pragma unroll
                for (int half = 0; half < 2; half++) {
                    int nf = 2 * nh + half;
                    uint32_t bhh[2] = {bh4[2*half], bh4[2*half+1]};
                    uint32_t bll[2] = {bl4[2*half], bl4[2*half+1]};
                    mma3(accO[nf], ah, al, bhh, bll);
                }
            }
        }
        __syncthreads();
        if (jt < 7) issue_v(jt + 1); else cpcommit();
    }

    // epilogue: normalize, split, store context
    #pragma unroll
    for (int nf = 0; nf < 4; nf++)
        #pragma unroll
        for (int half = 0; half < 2; half++) {
            int rl = wm + g + 8 * half;
            float inv = 1.f / l_s[rl];
            int dl = wcol * 32 + 8 * nf + 2 * t4;
            uint32_t hh, ll;
            split_pair(accO[nf][2*half] * inv, accO[nf][2*half+1] * inv, hh, ll);
            size_t o = (size_t)(b * SS + i0 + rl) * DD + h * DH + dl;
            *(uint32_t*)&g_ch[o] = hh;
            *(uint32_t*)&g_cl[o] = ll;
        }
}

// ---------------- launch ----------------
extern "C" void kernel_launch(void* const* d_in, const int* in_sizes, int n_in,
                              void* d_out, int out_size) {
    const float* query = (const float*)d_in[0];
    const float* key   = (const float*)d_in[1];
    const float* value = (const float*)d_in[2];
    const float* pos   = (const float*)d_in[3];
    const float* Wq    = (const float*)d_in[4];
    const float* Wk    = (const float*)d_in[5];
    const float* Wv    = (const float*)d_in[6];
    const float* Wp    = (const float*)d_in[7];
    const float* ub    = (const float*)d_in[8];
    const float* vb    = (const float*)d_in[9];
    const float* Wo    = (const float*)d_in[10];
    float* out = (float*)d_out;

    __nv_bfloat16 *kh, *kl, *ph, *pl;
    float *ukp, *vpp;
    cudaGetSymbolAddress((void**)&kh, g_kh);   cudaGetSymbolAddress((void**)&kl, g_kl);
    cudaGetSymbolAddress((void**)&ph, g_ph);   cudaGetSymbolAddress((void**)&pl, g_pl);
    cudaGetSymbolAddress((void**)&ukp, g_uk);  cudaGetSymbolAddress((void**)&vpp, g_vp);

    static bool attr_done = false;
    if (!attr_done) {
        cudaFuncSetAttribute(gemm_proj_all, cudaFuncAttributeMaxDynamicSharedMemorySize, 2*G_STG);
        cudaFuncSetAttribute(gemm_out,      cudaFuncAttributeMaxDynamicSharedMemorySize, 2*G_STG);
        cudaFuncSetAttribute(flash_v3,      cudaFuncAttributeMaxDynamicSharedMemorySize, FL_SMEM);
        attr_done = true;
    }

    dim3 blk(256);

    // merged splits
    split_in_all<<<(C_P + 255)/256, blk>>>((const float4*)query, (const float4*)key,
                                           (const float4*)value, (const float4*)pos);
    split_w_all<<<dim3(DD*DD/4/256, 1, 5), blk>>>((const float4*)Wq, (const float4*)Wk,
                                                  (const float4*)Wv, (const float4*)Wp,
                                                  (const float4*)Wo);

    // merged projections (q,k,v,p in one launch)
    gemm_proj_all<<<dim3(4, 320), blk, 2*G_STG>>>();

    // rank-1 bias terms
    biasdot<<<dim3(8*8*(SS/8)/8), blk>>>(ub, kh, kl, ukp, SS);
    biasdot<<<dim3((8*8*((L2P+7)/8) + 7)/8), blk>>>(vb, ph, pl, vpp, L2P);

    // fused attention
    flash_v3<<<dim3(SS/64, BB*HH), blk, FL_SMEM>>>();

    // output projection
    gemm_out<<<dim3(4, 64), blk, 2*G_STG>>>(out);
}

// round 10
// speedup vs baseline: 3.7253x; 1.0392x over previous
#include <cuda_runtime.h>
#include <cuda_bf16.h>
#include <cstdint>

#define BB 8
#define SS 1024
#define DD 512
#define HH 8
#define DH 64
#define L2P 2047
#define SCALE 0.125f
#define MROWS (BB*SS)      // 8192
#define PROWS (BB*L2P)     // 16376

// ---------------- scratch ----------------
__device__ __nv_bfloat16 g_xqh[MROWS*DD], g_xql[MROWS*DD];
__device__ __nv_bfloat16 g_xkh[MROWS*DD], g_xkl[MROWS*DD];
__device__ __nv_bfloat16 g_xvh[MROWS*DD], g_xvl[MROWS*DD];
__device__ __nv_bfloat16 g_xph[PROWS*DD], g_xpl[PROWS*DD];
__device__ __nv_bfloat16 g_wh[5*DD*DD], g_wl[5*DD*DD];
__device__ __nv_bfloat16 g_qh[MROWS*DD],  g_ql[MROWS*DD];
__device__ __nv_bfloat16 g_kh[MROWS*DD],  g_kl[MROWS*DD];
__device__ __nv_bfloat16 g_vh[MROWS*DD],  g_vl[MROWS*DD];
__device__ __nv_bfloat16 g_ph[(PROWS+8)*DD], g_pl[(PROWS+8)*DD];
__device__ __nv_bfloat16 g_ch[MROWS*DD], g_cl[MROWS*DD];
__device__ float g_uk[BB*HH*SS];
__device__ float g_vp[BB*HH*L2P + 64];

// ---------------- helpers ----------------
__device__ __forceinline__ void split_pair(float x0, float x1, uint32_t& h, uint32_t& l) {
    __nv_bfloat162 hh = __floats2bfloat162_rn(x0, x1);
    float r0 = x0 - __bfloat162float(hh.x);
    float r1 = x1 - __bfloat162float(hh.y);
    __nv_bfloat162 ll = __floats2bfloat162_rn(r0, r1);
    h = *reinterpret_cast<uint32_t*>(&hh);
    l = *reinterpret_cast<uint32_t*>(&ll);
}
__device__ __forceinline__ float2 unsplit(uint32_t h, uint32_t l) {
    __nv_bfloat162 hh = *reinterpret_cast<__nv_bfloat162*>(&h);
    __nv_bfloat162 ll = *reinterpret_cast<__nv_bfloat162*>(&l);
    return make_float2(__bfloat162float(hh.x) + __bfloat162float(ll.x),
                       __bfloat162float(hh.y) + __bfloat162float(ll.y));
}
__device__ __forceinline__ void mma16816(float d[4], const uint32_t a[4], const uint32_t b[2]) {
    asm volatile(
        "mma.sync.aligned.m16n8k16.row.col.f32.bf16.bf16.f32 "
        "{%0,%1,%2,%3}, {%4,%5,%6,%7}, {%8,%9}, {%0,%1,%2,%3};\n"
        : "+f"(d[0]), "+f"(d[1]), "+f"(d[2]), "+f"(d[3])
        : "r"(a[0]), "r"(a[1]), "r"(a[2]), "r"(a[3]), "r"(b[0]), "r"(b[1]));
}
__device__ __forceinline__ void mma3(float d[4], const uint32_t ah[4], const uint32_t al[4],
                                     const uint32_t bh[2], const uint32_t bl[2]) {
    mma16816(d, ah, bh);
    mma16816(d, ah, bl);
    mma16816(d, al, bh);
}
__device__ __forceinline__ void ldsm4(uint32_t r[4], uint32_t addr) {
    asm volatile("ldmatrix.sync.aligned.m8n8.x4.shared.b16 {%0,%1,%2,%3},[%4];"
        : "=r"(r[0]), "=r"(r[1]), "=r"(r[2]), "=r"(r[3]) : "r"(addr));
}
__device__ __forceinline__ void ldsm4t(uint32_t r[4], uint32_t addr) {
    asm volatile("ldmatrix.sync.aligned.m8n8.x4.trans.shared.b16 {%0,%1,%2,%3},[%4];"
        : "=r"(r[0]), "=r"(r[1]), "=r"(r[2]), "=r"(r[3]) : "r"(addr));
}
__device__ __forceinline__ void cp16(uint32_t dst, const void* src, bool pred) {
    int sz = pred ? 16 : 0;
    asm volatile("cp.async.cg.shared.global [%0],[%1],16,%2;\n"
        :: "r"(dst), "l"(src), "r"(sz));
}
__device__ __forceinline__ void cp4(uint32_t dst, const void* src) {
    asm volatile("cp.async.ca.shared.global [%0],[%1],4;\n" :: "r"(dst), "l"(src));
}
__device__ __forceinline__ void cpcommit() { asm volatile("cp.async.commit_group;\n"); }
template<int N> __device__ __forceinline__ void cpwait() {
    asm volatile("cp.async.wait_group %0;\n" :: "n"(N));
}

// ---------------- merged input split prepass ----------------
#define C_Q  (MROWS*DD/4)
#define C_K  (2*C_Q)
#define C_V  (3*C_Q)
#define C_P  (C_V + PROWS*DD/4)
__global__ __launch_bounds__(256) void split_in_all(const float4* __restrict__ q,
                                                    const float4* __restrict__ k,
                                                    const float4* __restrict__ v,
                                                    const float4* __restrict__ p) {
    long i = (long)blockIdx.x * 256 + threadIdx.x;
    const float4* src; uint32_t *hi, *lo; long off;
    if (i < C_Q)      { src = q; hi = (uint32_t*)g_xqh; lo = (uint32_t*)g_xql; off = i; }
    else if (i < C_K) { src = k; hi = (uint32_t*)g_xkh; lo = (uint32_t*)g_xkl; off = i - C_Q; }
    else if (i < C_V) { src = v; hi = (uint32_t*)g_xvh; lo = (uint32_t*)g_xvl; off = i - C_K; }
    else if (i < C_P) { src = p; hi = (uint32_t*)g_xph; lo = (uint32_t*)g_xpl; off = i - C_V; }
    else return;
    float4 val = src[off];
    uint32_t h0, l0, h1, l1;
    split_pair(val.x, val.y, h0, l0);
    split_pair(val.z, val.w, h1, l1);
    hi[2*off] = h0; hi[2*off+1] = h1;
    lo[2*off] = l0; lo[2*off+1] = l1;
}

__global__ __launch_bounds__(256) void split_w_all(const float4* __restrict__ W0,
                                                   const float4* __restrict__ W1,
                                                   const float4* __restrict__ W2,
                                                   const float4* __restrict__ W3,
                                                   const float4* __restrict__ W4) {
    int z = blockIdx.z;
    const float4* src = (z == 0) ? W0 : (z == 1) ? W1 : (z == 2) ? W2 : (z == 3) ? W3 : W4;
    uint32_t* hi = (uint32_t*)g_wh + (size_t)z * (DD*DD/2);
    uint32_t* lo = (uint32_t*)g_wl + (size_t)z * (DD*DD/2);
    int i = blockIdx.x * 256 + threadIdx.x;
    float4 v = src[i];
    uint32_t h0, l0, h1, l1;
    split_pair(v.x, v.y, h0, l0);
    split_pair(v.z, v.w, h1, l1);
    hi[2*i] = h0; hi[2*i+1] = h1;
    lo[2*i] = l0; lo[2*i+1] = l1;
}

// ---------------- merged bias GEMV (z=0: u.k ; z=1: v.p) ----------------
__global__ __launch_bounds__(256) void biasdot2(const float* __restrict__ ub,
                                                const float* __restrict__ vb) {
    int z = blockIdx.z;
    const float* bias = z ? vb : ub;
    const __nv_bfloat16* xh = z ? g_ph : g_kh;
    const __nv_bfloat16* xl = z ? g_pl : g_kl;
    float* outg = z ? g_vp : g_uk;
    int ROWS = z ? L2P : SS;

    int gw = blockIdx.x * 8 + (threadIdx.x >> 5);
    int lane = threadIdx.x & 31;
    int ngroups = (ROWS + 7) >> 3;
    int jg = gw % ngroups;
    int rem = gw / ngroups;
    int h = rem & 7, b = rem >> 3;
    if (b >= BB) return;
    int jsub = lane >> 2, dq = lane & 3;
    int j = jg * 8 + jsub;
    float acc = 0.f;
    if (j < ROWS) {
        size_t base = ((size_t)(b * ROWS + j)) * DD + h * DH + dq * 16;
        uint4 h0 = *(const uint4*)&xh[base];
        uint4 h1 = *(const uint4*)&xh[base + 8];
        uint4 l0 = *(const uint4*)&xl[base];
        uint4 l1 = *(const uint4*)&xl[base + 8];
        uint32_t hs[8] = {h0.x,h0.y,h0.z,h0.w,h1.x,h1.y,h1.z,h1.w};
        uint32_t ls[8] = {l0.x,l0.y,l0.z,l0.w,l1.x,l1.y,l1.z,l1.w};
        const float* u = bias + h * DH + dq * 16;
        #pragma unroll
        for (int e = 0; e < 8; e++) {
            float2 f = unsplit(hs[e], ls[e]);
            acc += f.x * u[2*e] + f.y * u[2*e+1];
        }
    }
    acc += __shfl_xor_sync(0xffffffffu, acc, 1);
    acc += __shfl_xor_sync(0xffffffffu, acc, 2);
    if (dq == 0 && j < ROWS)
        outg[((size_t)(b * HH + h)) * ROWS + j] = acc;
}

// ---------------- GEMM ----------------
#define G_AL  10240
#define G_BH  20480
#define G_BL  29184
#define G_STG 37888

__global__ __launch_bounds__(256, 2) void gemm_proj_all() {
    extern __shared__ char smem[];
    uint32_t sb = (uint32_t)__cvta_generic_to_shared(smem);
    int tid = threadIdx.x, lane = tid & 31, wi = tid >> 5;
    int g = lane >> 2, t4 = lane & 3;
    int y = blockIdx.y;
    const __nv_bfloat16 *Ah, *Al, *Bh, *Bl;
    __nv_bfloat16 *Ch, *Cl;
    int M, row0;
    if (y < 192) {
        int sel = y >> 6;
        row0 = (y & 63) * 128; M = MROWS;
        if (sel == 0)      { Ah = g_xqh; Al = g_xql; Ch = g_qh; Cl = g_ql; }
        else if (sel == 1) { Ah = g_xkh; Al = g_xkl; Ch = g_kh; Cl = g_kl; }
        else               { Ah = g_xvh; Al = g_xvl; Ch = g_vh; Cl = g_vl; }
        Bh = g_wh + (size_t)sel * DD * DD;
        Bl = g_wl + (size_t)sel * DD * DD;
    } else {
        row0 = (y - 192) * 128; M = PROWS;
        Ah = g_xph; Al = g_xpl; Ch = g_ph; Cl = g_pl;
        Bh = g_wh + (size_t)3 * DD * DD;
        Bl = g_wl + (size_t)3 * DD * DD;
    }
    int col0 = blockIdx.x * 128;
    int wm = (wi & 3) * 32, wn = (wi >> 2) * 64;

    float acc[2][8][4];
    #pragma unroll
    for (int a = 0; a < 2; a++)
        #pragma unroll
        for (int b = 0; b < 8; b++)
            #pragma unroll
            for (int c = 0; c < 4; c++) acc[a][b][c] = 0.f;

    auto issue = [&](int it) {
        int k0 = it * 32;
        uint32_t st = sb + (it & 1) * G_STG;
        #pragma unroll
        for (int q = 0; q < 2; q++) {
            int c = q * 256 + tid;
            int m = c >> 2, seg = c & 3;
            bool ok = (row0 + m) < M;
            int mr = ok ? (row0 + m) : 0;
            cp16(st + m * 80 + seg * 16, Ah + (size_t)mr * DD + k0 + seg * 8, ok);
            cp16(st + G_AL + m * 80 + seg * 16, Al + (size_t)mr * DD + k0 + seg * 8, ok);
        }
        #pragma unroll
        for (int q = 0; q < 2; q++) {
            int c = q * 256 + tid;
            int k = c >> 4, seg = c & 15;
            cp16(st + G_BH + k * 272 + seg * 16, Bh + (size_t)(k0 + k) * DD + col0 + seg * 8, true);
            cp16(st + G_BL + k * 272 + seg * 16, Bl + (size_t)(k0 + k) * DD + col0 + seg * 8, true);
        }
        cpcommit();
    };

    issue(0);
    for (int it = 0; it < 16; it++) {
        if (it + 1 < 16) { issue(it + 1); cpwait<1>(); }
        else cpwait<0>();
        __syncthreads();
        uint32_t st = sb + (it & 1) * G_STG;
        #pragma unroll
        for (int kk = 0; kk < 32; kk += 16) {
            uint32_t ah[2][4], al[2][4];
            #pragma unroll
            for (int mi = 0; mi < 2; mi++) {
                uint32_t ad = st + (wm + 16 * mi + (lane & 15)) * 80 + (kk + ((lane >> 4) << 3)) * 2;
                ldsm4(ah[mi], ad);
                ldsm4(al[mi], ad + G_AL);
            }
            #pragma unroll
            for (int nh = 0; nh < 4; nh++) {
                int n0 = wn + 16 * nh;
                uint32_t bd = st + G_BH + (kk + (lane & 7) + (lane & 8)) * 272
                              + (n0 + ((lane & 16) >> 1)) * 2;
                uint32_t bh4[4], bl4[4];
                ldsm4t(bh4, bd);
                ldsm4t(bl4, bd + (G_BL - G_BH));
                #pragma unroll
                for (int half = 0; half < 2; half++) {
                    int nf = 2 * nh + half;
                    uint32_t bhh[2] = {bh4[2*half], bh4[2*half+1]};
                    uint32_t bll[2] = {bl4[2*half], bl4[2*half+1]};
                    #pragma unroll
                    for (int mi = 0; mi < 2; mi++)
                        mma3(acc[mi][nf], ah[mi], al[mi], bhh, bll);
                }
            }
        }
        __syncthreads();
    }

    #pragma unroll
    for (int mi = 0; mi < 2; mi++)
        #pragma unroll
        for (int nf = 0; nf < 8; nf++)
            #pragma unroll
            for (int half = 0; half < 2; half++) {
                int r = row0 + wm + 16 * mi + g + 8 * half;
                int c = col0 + wn + 8 * nf + 2 * t4;
                if (r < M) {
                    uint32_t h, l;
                    split_pair(acc[mi][nf][2*half], acc[mi][nf][2*half+1], h, l);
                    *(uint32_t*)&Ch[(size_t)r * DD + c] = h;
                    *(uint32_t*)&Cl[(size_t)r * DD + c] = l;
                }
            }
}

__global__ __launch_bounds__(256, 2) void gemm_out(float* __restrict__ Cf) {
    extern __shared__ char smem[];
    uint32_t sb = (uint32_t)__cvta_generic_to_shared(smem);
    int tid = threadIdx.x, lane = tid & 31, wi = tid >> 5;
    int g = lane >> 2, t4 = lane & 3;
    int row0 = blockIdx.y * 128, col0 = blockIdx.x * 128;
    int wm = (wi & 3) * 32, wn = (wi >> 2) * 64;
    const __nv_bfloat16* Ah = g_ch;
    const __nv_bfloat16* Al = g_cl;
    const __nv_bfloat16* Bh = g_wh + (size_t)4 * DD * DD;
    const __nv_bfloat16* Bl = g_wl + (size_t)4 * DD * DD;

    float acc[2][8][4];
    #pragma unroll
    for (int a = 0; a < 2; a++)
        #pragma unroll
        for (int b = 0; b < 8; b++)
            #pragma unroll
            for (int c = 0; c < 4; c++) acc[a][b][c] = 0.f;

    auto issue = [&](int it) {
        int k0 = it * 32;
        uint32_t st = sb + (it & 1) * G_STG;
        #pragma unroll
        for (int q = 0; q < 2; q++) {
            int c = q * 256 + tid;
            int m = c >> 2, seg = c & 3;
            cp16(st + m * 80 + seg * 16, Ah + (size_t)(row0 + m) * DD + k0 + seg * 8, true);
            cp16(st + G_AL + m * 80 + seg * 16, Al + (size_t)(row0 + m) * DD + k0 + seg * 8, true);
        }
        #pragma unroll
        for (int q = 0; q < 2; q++) {
            int c = q * 256 + tid;
            int k = c >> 4, seg = c & 15;
            cp16(st + G_BH + k * 272 + seg * 16, Bh + (size_t)(k0 + k) * DD + col0 + seg * 8, true);
            cp16(st + G_BL + k * 272 + seg * 16, Bl + (size_t)(k0 + k) * DD + col0 + seg * 8, true);
        }
        cpcommit();
    };

    issue(0);
    for (int it = 0; it < 16; it++) {
        if (it + 1 < 16) { issue(it + 1); cpwait<1>(); }
        else cpwait<0>();
        __syncthreads();
        uint32_t st = sb + (it & 1) * G_STG;
        #pragma unroll
        for (int kk = 0; kk < 32; kk += 16) {
            uint32_t ah[2][4], al[2][4];
            #pragma unroll
            for (int mi = 0; mi < 2; mi++) {
                uint32_t ad = st + (wm + 16 * mi + (lane & 15)) * 80 + (kk + ((lane >> 4) << 3)) * 2;
                ldsm4(ah[mi], ad);
                ldsm4(al[mi], ad + G_AL);
            }
            #pragma unroll
            for (int nh = 0; nh < 4; nh++) {
                int n0 = wn + 16 * nh;
                uint32_t bd = st + G_BH + (kk + (lane & 7) + (lane & 8)) * 272
                              + (n0 + ((lane & 16) >> 1)) * 2;
                uint32_t bh4[4], bl4[4];
                ldsm4t(bh4, bd);
                ldsm4t(bl4, bd + (G_BL - G_BH));
                #pragma unroll
                for (int half = 0; half < 2; half++) {
                    int nf = 2 * nh + half;
                    uint32_t bhh[2] = {bh4[2*half], bh4[2*half+1]};
                    uint32_t bll[2] = {bl4[2*half], bl4[2*half+1]};
                    #pragma unroll
                    for (int mi = 0; mi < 2; mi++)
                        mma3(acc[mi][nf], ah[mi], al[mi], bhh, bll);
                }
            }
        }
        __syncthreads();
    }

    #pragma unroll
    for (int mi = 0; mi < 2; mi++)
        #pragma unroll
        for (int nf = 0; nf < 8; nf++)
            #pragma unroll
            for (int half = 0; half < 2; half++) {
                int r = row0 + wm + 16 * mi + g + 8 * half;
                int c = col0 + wn + 8 * nf + 2 * t4;
                *(float2*)&Cf[(size_t)r * DD + c] =
                    make_float2(acc[mi][nf][2*half], acc[mi][nf][2*half+1]);
            }
}

// ---------------- fused flash attention v4: 512 threads (16 warps) ----------------
#define SQ_H  0
#define SQ_L  9216
#define SK_H  18432
#define SK_L  36864
#define SP_H  55296
#define SP_L  82944
#define SV_H  110592
#define SV_L  129024
#define SATT  147456
#define SATT_L (SATT + 17408)
#define SSTAT (SATT + 34816)
#define UKOFF (SSTAT + 768)
#define VPOFF (UKOFF + 1024)
#define FL_SMEM (VPOFF + 1536)

__global__ __launch_bounds__(512, 1) void flash_v4() {
    extern __shared__ char smem[];
    uint32_t sb = (uint32_t)__cvta_generic_to_shared(smem);
    float* S32  = (float*)(smem + SATT);
    float* m_s  = (float*)(smem + SSTAT);
    float* l_s  = m_s + 64;
    float* al_s = m_s + 128;
    float* uk_s = (float*)(smem + UKOFF);
    float* vp_s = (float*)(smem + VPOFF);

    int tid = threadIdx.x, lane = tid & 31, wi = tid >> 5;
    int g = lane >> 2, t4 = lane & 3;
    int bh = blockIdx.y, b = bh >> 3, h = bh & 7;
    int i0 = blockIdx.x * 64;
    int wm = (wi & 3) * 16, wcol = wi >> 2;   // wcol 0..3

    float accO[2][4];
    #pragma unroll
    for (int c = 0; c < 2; c++)
        #pragma unroll
        for (int e = 0; e < 4; e++) accO[c][e] = 0.f;

    auto issue_kp = [&](int jt) {
        int j0 = jt * 128;
        int pbase = 960 + j0 - i0;
        #pragma unroll
        for (int q = 0; q < 2; q++) {
            int c = q * 512 + tid;
            int row = c >> 3, seg = c & 7;
            size_t src = (size_t)(b * SS + j0 + row) * DD + h * DH + seg * 8;
            uint32_t d = sb + row * 144 + seg * 16;
            cp16(d + SK_H, g_kh + src, true);
            cp16(d + SK_L, g_kl + src, true);
        }
        #pragma unroll
        for (int q = 0; q < 3; q++) {
            int c = q * 512 + tid;
            int row = c >> 3, seg = c & 7;
            bool ok = row < 191;
            int rc = ok ? row : 0;
            size_t src = (size_t)(b * L2P + pbase + rc) * DD + h * DH + seg * 8;
            uint32_t d = sb + row * 144 + seg * 16;
            cp16(d + SP_H, g_ph + src, ok);
            cp16(d + SP_L, g_pl + src, ok);
        }
        if (tid < 32)
            cp16(sb + UKOFF + (jt & 1) * 512 + tid * 16,
                 g_uk + ((size_t)(b * HH + h)) * SS + j0 + tid * 4, true);
        if (tid < 192)
            cp4(sb + VPOFF + (jt & 1) * 768 + tid * 4,
                g_vp + ((size_t)(b * HH + h)) * L2P + pbase + tid);
        cpcommit();
    };
    auto issue_v = [&](int jt) {
        int j0 = jt * 128;
        #pragma unroll
        for (int q = 0; q < 2; q++) {
            int c = q * 512 + tid;
            int row = c >> 3, seg = c & 7;
            size_t src = (size_t)(b * SS + j0 + row) * DD + h * DH + seg * 8;
            uint32_t d = sb + row * 144 + seg * 16;
            cp16(d + SV_H, g_vh + src, true);
            cp16(d + SV_L, g_vl + src, true);
        }
        cpcommit();
    };

    // prologue: Q (512 slots = 1 pass) + KP(0), then V(0)
    {
        int row = tid >> 3, seg = tid & 7;
        size_t src = (size_t)(b * SS + i0 + row) * DD + h * DH + seg * 8;
        uint32_t d = sb + row * 144 + seg * 16;
        cp16(d + SQ_H, g_qh + src, true);
        cp16(d + SQ_L, g_ql + src, true);
    }
    issue_kp(0);
    issue_v(0);

    for (int jt = 0; jt < 8; jt++) {
        cpwait<1>();
        __syncthreads();
        int ub2 = (jt & 1) * 128;
        int vb2 = (jt & 1) * 192;

        // ---- merged content (QK^T, 32 cols/warp) + pos (QP^T, 48 cols/warp) ----
        float accC[4][4];
        float accR[6][4];
        #pragma unroll
        for (int c = 0; c < 4; c++)
            #pragma unroll
            for (int e = 0; e < 4; e++) accC[c][e] = 0.f;
        #pragma unroll
        for (int c = 0; c < 6; c++)
            #pragma unroll
            for (int e = 0; e < 4; e++) accR[c][e] = 0.f;

        #pragma unroll
        for (int kk = 0; kk < 64; kk += 16) {
            uint32_t ah[4], al[4];
            uint32_t ad = sb + SQ_H + (wm + (lane & 15)) * 144 + (kk + ((lane >> 4) << 3)) * 2;
            ldsm4(ah, ad);
            ldsm4(al, ad + (SQ_L - SQ_H));
            #pragma unroll
            for (int nh = 0; nh < 2; nh++) {
                int n0 = wcol * 32 + 16 * nh;
                uint32_t bd = sb + SK_H + (n0 + (lane & 15)) * 144 + (kk + ((lane >> 4) << 3)) * 2;
                uint32_t bh4[4], bl4[4];
                ldsm4(bh4, bd);
                ldsm4(bl4, bd + (SK_L - SK_H));
                #pragma unroll
                for (int half = 0; half < 2; half++) {
                    int nf = 2 * nh + half;
                    uint32_t bhh[2] = {bh4[half], bh4[half+2]};
                    uint32_t bll[2] = {bl4[half], bl4[half+2]};
                    mma3(accC[nf], ah, al, bhh, bll);
                }
            }
            #pragma unroll
            for (int nh = 0; nh < 3; nh++) {
                int n0 = wcol * 48 + 16 * nh;
                uint32_t bd = sb + SP_H + (n0 + (lane & 15)) * 144 + (kk + ((lane >> 4) << 3)) * 2;
                uint32_t bh4[4], bl4[4];
                ldsm4(bh4, bd);
                ldsm4(bl4, bd + (SP_L - SP_H));
                #pragma unroll
                for (int half = 0; half < 2; half++) {
                    int nf = 2 * nh + half;
                    uint32_t bhh[2] = {bh4[half], bh4[half+2]};
                    uint32_t bll[2] = {bl4[half], bl4[half+2]};
                    mma3(accR[nf], ah, al, bhh, bll);
                }
            }
        }
        // dump content + uk (exclusive cells)
        #pragma unroll
        for (int nf = 0; nf < 4; nf++) {
            int jj = wcol * 32 + 8 * nf + 2 * t4;
            int rl = wm + g;
            S32[rl * 132 + jj]     = (accC[nf][0] + uk_s[ub2 + jj])     * SCALE;
            S32[rl * 132 + jj + 1] = (accC[nf][1] + uk_s[ub2 + jj + 1]) * SCALE;
            S32[(rl + 8) * 132 + jj]     = (accC[nf][2] + uk_s[ub2 + jj])     * SCALE;
            S32[(rl + 8) * 132 + jj + 1] = (accC[nf][3] + uk_s[ub2 + jj + 1]) * SCALE;
        }
        __syncthreads();          // K,P consumed; content visible
        if (jt < 7) issue_kp(jt + 1); else cpcommit();

        // scatter pos: jl = t + rl - 63 (injective per row)
        #pragma unroll
        for (int nf = 0; nf < 6; nf++) {
            int t = wcol * 48 + 8 * nf + 2 * t4;
            #pragma unroll
            for (int half = 0; half < 2; half++) {
                int rl = wm + g + 8 * half;
                int jl = t + rl - 63;
                if (jl >= 0 && jl < 128)
                    S32[rl * 132 + jl] += (accR[nf][2*half] + vp_s[vb2 + t]) * SCALE;
                int jl2 = jl + 1;
                if (jl2 >= 0 && jl2 < 128)
                    S32[rl * 132 + jl2] += (accR[nf][2*half+1] + vp_s[vb2 + t + 1]) * SCALE;
            }
        }
        __syncthreads();

        // ---- online softmax (8 threads per row) ----
        int r = tid >> 3, q8 = tid & 7;
        float p[16];
        {
            const float4* Sp = (const float4*)(S32 + r * 132 + q8 * 16);
            float tm = -1e30f;
            #pragma unroll
            for (int q = 0; q < 4; q++) {
                float4 v = Sp[q];
                p[4*q] = v.x; p[4*q+1] = v.y; p[4*q+2] = v.z; p[4*q+3] = v.w;
                tm = fmaxf(tm, fmaxf(fmaxf(v.x, v.y), fmaxf(v.z, v.w)));
            }
            tm = fmaxf(tm, __shfl_xor_sync(0xffffffffu, tm, 1));
            tm = fmaxf(tm, __shfl_xor_sync(0xffffffffu, tm, 2));
            tm = fmaxf(tm, __shfl_xor_sync(0xffffffffu, tm, 4));
            float mo = jt ? m_s[r] : -1e30f;
            float lo = jt ? l_s[r] : 0.f;
            float mn = fmaxf(mo, tm);
            float alpha = __expf(mo - mn);
            float sum = 0.f;
            #pragma unroll
            for (int c = 0; c < 16; c++) { p[c] = __expf(p[c] - mn); sum += p[c]; }
            sum += __shfl_xor_sync(0xffffffffu, sum, 1);
            sum += __shfl_xor_sync(0xffffffffu, sum, 2);
            sum += __shfl_xor_sync(0xffffffffu, sum, 4);
            if (q8 == 0) { m_s[r] = mn; l_s[r] = alpha * lo + sum; al_s[r] = alpha; }
        }
        __syncthreads();

        // write probs (split bf16) into attn buffer (aliases S32)
        {
            uint32_t* ahp = (uint32_t*)(smem + SATT)   + r * 68 + q8 * 8;
            uint32_t* alp = (uint32_t*)(smem + SATT_L) + r * 68 + q8 * 8;
            #pragma unroll
            for (int q = 0; q < 8; q++) {
                uint32_t hh, ll;
                split_pair(p[2*q], p[2*q+1], hh, ll);
                ahp[q] = hh; alp[q] = ll;
            }
        }
        cpwait<1>();              // V(jt) ready
        __syncthreads();

        // rescale O, then accumulate P @ V (16 d-cols per warp)
        {
            float a1 = al_s[wm + g];
            float a2 = al_s[wm + g + 8];
            #pragma unroll
            for (int nf = 0; nf < 2; nf++) {
                accO[nf][0] *= a1; accO[nf][1] *= a1;
                accO[nf][2] *= a2; accO[nf][3] *= a2;
            }
        }
        #pragma unroll
        for (int kk = 0; kk < 128; kk += 16) {
            uint32_t ah[4], al[4];
            uint32_t ad = sb + SATT + (wm + (lane & 15)) * 272 + (kk + ((lane >> 4) << 3)) * 2;
            ldsm4(ah, ad);
            ldsm4(al, ad + (SATT_L - SATT));
            int n0 = wcol * 16;
            uint32_t bd = sb + SV_H + (kk + (lane & 7) + (lane & 8)) * 144
                          + (n0 + ((lane & 16) >> 1)) * 2;
            uint32_t bh4[4], bl4[4];
            ldsm4t(bh4, bd);
            ldsm4t(bl4, bd + (SV_L - SV_H));
            #pragma unroll
            for (int half = 0; half < 2; half++) {
                uint32_t bhh[2] = {bh4[2*half], bh4[2*half+1]};
                uint32_t bll[2] = {bl4[2*half], bl4[2*half+1]};
                mma3(accO[half], ah, al, bhh, bll);
            }
        }
        __syncthreads();
        if (jt < 7) issue_v(jt + 1); else cpcommit();
    }

    // epilogue: normalize, split, store context
    #pragma unroll
    for (int nf = 0; nf < 2; nf++)
        #pragma unroll
        for (int half = 0; half < 2; half++) {
            int rl = wm + g + 8 * half;
            float inv = 1.f / l_s[rl];
            int dl = wcol * 16 + 8 * nf + 2 * t4;
            uint32_t hh, ll;
            split_pair(accO[nf][2*half] * inv, accO[nf][2*half+1] * inv, hh, ll);
            size_t o = (size_t)(b * SS + i0 + rl) * DD + h * DH + dl;
            *(uint32_t*)&g_ch[o] = hh;
            *(uint32_t*)&g_cl[o] = ll;
        }
}

// ---------------- launch ----------------
extern "C" void kernel_launch(void* const* d_in, const int* in_sizes, int n_in,
                              void* d_out, int out_size) {
    const float* query = (const float*)d_in[0];
    const float* key   = (const float*)d_in[1];
    const float* value = (const float*)d_in[2];
    const float* pos   = (const float*)d_in[3];
    const float* Wq    = (const float*)d_in[4];
    const float* Wk    = (const float*)d_in[5];
    const float* Wv    = (const float*)d_in[6];
    const float* Wp    = (const float*)d_in[7];
    const float* ub    = (const float*)d_in[8];
    const float* vb    = (const float*)d_in[9];
    const float* Wo    = (const float*)d_in[10];
    float* out = (float*)d_out;

    static bool attr_done = false;
    if (!attr_done) {
        cudaFuncSetAttribute(gemm_proj_all, cudaFuncAttributeMaxDynamicSharedMemorySize, 2*G_STG);
        cudaFuncSetAttribute(gemm_out,      cudaFuncAttributeMaxDynamicSharedMemorySize, 2*G_STG);
        cudaFuncSetAttribute(flash_v4,      cudaFuncAttributeMaxDynamicSharedMemorySize, FL_SMEM);
        attr_done = true;
    }

    dim3 blk(256);

    // merged splits
    split_in_all<<<(C_P + 255)/256, blk>>>((const float4*)query, (const float4*)key,
                                           (const float4*)value, (const float4*)pos);
    split_w_all<<<dim3(DD*DD/4/256, 1, 5), blk>>>((const float4*)Wq, (const float4*)Wk,
                                                  (const float4*)Wv, (const float4*)Wp,
                                                  (const float4*)Wo);

    // merged projections
    gemm_proj_all<<<dim3(4, 320), blk, 2*G_STG>>>();

    // merged rank-1 bias terms (z=0: uk over SS, z=1: vp over L2P)
    biasdot2<<<dim3((8*8*((L2P+7)/8) + 7)/8, 1, 2), blk>>>(ub, vb);

    // fused attention (512 threads)
    flash_v4<<<dim3(SS/64, BB*HH), 512, FL_SMEM>>>();

    // output projection
    gemm_out<<<dim3(4, 64), blk, 2*G_STG>>>(out);
}

// round 11
// speedup vs baseline: 3.9460x; 1.0593x over previous
#include <cuda_runtime.h>
#include <cuda_bf16.h>
#include <cstdint>

#define BB 8
#define SS 1024
#define DD 512
#define HH 8
#define DH 64
#define L2P 2047
#define SCALE 0.125f
#define MROWS (BB*SS)      // 8192
#define PROWS (BB*L2P)     // 16376

// ---------------- scratch ----------------
__device__ __nv_bfloat16 g_xqh[MROWS*DD], g_xql[MROWS*DD];
__device__ __nv_bfloat16 g_xkh[MROWS*DD], g_xkl[MROWS*DD];
__device__ __nv_bfloat16 g_xvh[MROWS*DD], g_xvl[MROWS*DD];
__device__ __nv_bfloat16 g_xph[PROWS*DD], g_xpl[PROWS*DD];
__device__ __nv_bfloat16 g_wh[5*DD*DD], g_wl[5*DD*DD];
__device__ __nv_bfloat16 g_qh[MROWS*DD],  g_ql[MROWS*DD];
__device__ __nv_bfloat16 g_kh[MROWS*DD],  g_kl[MROWS*DD];
__device__ __nv_bfloat16 g_vh[MROWS*DD],  g_vl[MROWS*DD];
__device__ __nv_bfloat16 g_ph[(PROWS+8)*DD], g_pl[(PROWS+8)*DD];
__device__ __nv_bfloat16 g_ch[MROWS*DD], g_cl[MROWS*DD];
__device__ float g_uk[BB*HH*SS];
__device__ float g_vp[BB*HH*L2P + 64];

// ---------------- helpers ----------------
__device__ __forceinline__ void split_pair(float x0, float x1, uint32_t& h, uint32_t& l) {
    __nv_bfloat162 hh = __floats2bfloat162_rn(x0, x1);
    float r0 = x0 - __bfloat162float(hh.x);
    float r1 = x1 - __bfloat162float(hh.y);
    __nv_bfloat162 ll = __floats2bfloat162_rn(r0, r1);
    h = *reinterpret_cast<uint32_t*>(&hh);
    l = *reinterpret_cast<uint32_t*>(&ll);
}
__device__ __forceinline__ float2 unsplit(uint32_t h, uint32_t l) {
    __nv_bfloat162 hh = *reinterpret_cast<__nv_bfloat162*>(&h);
    __nv_bfloat162 ll = *reinterpret_cast<__nv_bfloat162*>(&l);
    return make_float2(__bfloat162float(hh.x) + __bfloat162float(ll.x),
                       __bfloat162float(hh.y) + __bfloat162float(ll.y));
}
__device__ __forceinline__ void mma16816(float d[4], const uint32_t a[4], const uint32_t b[2]) {
    asm volatile(
        "mma.sync.aligned.m16n8k16.row.col.f32.bf16.bf16.f32 "
        "{%0,%1,%2,%3}, {%4,%5,%6,%7}, {%8,%9}, {%0,%1,%2,%3};\n"
        : "+f"(d[0]), "+f"(d[1]), "+f"(d[2]), "+f"(d[3])
        : "r"(a[0]), "r"(a[1]), "r"(a[2]), "r"(a[3]), "r"(b[0]), "r"(b[1]));
}
__device__ __forceinline__ void mma3(float d[4], const uint32_t ah[4], const uint32_t al[4],
                                     const uint32_t bh[2], const uint32_t bl[2]) {
    mma16816(d, ah, bh);
    mma16816(d, ah, bl);
    mma16816(d, al, bh);
}
__device__ __forceinline__ void ldsm4(uint32_t r[4], uint32_t addr) {
    asm volatile("ldmatrix.sync.aligned.m8n8.x4.shared.b16 {%0,%1,%2,%3},[%4];"
        : "=r"(r[0]), "=r"(r[1]), "=r"(r[2]), "=r"(r[3]) : "r"(addr));
}
__device__ __forceinline__ void ldsm4t(uint32_t r[4], uint32_t addr) {
    asm volatile("ldmatrix.sync.aligned.m8n8.x4.trans.shared.b16 {%0,%1,%2,%3},[%4];"
        : "=r"(r[0]), "=r"(r[1]), "=r"(r[2]), "=r"(r[3]) : "r"(addr));
}
__device__ __forceinline__ void cp16(uint32_t dst, const void* src, bool pred) {
    int sz = pred ? 16 : 0;
    asm volatile("cp.async.cg.shared.global [%0],[%1],16,%2;\n"
        :: "r"(dst), "l"(src), "r"(sz));
}
__device__ __forceinline__ void cp4(uint32_t dst, const void* src) {
    asm volatile("cp.async.ca.shared.global [%0],[%1],4;\n" :: "r"(dst), "l"(src));
}
__device__ __forceinline__ void cpcommit() { asm volatile("cp.async.commit_group;\n"); }
template<int N> __device__ __forceinline__ void cpwait() {
    asm volatile("cp.async.wait_group %0;\n" :: "n"(N));
}

// ---------------- merged input split prepass ----------------
#define C_Q  (MROWS*DD/4)
#define C_K  (2*C_Q)
#define C_V  (3*C_Q)
#define C_P  (C_V + PROWS*DD/4)
__global__ __launch_bounds__(256) void split_in_all(const float4* __restrict__ q,
                                                    const float4* __restrict__ k,
                                                    const float4* __restrict__ v,
                                                    const float4* __restrict__ p) {
    long i = (long)blockIdx.x * 256 + threadIdx.x;
    const float4* src; uint32_t *hi, *lo; long off;
    if (i < C_Q)      { src = q; hi = (uint32_t*)g_xqh; lo = (uint32_t*)g_xql; off = i; }
    else if (i < C_K) { src = k; hi = (uint32_t*)g_xkh; lo = (uint32_t*)g_xkl; off = i - C_Q; }
    else if (i < C_V) { src = v; hi = (uint32_t*)g_xvh; lo = (uint32_t*)g_xvl; off = i - C_K; }
    else if (i < C_P) { src = p; hi = (uint32_t*)g_xph; lo = (uint32_t*)g_xpl; off = i - C_V; }
    else return;
    float4 val = src[off];
    uint32_t h0, l0, h1, l1;
    split_pair(val.x, val.y, h0, l0);
    split_pair(val.z, val.w, h1, l1);
    hi[2*off] = h0; hi[2*off+1] = h1;
    lo[2*off] = l0; lo[2*off+1] = l1;
}

__global__ __launch_bounds__(256) void split_w_all(const float4* __restrict__ W0,
                                                   const float4* __restrict__ W1,
                                                   const float4* __restrict__ W2,
                                                   const float4* __restrict__ W3,
                                                   const float4* __restrict__ W4) {
    int z = blockIdx.z;
    const float4* src = (z == 0) ? W0 : (z == 1) ? W1 : (z == 2) ? W2 : (z == 3) ? W3 : W4;
    uint32_t* hi = (uint32_t*)g_wh + (size_t)z * (DD*DD/2);
    uint32_t* lo = (uint32_t*)g_wl + (size_t)z * (DD*DD/2);
    int i = blockIdx.x * 256 + threadIdx.x;
    float4 v = src[i];
    uint32_t h0, l0, h1, l1;
    split_pair(v.x, v.y, h0, l0);
    split_pair(v.z, v.w, h1, l1);
    hi[2*i] = h0; hi[2*i+1] = h1;
    lo[2*i] = l0; lo[2*i+1] = l1;
}

// ---------------- merged bias GEMV (z=0: u.k ; z=1: v.p) ----------------
__global__ __launch_bounds__(256) void biasdot2(const float* __restrict__ ub,
                                                const float* __restrict__ vb) {
    int z = blockIdx.z;
    const float* bias = z ? vb : ub;
    const __nv_bfloat16* xh = z ? g_ph : g_kh;
    const __nv_bfloat16* xl = z ? g_pl : g_kl;
    float* outg = z ? g_vp : g_uk;
    int ROWS = z ? L2P : SS;

    int gw = blockIdx.x * 8 + (threadIdx.x >> 5);
    int lane = threadIdx.x & 31;
    int ngroups = (ROWS + 7) >> 3;
    int jg = gw % ngroups;
    int rem = gw / ngroups;
    int h = rem & 7, b = rem >> 3;
    if (b >= BB) return;
    int jsub = lane >> 2, dq = lane & 3;
    int j = jg * 8 + jsub;
    float acc = 0.f;
    if (j < ROWS) {
        size_t base = ((size_t)(b * ROWS + j)) * DD + h * DH + dq * 16;
        uint4 h0 = *(const uint4*)&xh[base];
        uint4 h1 = *(const uint4*)&xh[base + 8];
        uint4 l0 = *(const uint4*)&xl[base];
        uint4 l1 = *(const uint4*)&xl[base + 8];
        uint32_t hs[8] = {h0.x,h0.y,h0.z,h0.w,h1.x,h1.y,h1.z,h1.w};
        uint32_t ls[8] = {l0.x,l0.y,l0.z,l0.w,l1.x,l1.y,l1.z,l1.w};
        const float* u = bias + h * DH + dq * 16;
        #pragma unroll
        for (int e = 0; e < 8; e++) {
            float2 f = unsplit(hs[e], ls[e]);
            acc += f.x * u[2*e] + f.y * u[2*e+1];
        }
    }
    acc += __shfl_xor_sync(0xffffffffu, acc, 1);
    acc += __shfl_xor_sync(0xffffffffu, acc, 2);
    if (dq == 0 && j < ROWS)
        outg[((size_t)(b * HH + h)) * ROWS + j] = acc;
}

// ---------------- GEMM ----------------
#define G_AL  10240
#define G_BH  20480
#define G_BL  29184
#define G_STG 37888

__global__ __launch_bounds__(256, 2) void gemm_proj_all() {
    extern __shared__ char smem[];
    uint32_t sb = (uint32_t)__cvta_generic_to_shared(smem);
    int tid = threadIdx.x, lane = tid & 31, wi = tid >> 5;
    int g = lane >> 2, t4 = lane & 3;
    int y = blockIdx.y;
    const __nv_bfloat16 *Ah, *Al, *Bh, *Bl;
    __nv_bfloat16 *Ch, *Cl;
    int M, row0;
    if (y < 192) {
        int sel = y >> 6;
        row0 = (y & 63) * 128; M = MROWS;
        if (sel == 0)      { Ah = g_xqh; Al = g_xql; Ch = g_qh; Cl = g_ql; }
        else if (sel == 1) { Ah = g_xkh; Al = g_xkl; Ch = g_kh; Cl = g_kl; }
        else               { Ah = g_xvh; Al = g_xvl; Ch = g_vh; Cl = g_vl; }
        Bh = g_wh + (size_t)sel * DD * DD;
        Bl = g_wl + (size_t)sel * DD * DD;
    } else {
        row0 = (y - 192) * 128; M = PROWS;
        Ah = g_xph; Al = g_xpl; Ch = g_ph; Cl = g_pl;
        Bh = g_wh + (size_t)3 * DD * DD;
        Bl = g_wl + (size_t)3 * DD * DD;
    }
    int col0 = blockIdx.x * 128;
    int wm = (wi & 3) * 32, wn = (wi >> 2) * 64;

    float acc[2][8][4];
    #pragma unroll
    for (int a = 0; a < 2; a++)
        #pragma unroll
        for (int b = 0; b < 8; b++)
            #pragma unroll
            for (int c = 0; c < 4; c++) acc[a][b][c] = 0.f;

    auto issue = [&](int it) {
        int k0 = it * 32;
        uint32_t st = sb + (it & 1) * G_STG;
        #pragma unroll
        for (int q = 0; q < 2; q++) {
            int c = q * 256 + tid;
            int m = c >> 2, seg = c & 3;
            bool ok = (row0 + m) < M;
            int mr = ok ? (row0 + m) : 0;
            cp16(st + m * 80 + seg * 16, Ah + (size_t)mr * DD + k0 + seg * 8, ok);
            cp16(st + G_AL + m * 80 + seg * 16, Al + (size_t)mr * DD + k0 + seg * 8, ok);
        }
        #pragma unroll
        for (int q = 0; q < 2; q++) {
            int c = q * 256 + tid;
            int k = c >> 4, seg = c & 15;
            cp16(st + G_BH + k * 272 + seg * 16, Bh + (size_t)(k0 + k) * DD + col0 + seg * 8, true);
            cp16(st + G_BL + k * 272 + seg * 16, Bl + (size_t)(k0 + k) * DD + col0 + seg * 8, true);
        }
        cpcommit();
    };

    issue(0);
    for (int it = 0; it < 16; it++) {
        if (it + 1 < 16) { issue(it + 1); cpwait<1>(); }
        else cpwait<0>();
        __syncthreads();
        uint32_t st = sb + (it & 1) * G_STG;
        #pragma unroll
        for (int kk = 0; kk < 32; kk += 16) {
            uint32_t ah[2][4], al[2][4];
            #pragma unroll
            for (int mi = 0; mi < 2; mi++) {
                uint32_t ad = st + (wm + 16 * mi + (lane & 15)) * 80 + (kk + ((lane >> 4) << 3)) * 2;
                ldsm4(ah[mi], ad);
                ldsm4(al[mi], ad + G_AL);
            }
            #pragma unroll
            for (int nh = 0; nh < 4; nh++) {
                int n0 = wn + 16 * nh;
                uint32_t bd = st + G_BH + (kk + (lane & 7) + (lane & 8)) * 272
                              + (n0 + ((lane & 16) >> 1)) * 2;
                uint32_t bh4[4], bl4[4];
                ldsm4t(bh4, bd);
                ldsm4t(bl4, bd + (G_BL - G_BH));
                #pragma unroll
                for (int half = 0; half < 2; half++) {
                    int nf = 2 * nh + half;
                    uint32_t bhh[2] = {bh4[2*half], bh4[2*half+1]};
                    uint32_t bll[2] = {bl4[2*half], bl4[2*half+1]};
                    #pragma unroll
                    for (int mi = 0; mi < 2; mi++)
                        mma3(acc[mi][nf], ah[mi], al[mi], bhh, bll);
                }
            }
        }
        __syncthreads();
    }

    #pragma unroll
    for (int mi = 0; mi < 2; mi++)
        #pragma unroll
        for (int nf = 0; nf < 8; nf++)
            #pragma unroll
            for (int half = 0; half < 2; half++) {
                int r = row0 + wm + 16 * mi + g + 8 * half;
                int c = col0 + wn + 8 * nf + 2 * t4;
                if (r < M) {
                    uint32_t h, l;
                    split_pair(acc[mi][nf][2*half], acc[mi][nf][2*half+1], h, l);
                    *(uint32_t*)&Ch[(size_t)r * DD + c] = h;
                    *(uint32_t*)&Cl[(size_t)r * DD + c] = l;
                }
            }
}

__global__ __launch_bounds__(256, 2) void gemm_out(float* __restrict__ Cf) {
    extern __shared__ char smem[];
    uint32_t sb = (uint32_t)__cvta_generic_to_shared(smem);
    int tid = threadIdx.x, lane = tid & 31, wi = tid >> 5;
    int g = lane >> 2, t4 = lane & 3;
    int row0 = blockIdx.y * 128, col0 = blockIdx.x * 128;
    int wm = (wi & 3) * 32, wn = (wi >> 2) * 64;
    const __nv_bfloat16* Ah = g_ch;
    const __nv_bfloat16* Al = g_cl;
    const __nv_bfloat16* Bh = g_wh + (size_t)4 * DD * DD;
    const __nv_bfloat16* Bl = g_wl + (size_t)4 * DD * DD;

    float acc[2][8][4];
    #pragma unroll
    for (int a = 0; a < 2; a++)
        #pragma unroll
        for (int b = 0; b < 8; b++)
            #pragma unroll
            for (int c = 0; c < 4; c++) acc[a][b][c] = 0.f;

    auto issue = [&](int it) {
        int k0 = it * 32;
        uint32_t st = sb + (it & 1) * G_STG;
        #pragma unroll
        for (int q = 0; q < 2; q++) {
            int c = q * 256 + tid;
            int m = c >> 2, seg = c & 3;
            cp16(st + m * 80 + seg * 16, Ah + (size_t)(row0 + m) * DD + k0 + seg * 8, true);
            cp16(st + G_AL + m * 80 + seg * 16, Al + (size_t)(row0 + m) * DD + k0 + seg * 8, true);
        }
        #pragma unroll
        for (int q = 0; q < 2; q++) {
            int c = q * 256 + tid;
            int k = c >> 4, seg = c & 15;
            cp16(st + G_BH + k * 272 + seg * 16, Bh + (size_t)(k0 + k) * DD + col0 + seg * 8, true);
            cp16(st + G_BL + k * 272 + seg * 16, Bl + (size_t)(k0 + k) * DD + col0 + seg * 8, true);
        }
        cpcommit();
    };

    issue(0);
    for (int it = 0; it < 16; it++) {
        if (it + 1 < 16) { issue(it + 1); cpwait<1>(); }
        else cpwait<0>();
        __syncthreads();
        uint32_t st = sb + (it & 1) * G_STG;
        #pragma unroll
        for (int kk = 0; kk < 32; kk += 16) {
            uint32_t ah[2][4], al[2][4];
            #pragma unroll
            for (int mi = 0; mi < 2; mi++) {
                uint32_t ad = st + (wm + 16 * mi + (lane & 15)) * 80 + (kk + ((lane >> 4) << 3)) * 2;
                ldsm4(ah[mi], ad);
                ldsm4(al[mi], ad + G_AL);
            }
            #pragma unroll
            for (int nh = 0; nh < 4; nh++) {
                int n0 = wn + 16 * nh;
                uint32_t bd = st + G_BH + (kk + (lane & 7) + (lane & 8)) * 272
                              + (n0 + ((lane & 16) >> 1)) * 2;
                uint32_t bh4[4], bl4[4];
                ldsm4t(bh4, bd);
                ldsm4t(bl4, bd + (G_BL - G_BH));
                #pragma unroll
                for (int half = 0; half < 2; half++) {
                    int nf = 2 * nh + half;
                    uint32_t bhh[2] = {bh4[2*half], bh4[2*half+1]};
                    uint32_t bll[2] = {bl4[2*half], bl4[2*half+1]};
                    #pragma unroll
                    for (int mi = 0; mi < 2; mi++)
                        mma3(acc[mi][nf], ah[mi], al[mi], bhh, bll);
                }
            }
        }
        __syncthreads();
    }

    #pragma unroll
    for (int mi = 0; mi < 2; mi++)
        #pragma unroll
        for (int nf = 0; nf < 8; nf++)
            #pragma unroll
            for (int half = 0; half < 2; half++) {
                int r = row0 + wm + 16 * mi + g + 8 * half;
                int c = col0 + wn + 8 * nf + 2 * t4;
                *(float2*)&Cf[(size_t)r * DD + c] =
                    make_float2(acc[mi][nf][2*half], acc[mi][nf][2*half+1]);
            }
}

// ---------------- fused flash attention v5: 64x64 tile, 2 CTAs/SM ----------------
// smem layout (bytes)
#define SQ_H  0
#define SQ_L  9216
#define SK_H  18432
#define SK_L  27648
#define SP_H  36864
#define SP_L  55296
#define SV_H  73728
#define SV_L  82944
#define SATT  92160
#define SATT_L (SATT + 9216)
#define SSTAT (SATT + 18432)
#define UKOFF (SSTAT + 768)
#define VPOFF (UKOFF + 512)
#define FL_SMEM (VPOFF + 1024)    // 112384 B -> 2 CTAs/SM

__global__ __launch_bounds__(256, 2) void flash_v5() {
    extern __shared__ char smem[];
    uint32_t sb = (uint32_t)__cvta_generic_to_shared(smem);
    float* S32  = (float*)(smem + SATT);
    float* m_s  = (float*)(smem + SSTAT);
    float* l_s  = m_s + 64;
    float* al_s = m_s + 128;
    float* uk_s = (float*)(smem + UKOFF);
    float* vp_s = (float*)(smem + VPOFF);

    int tid = threadIdx.x, lane = tid & 31, wi = tid >> 5;
    int g = lane >> 2, t4 = lane & 3;
    int bh = blockIdx.y, b = bh >> 3, h = bh & 7;
    int i0 = blockIdx.x * 64;
    int wm = (wi & 3) * 16, wcol = wi >> 2;   // wcol 0..1

    float accO[4][4];
    #pragma unroll
    for (int c = 0; c < 4; c++)
        #pragma unroll
        for (int e = 0; e < 4; e++) accO[c][e] = 0.f;

    auto issue_kp = [&](int jt) {
        int j0 = jt * 64;
        int pbase = 960 + j0 - i0;
        #pragma unroll
        for (int q = 0; q < 2; q++) {   // K: 64 rows x 8 segs
            int c = q * 256 + tid;
            int row = c >> 3, seg = c & 7;
            size_t src = (size_t)(b * SS + j0 + row) * DD + h * DH + seg * 8;
            uint32_t d = sb + row * 144 + seg * 16;
            cp16(d + SK_H, g_kh + src, true);
            cp16(d + SK_L, g_kl + src, true);
        }
        #pragma unroll
        for (int q = 0; q < 4; q++) {   // P: 127 valid rows (pad to 128)
            int c = q * 256 + tid;
            int row = c >> 3, seg = c & 7;
            bool ok = row < 127;
            int rc = ok ? row : 0;
            size_t src = (size_t)(b * L2P + pbase + rc) * DD + h * DH + seg * 8;
            uint32_t d = sb + row * 144 + seg * 16;
            cp16(d + SP_H, g_ph + src, ok);
            cp16(d + SP_L, g_pl + src, ok);
        }
        if (tid < 16)
            cp16(sb + UKOFF + (jt & 1) * 256 + tid * 16,
                 g_uk + ((size_t)(b * HH + h)) * SS + j0 + tid * 4, true);
        if (tid < 128)
            cp4(sb + VPOFF + (jt & 1) * 512 + tid * 4,
                g_vp + ((size_t)(b * HH + h)) * L2P + pbase + tid);
        cpcommit();
    };
    auto issue_v = [&](int jt) {
        int j0 = jt * 64;
        #pragma unroll
        for (int q = 0; q < 2; q++) {
            int c = q * 256 + tid;
            int row = c >> 3, seg = c & 7;
            size_t src = (size_t)(b * SS + j0 + row) * DD + h * DH + seg * 8;
            uint32_t d = sb + row * 144 + seg * 16;
            cp16(d + SV_H, g_vh + src, true);
            cp16(d + SV_L, g_vl + src, true);
        }
        cpcommit();
    };

    // prologue: Q + KP(0) [group 1], V(0) [group 2]
    #pragma unroll
    for (int q = 0; q < 2; q++) {
        int c = q * 256 + tid;
        int row = c >> 3, seg = c & 7;
        size_t src = (size_t)(b * SS + i0 + row) * DD + h * DH + seg * 8;
        uint32_t d = sb + row * 144 + seg * 16;
        cp16(d + SQ_H, g_qh + src, true);
        cp16(d + SQ_L, g_ql + src, true);
    }
    issue_kp(0);
    issue_v(0);

    for (int jt = 0; jt < 16; jt++) {
        cpwait<1>();
        __syncthreads();
        int ub2 = (jt & 1) * 64;
        int vb2 = (jt & 1) * 128;

        // ---- merged content (QK^T, 32 cols/warp) + pos (QP^T, 64 cols/warp) ----
        float accC[4][4];
        float accR[8][4];
        #pragma unroll
        for (int c = 0; c < 4; c++)
            #pragma unroll
            for (int e = 0; e < 4; e++) accC[c][e] = 0.f;
        #pragma unroll
        for (int c = 0; c < 8; c++)
            #pragma unroll
            for (int e = 0; e < 4; e++) accR[c][e] = 0.f;

        #pragma unroll
        for (int kk = 0; kk < 64; kk += 16) {
            uint32_t ah[4], al[4];
            uint32_t ad = sb + SQ_H + (wm + (lane & 15)) * 144 + (kk + ((lane >> 4) << 3)) * 2;
            ldsm4(ah, ad);
            ldsm4(al, ad + (SQ_L - SQ_H));
            #pragma unroll
            for (int nh = 0; nh < 2; nh++) {
                int n0 = wcol * 32 + 16 * nh;
                uint32_t bd = sb + SK_H + (n0 + (lane & 15)) * 144 + (kk + ((lane >> 4) << 3)) * 2;
                uint32_t bh4[4], bl4[4];
                ldsm4(bh4, bd);
                ldsm4(bl4, bd + (SK_L - SK_H));
                #pragma unroll
                for (int half = 0; half < 2; half++) {
                    int nf = 2 * nh + half;
                    uint32_t bhh[2] = {bh4[half], bh4[half+2]};
                    uint32_t bll[2] = {bl4[half], bl4[half+2]};
                    mma3(accC[nf], ah, al, bhh, bll);
                }
            }
            #pragma unroll
            for (int nh = 0; nh < 4; nh++) {
                int n0 = wcol * 64 + 16 * nh;
                uint32_t bd = sb + SP_H + (n0 + (lane & 15)) * 144 + (kk + ((lane >> 4) << 3)) * 2;
                uint32_t bh4[4], bl4[4];
                ldsm4(bh4, bd);
                ldsm4(bl4, bd + (SP_L - SP_H));
                #pragma unroll
                for (int half = 0; half < 2; half++) {
                    int nf = 2 * nh + half;
                    uint32_t bhh[2] = {bh4[half], bh4[half+2]};
                    uint32_t bll[2] = {bl4[half], bl4[half+2]};
                    mma3(accR[nf], ah, al, bhh, bll);
                }
            }
        }
        // dump content + uk (exclusive cells)
        #pragma unroll
        for (int nf = 0; nf < 4; nf++) {
            int jj = wcol * 32 + 8 * nf + 2 * t4;
            int rl = wm + g;
            S32[rl * 68 + jj]     = (accC[nf][0] + uk_s[ub2 + jj])     * SCALE;
            S32[rl * 68 + jj + 1] = (accC[nf][1] + uk_s[ub2 + jj + 1]) * SCALE;
            S32[(rl + 8) * 68 + jj]     = (accC[nf][2] + uk_s[ub2 + jj])     * SCALE;
            S32[(rl + 8) * 68 + jj + 1] = (accC[nf][3] + uk_s[ub2 + jj + 1]) * SCALE;
        }
        __syncthreads();          // K,P consumed; content visible
        if (jt < 15) issue_kp(jt + 1); else cpcommit();

        // scatter pos: jl = t + rl - 63 (injective per row); t in [0,126]
        #pragma unroll
        for (int nf = 0; nf < 8; nf++) {
            int t = wcol * 64 + 8 * nf + 2 * t4;
            #pragma unroll
            for (int half = 0; half < 2; half++) {
                int rl = wm + g + 8 * half;
                int jl = t + rl - 63;
                if (jl >= 0 && jl < 64)
                    S32[rl * 68 + jl] += (accR[nf][2*half] + vp_s[vb2 + t]) * SCALE;
                int jl2 = jl + 1;
                if (jl2 >= 0 && jl2 < 64)
                    S32[rl * 68 + jl2] += (accR[nf][2*half+1] + vp_s[vb2 + t + 1]) * SCALE;
            }
        }
        __syncthreads();

        // ---- online softmax (4 threads per row, 16 cols each) ----
        int r = tid >> 2, q4 = tid & 3;
        float p[16];
        {
            const float4* Sp = (const float4*)(S32 + r * 68 + q4 * 16);
            float tm = -1e30f;
            #pragma unroll
            for (int q = 0; q < 4; q++) {
                float4 v = Sp[q];
                p[4*q] = v.x; p[4*q+1] = v.y; p[4*q+2] = v.z; p[4*q+3] = v.w;
                tm = fmaxf(tm, fmaxf(fmaxf(v.x, v.y), fmaxf(v.z, v.w)));
            }
            tm = fmaxf(tm, __shfl_xor_sync(0xffffffffu, tm, 1));
            tm = fmaxf(tm, __shfl_xor_sync(0xffffffffu, tm, 2));
            float mo = jt ? m_s[r] : -1e30f;
            float lo = jt ? l_s[r] : 0.f;
            float mn = fmaxf(mo, tm);
            float alpha = __expf(mo - mn);
            float sum = 0.f;
            #pragma unroll
            for (int c = 0; c < 16; c++) { p[c] = __expf(p[c] - mn); sum += p[c]; }
            sum += __shfl_xor_sync(0xffffffffu, sum, 1);
            sum += __shfl_xor_sync(0xffffffffu, sum, 2);
            if (q4 == 0) { m_s[r] = mn; l_s[r] = alpha * lo + sum; al_s[r] = alpha; }
        }
        __syncthreads();

        // write probs (split bf16) into attn buffer (aliases S32)
        {
            uint32_t* ahp = (uint32_t*)(smem + SATT)   + r * 36 + q4 * 8;
            uint32_t* alp = (uint32_t*)(smem + SATT_L) + r * 36 + q4 * 8;
            #pragma unroll
            for (int q = 0; q < 8; q++) {
                uint32_t hh, ll;
                split_pair(p[2*q], p[2*q+1], hh, ll);
                ahp[q] = hh; alp[q] = ll;
            }
        }
        cpwait<1>();              // V(jt) ready
        __syncthreads();

        // rescale O, then accumulate P @ V (32 d-cols per warp, k=64)
        {
            float a1 = al_s[wm + g];
            float a2 = al_s[wm + g + 8];
            #pragma unroll
            for (int nf = 0; nf < 4; nf++) {
                accO[nf][0] *= a1; accO[nf][1] *= a1;
                accO[nf][2] *= a2; accO[nf][3] *= a2;
            }
        }
        #pragma unroll
        for (int kk = 0; kk < 64; kk += 16) {
            uint32_t ah[4], al[4];
            uint32_t ad = sb + SATT + (wm + (lane & 15)) * 144 + (kk + ((lane >> 4) << 3)) * 2;
            ldsm4(ah, ad);
            ldsm4(al, ad + (SATT_L - SATT));
            #pragma unroll
            for (int nh = 0; nh < 2; nh++) {
                int n0 = wcol * 32 + 16 * nh;
                uint32_t bd = sb + SV_H + (kk + (lane & 7) + (lane & 8)) * 144
                              + (n0 + ((lane & 16) >> 1)) * 2;
                uint32_t bh4[4], bl4[4];
                ldsm4t(bh4, bd);
                ldsm4t(bl4, bd + (SV_L - SV_H));
                #pragma unroll
                for (int half = 0; half < 2; half++) {
                    int nf = 2 * nh + half;
                    uint32_t bhh[2] = {bh4[2*half], bh4[2*half+1]};
                    uint32_t bll[2] = {bl4[2*half], bl4[2*half+1]};
                    mma3(accO[nf], ah, al, bhh, bll);
                }
            }
        }
        __syncthreads();
        if (jt < 15) issue_v(jt + 1); else cpcommit();
    }

    // epilogue: normalize, split, store context
    #pragma unroll
    for (int nf = 0; nf < 4; nf++)
        #pragma unroll
        for (int half = 0; half < 2; half++) {
            int rl = wm + g + 8 * half;
            float inv = 1.f / l_s[rl];
            int dl = wcol * 32 + 8 * nf + 2 * t4;
            uint32_t hh, ll;
            split_pair(accO[nf][2*half] * inv, accO[nf][2*half+1] * inv, hh, ll);
            size_t o = (size_t)(b * SS + i0 + rl) * DD + h * DH + dl;
            *(uint32_t*)&g_ch[o] = hh;
            *(uint32_t*)&g_cl[o] = ll;
        }
}

// ---------------- launch ----------------
extern "C" void kernel_launch(void* const* d_in, const int* in_sizes, int n_in,
                              void* d_out, int out_size) {
    const float* query = (const float*)d_in[0];
    const float* key   = (const float*)d_in[1];
    const float* value = (const float*)d_in[2];
    const float* pos   = (const float*)d_in[3];
    const float* Wq    = (const float*)d_in[4];
    const float* Wk    = (const float*)d_in[5];
    const float* Wv    = (const float*)d_in[6];
    const float* Wp    = (const float*)d_in[7];
    const float* ub    = (const float*)d_in[8];
    const float* vb    = (const float*)d_in[9];
    const float* Wo    = (const float*)d_in[10];
    float* out = (float*)d_out;

    static bool attr_done = false;
    if (!attr_done) {
        cudaFuncSetAttribute(gemm_proj_all, cudaFuncAttributeMaxDynamicSharedMemorySize, 2*G_STG);
        cudaFuncSetAttribute(gemm_out,      cudaFuncAttributeMaxDynamicSharedMemorySize, 2*G_STG);
        cudaFuncSetAttribute(flash_v5,      cudaFuncAttributeMaxDynamicSharedMemorySize, FL_SMEM);
        attr_done = true;
    }

    dim3 blk(256);

    // merged splits
    split_in_all<<<(C_P + 255)/256, blk>>>((const float4*)query, (const float4*)key,
                                           (const float4*)value, (const float4*)pos);
    split_w_all<<<dim3(DD*DD/4/256, 1, 5), blk>>>((const float4*)Wq, (const float4*)Wk,
                                                  (const float4*)Wv, (const float4*)Wp,
                                                  (const float4*)Wo);

    // merged projections
    gemm_proj_all<<<dim3(4, 320), blk, 2*G_STG>>>();

    // merged rank-1 bias terms
    biasdot2<<<dim3((8*8*((L2P+7)/8) + 7)/8, 1, 2), blk>>>(ub, vb);

    // fused attention (64x64 tiles, 2 CTAs/SM)
    flash_v5<<<dim3(SS/64, BB*HH), blk, FL_SMEM>>>();

    // output projection
    gemm_out<<<dim3(4, 64), blk, 2*G_STG>>>(out);
}